// round 1
// baseline (speedup 1.0000x reference)
#include <cuda_runtime.h>
#include <cuda_bf16.h>
#include <math.h>
#include <stdint.h>

#define T_TOK   16384
#define HS      1024
#define FFN     4096
#define NEXP    8
#define CAP     4096
#define NASSIGN (2*T_TOK)
#define SLOTS   (NEXP*CAP)

// ---------------- static device scratch (allocation-free rule) ----------------
__device__ __nv_bfloat16 g_xb_hi[(size_t)SLOTS*HS];
__device__ __nv_bfloat16 g_xb_lo[(size_t)SLOTS*HS];
__device__ __nv_bfloat16 g_h_hi[(size_t)SLOTS*FFN];
__device__ __nv_bfloat16 g_h_lo[(size_t)SLOTS*FFN];
__device__ float         g_y[(size_t)SLOTS*HS];
__device__ __nv_bfloat16 g_w1_hi[(size_t)NEXP*HS*FFN];
__device__ __nv_bfloat16 g_w1_lo[(size_t)NEXP*HS*FFN];
__device__ __nv_bfloat16 g_w2_hi[(size_t)NEXP*FFN*HS];
__device__ __nv_bfloat16 g_w2_lo[(size_t)NEXP*FFN*HS];
__device__ int           g_top_e[NASSIGN];
__device__ float         g_top_w[NASSIGN];
__device__ int           g_dst_slot[NASSIGN];

// ---------------- helpers ----------------
__device__ __forceinline__ uint32_t smem_addr32(const void* p){
  return (uint32_t)__cvta_generic_to_shared(p);
}
__device__ __forceinline__ void cp16(__nv_bfloat16* dst, const __nv_bfloat16* src){
  uint32_t d = smem_addr32(dst);
  asm volatile("cp.async.cg.shared.global [%0], [%1], 16;\n" :: "r"(d), "l"(src));
}
__device__ __forceinline__ void cp_commit(){ asm volatile("cp.async.commit_group;\n"); }
template<int NW> __device__ __forceinline__ void cp_wait(){
  asm volatile("cp.async.wait_group %0;\n" :: "n"(NW));
}
__device__ __forceinline__ void ldsm4(uint32_t* r, const __nv_bfloat16* p){
  uint32_t a = smem_addr32(p);
  asm volatile("ldmatrix.sync.aligned.m8n8.x4.shared.b16 {%0,%1,%2,%3}, [%4];\n"
    : "=r"(r[0]),"=r"(r[1]),"=r"(r[2]),"=r"(r[3]) : "r"(a));
}
__device__ __forceinline__ void ldsm4t(uint32_t* r, const __nv_bfloat16* p){
  uint32_t a = smem_addr32(p);
  asm volatile("ldmatrix.sync.aligned.m8n8.x4.trans.shared.b16 {%0,%1,%2,%3}, [%4];\n"
    : "=r"(r[0]),"=r"(r[1]),"=r"(r[2]),"=r"(r[3]) : "r"(a));
}
__device__ __forceinline__ void mma_bf16(float* c, const uint32_t* a, uint32_t b0, uint32_t b1){
  asm volatile("mma.sync.aligned.m16n8k16.row.col.f32.bf16.bf16.f32 "
    "{%0,%1,%2,%3}, {%4,%5,%6,%7}, {%8,%9}, {%0,%1,%2,%3};\n"
    : "+f"(c[0]),"+f"(c[1]),"+f"(c[2]),"+f"(c[3])
    : "r"(a[0]),"r"(a[1]),"r"(a[2]),"r"(a[3]), "r"(b0),"r"(b1));
}
__device__ __forceinline__ float gelu_tanh(float x){
  float u = 0.7978845608028654f*(x + 0.044715f*x*x*x);
  return 0.5f*x*(1.0f + tanhf(u));
}

// ---------------- router: fp64 logits + softmax + top-2 ----------------
__global__ void router_kernel(const float* __restrict__ x, const float* __restrict__ wr){
  int widx = (blockIdx.x * blockDim.x + threadIdx.x) >> 5;
  int lane = threadIdx.x & 31;
  if (widx >= T_TOK) return;
  const float* xr = x + (size_t)widx * HS;
  double acc[NEXP];
  #pragma unroll
  for (int e=0;e<NEXP;e++) acc[e]=0.0;
  for (int h = lane; h < HS; h += 32){
    double xv = (double)xr[h];
    const float* wrow = wr + h*NEXP;
    #pragma unroll
    for (int e=0;e<NEXP;e++) acc[e] += xv * (double)wrow[e];
  }
  #pragma unroll
  for (int off=16; off; off>>=1){
    #pragma unroll
    for (int e=0;e<NEXP;e++) acc[e] += __shfl_xor_sync(0xffffffffu, acc[e], off);
  }
  if (lane == 0){
    double m = acc[0];
    #pragma unroll
    for (int e=1;e<NEXP;e++) m = fmax(m, acc[e]);
    double ex[NEXP], s = 0.0;
    #pragma unroll
    for (int e=0;e<NEXP;e++){ ex[e] = exp(acc[e]-m); s += ex[e]; }
    int e0 = 0; double b0 = acc[0];
    #pragma unroll
    for (int e=1;e<NEXP;e++) if (acc[e] > b0){ b0 = acc[e]; e0 = e; }
    int e1 = (e0==0) ? 1 : 0; double b1 = acc[e1];
    #pragma unroll
    for (int e=0;e<NEXP;e++) if (e != e0 && acc[e] > b1){ b1 = acc[e]; e1 = e; }
    g_top_e[2*widx]   = e0;
    g_top_e[2*widx+1] = e1;
    g_top_w[2*widx]   = (float)(ex[e0]/s);
    g_top_w[2*widx+1] = (float)(ex[e1]/s);
  }
}

// ---------------- stable counting sort + capacity -> slot assignment ----------------
__global__ void scan_kernel(){
  __shared__ int base[256][NEXP];
  int t = threadIdx.x;
  int cnt[NEXP];
  #pragma unroll
  for (int e=0;e<NEXP;e++) cnt[e]=0;
  const int i0 = t*128;
  for (int j=0;j<128;j++) cnt[g_top_e[i0+j]]++;
  #pragma unroll
  for (int e=0;e<NEXP;e++) base[t][e]=cnt[e];
  __syncthreads();
  if (t==0){
    int run[NEXP];
    #pragma unroll
    for (int e=0;e<NEXP;e++) run[e]=0;
    for (int b=0;b<256;b++){
      #pragma unroll
      for (int e=0;e<NEXP;e++){ int c=base[b][e]; base[b][e]=run[e]; run[e]+=c; }
    }
  }
  __syncthreads();
  int run[NEXP];
  #pragma unroll
  for (int e=0;e<NEXP;e++) run[e]=base[t][e];
  for (int j=0;j<128;j++){
    int e = g_top_e[i0+j];
    int r = run[e]++;
    g_dst_slot[i0+j] = (r < CAP) ? (e*CAP + r) : -1;
  }
}

// ---------------- gather token rows -> slot buffer, split fp32 -> bf16 hi/lo ----------------
__global__ void gather_split_kernel(const float* __restrict__ x){
  int i = blockIdx.x;
  int dst = g_dst_slot[i];
  if (dst < 0) return;
  const float4* src = (const float4*)(x + (size_t)(i>>1)*HS);
  __nv_bfloat16* hi = g_xb_hi + (size_t)dst*HS;
  __nv_bfloat16* lo = g_xb_lo + (size_t)dst*HS;
  for (int j = threadIdx.x; j < HS/4; j += blockDim.x){
    float4 v = src[j];
    __nv_bfloat16 hx=__float2bfloat16(v.x), hy=__float2bfloat16(v.y);
    __nv_bfloat16 hz=__float2bfloat16(v.z), hw=__float2bfloat16(v.w);
    __nv_bfloat16 lx=__float2bfloat16(v.x-__bfloat162float(hx));
    __nv_bfloat16 ly=__float2bfloat16(v.y-__bfloat162float(hy));
    __nv_bfloat16 lz=__float2bfloat16(v.z-__bfloat162float(hz));
    __nv_bfloat16 lw=__float2bfloat16(v.w-__bfloat162float(hw));
    *(__nv_bfloat162*)&hi[j*4]   = __halves2bfloat162(hx,hy);
    *(__nv_bfloat162*)&hi[j*4+2] = __halves2bfloat162(hz,hw);
    *(__nv_bfloat162*)&lo[j*4]   = __halves2bfloat162(lx,ly);
    *(__nv_bfloat162*)&lo[j*4+2] = __halves2bfloat162(lz,lw);
  }
}

// ---------------- weight split fp32 -> bf16 hi/lo ----------------
__global__ void split_w_kernel(const float* __restrict__ w, int which){
  __nv_bfloat16* hi = which ? g_w2_hi : g_w1_hi;
  __nv_bfloat16* lo = which ? g_w2_lo : g_w1_lo;
  size_t i = (size_t)blockIdx.x*blockDim.x + threadIdx.x;
  const size_t n4 = (size_t)NEXP*HS*FFN/4;
  if (i >= n4) return;
  float4 v = ((const float4*)w)[i];
  __nv_bfloat16 hx=__float2bfloat16(v.x), hy=__float2bfloat16(v.y);
  __nv_bfloat16 hz=__float2bfloat16(v.z), hw=__float2bfloat16(v.w);
  __nv_bfloat16 lx=__float2bfloat16(v.x-__bfloat162float(hx));
  __nv_bfloat16 ly=__float2bfloat16(v.y-__bfloat162float(hy));
  __nv_bfloat16 lz=__float2bfloat16(v.z-__bfloat162float(hz));
  __nv_bfloat16 lw=__float2bfloat16(v.w-__bfloat162float(hw));
  *(__nv_bfloat162*)&hi[i*4]   = __halves2bfloat162(hx,hy);
  *(__nv_bfloat162*)&hi[i*4+2] = __halves2bfloat162(hz,hw);
  *(__nv_bfloat162*)&lo[i*4]   = __halves2bfloat162(lx,ly);
  *(__nv_bfloat162*)&lo[i*4+2] = __halves2bfloat162(lz,lw);
}

// ---------------- grouped GEMM, 3-product bf16 split, mma.sync m16n8k16 ----------------
// PHASE 1: h = gelu(xb @ w1[e]) -> split bf16 hi/lo       (K=1024, N=4096)
// PHASE 2: y = h @ w2[e] -> fp32                          (K=4096, N=1024)
// Block tile 128x128x32, 512 threads (16 warps, 4x4), warp tile 32x32.
#define GEMM_SMEM_BYTES 75776
template<int PHASE>
__global__ void __launch_bounds__(512,1) gemm_split_kernel(){
  constexpr int K  = (PHASE==1) ? HS  : FFN;
  constexpr int N  = (PHASE==1) ? FFN : HS;
  constexpr int KB = K/32;
  const __nv_bfloat16* __restrict__ Ah_g = (PHASE==1) ? g_xb_hi : g_h_hi;
  const __nv_bfloat16* __restrict__ Al_g = (PHASE==1) ? g_xb_lo : g_h_lo;
  const __nv_bfloat16* __restrict__ Bh_g = (PHASE==1) ? g_w1_hi : g_w2_hi;
  const __nv_bfloat16* __restrict__ Bl_g = (PHASE==1) ? g_w1_lo : g_w2_lo;

  extern __shared__ __align__(16) __nv_bfloat16 sm[];
  // stage layout (elems): Ah[128][40]=5120 | Al=5120 | Bh[32][136]=4352 | Bl=4352  => 18944/stage

  const int e  = blockIdx.z;
  const int m0 = blockIdx.y * 128;
  const int n0 = blockIdx.x * 128;
  const size_t Abase = (size_t)e*CAP*K;
  const size_t Bbase = (size_t)e*K*N;
  const size_t Cbase = (size_t)e*CAP*N;

  const int tid = threadIdx.x;
  const int warp = tid >> 5, lane = tid & 31;
  const int wm = warp >> 2, wn = warp & 3;

  const int ar = tid >> 2,  ac = (tid & 3)  * 8;   // A tile: 128 rows x 32 cols (4x16B per row)
  const int br = tid >> 4,  bc = (tid & 15) * 8;   // B tile: 32 rows x 128 cols (16x16B per row)

  float acc[2][4][4];
  #pragma unroll
  for (int i=0;i<2;i++)
    #pragma unroll
    for (int j=0;j<4;j++)
      #pragma unroll
      for (int k=0;k<4;k++) acc[i][j][k]=0.f;

  { // prefetch stage 0
    __nv_bfloat16* s = sm;
    cp16(s +         ar*40 + ac, Ah_g + Abase + (size_t)(m0+ar)*K + ac);
    cp16(s + 5120  + ar*40 + ac, Al_g + Abase + (size_t)(m0+ar)*K + ac);
    cp16(s + 10240 + br*136 + bc, Bh_g + Bbase + (size_t)br*N + n0 + bc);
    cp16(s + 14592 + br*136 + bc, Bl_g + Bbase + (size_t)br*N + n0 + bc);
    cp_commit();
  }
  for (int kb=0; kb<KB; kb++){
    if (kb+1 < KB){
      const int k0 = (kb+1)*32;
      __nv_bfloat16* s = sm + ((kb+1)&1)*18944;
      cp16(s +         ar*40 + ac, Ah_g + Abase + (size_t)(m0+ar)*K + k0 + ac);
      cp16(s + 5120  + ar*40 + ac, Al_g + Abase + (size_t)(m0+ar)*K + k0 + ac);
      cp16(s + 10240 + br*136 + bc, Bh_g + Bbase + (size_t)(k0+br)*N + n0 + bc);
      cp16(s + 14592 + br*136 + bc, Bl_g + Bbase + (size_t)(k0+br)*N + n0 + bc);
      cp_commit();
      cp_wait<1>();
    } else {
      cp_wait<0>();
    }
    __syncthreads();
    const __nv_bfloat16* s = sm + (kb&1)*18944;
    #pragma unroll
    for (int ks=0; ks<2; ks++){
      uint32_t ah[2][4], al[2][4];
      #pragma unroll
      for (int mt=0; mt<2; mt++){
        const __nv_bfloat16* p = s + (wm*32 + mt*16 + (lane&15))*40 + ks*16 + (lane>>4)*8;
        ldsm4(ah[mt], p);
        ldsm4(al[mt], p + 5120);
      }
      uint32_t bh[2][4], bl[2][4];
      #pragma unroll
      for (int nh=0; nh<2; nh++){
        const __nv_bfloat16* p = s + 10240 + (ks*16 + (lane&15))*136 + wn*32 + nh*16 + (lane>>4)*8;
        ldsm4t(bh[nh], p);
        ldsm4t(bl[nh], p + 4352);
      }
      #pragma unroll
      for (int mt=0; mt<2; mt++){
        #pragma unroll
        for (int nt=0; nt<4; nt++){
          const int nh = nt>>1, sb = (nt&1)*2;
          mma_bf16(acc[mt][nt], ah[mt], bh[nh][sb], bh[nh][sb+1]);  // hi*hi
          mma_bf16(acc[mt][nt], ah[mt], bl[nh][sb], bl[nh][sb+1]);  // hi*lo
          mma_bf16(acc[mt][nt], al[mt], bh[nh][sb], bh[nh][sb+1]);  // lo*hi
        }
      }
    }
    __syncthreads();
  }
  // epilogue
  const int g = lane>>2, tg = lane&3;
  #pragma unroll
  for (int mt=0; mt<2; mt++){
    #pragma unroll
    for (int nt=0; nt<4; nt++){
      const int row = m0 + wm*32 + mt*16 + g;
      const int col = n0 + wn*32 + nt*8 + tg*2;
      float v0=acc[mt][nt][0], v1=acc[mt][nt][1], v2=acc[mt][nt][2], v3=acc[mt][nt][3];
      if constexpr (PHASE==1){
        v0=gelu_tanh(v0); v1=gelu_tanh(v1); v2=gelu_tanh(v2); v3=gelu_tanh(v3);
        __nv_bfloat16 h0=__float2bfloat16(v0), h1=__float2bfloat16(v1);
        __nv_bfloat16 l0=__float2bfloat16(v0-__bfloat162float(h0));
        __nv_bfloat16 l1=__float2bfloat16(v1-__bfloat162float(h1));
        size_t o = Cbase + (size_t)row*N + col;
        *(__nv_bfloat162*)&g_h_hi[o] = __halves2bfloat162(h0,h1);
        *(__nv_bfloat162*)&g_h_lo[o] = __halves2bfloat162(l0,l1);
        __nv_bfloat16 h2=__float2bfloat16(v2), h3=__float2bfloat16(v3);
        __nv_bfloat16 l2=__float2bfloat16(v2-__bfloat162float(h2));
        __nv_bfloat16 l3=__float2bfloat16(v3-__bfloat162float(h3));
        size_t o2 = Cbase + (size_t)(row+8)*N + col;
        *(__nv_bfloat162*)&g_h_hi[o2] = __halves2bfloat162(h2,h3);
        *(__nv_bfloat162*)&g_h_lo[o2] = __halves2bfloat162(l2,l3);
      } else {
        *(float2*)&g_y[Cbase + (size_t)row*N + col]     = make_float2(v0,v1);
        *(float2*)&g_y[Cbase + (size_t)(row+8)*N + col] = make_float2(v2,v3);
      }
    }
  }
}

// ---------------- per-token weighted combine + bias ----------------
__global__ void scatter_kernel(const float* __restrict__ bias, float* __restrict__ out){
  int t = blockIdx.x;
  int s0 = g_dst_slot[2*t], s1 = g_dst_slot[2*t+1];
  float w0 = g_top_w[2*t], w1 = g_top_w[2*t+1];
  const float4* y0 = (const float4*)(g_y + (size_t)(s0 < 0 ? 0 : s0)*HS);
  const float4* y1 = (const float4*)(g_y + (size_t)(s1 < 0 ? 0 : s1)*HS);
  const float4* b4 = (const float4*)bias;
  float4* o = (float4*)(out + (size_t)t*HS);
  for (int j = threadIdx.x; j < HS/4; j += blockDim.x){
    float4 r = b4[j];
    if (s0 >= 0){ float4 v = y0[j]; r.x += w0*v.x; r.y += w0*v.y; r.z += w0*v.z; r.w += w0*v.w; }
    if (s1 >= 0){ float4 v = y1[j]; r.x += w1*v.x; r.y += w1*v.y; r.z += w1*v.z; r.w += w1*v.w; }
    o[j] = r;
  }
}

// ---------------- launcher ----------------
extern "C" void kernel_launch(void* const* d_in, const int* in_sizes, int n_in,
                              void* d_out, int out_size){
  const float* x    = (const float*)d_in[0];
  const float* wr   = (const float*)d_in[1];
  const float* w1   = (const float*)d_in[2];
  const float* w2   = (const float*)d_in[3];
  const float* bias = (const float*)d_in[4];
  float* out = (float*)d_out;

  cudaFuncSetAttribute(gemm_split_kernel<1>, cudaFuncAttributeMaxDynamicSharedMemorySize, GEMM_SMEM_BYTES);
  cudaFuncSetAttribute(gemm_split_kernel<2>, cudaFuncAttributeMaxDynamicSharedMemorySize, GEMM_SMEM_BYTES);

  const int n4 = NEXP*HS*FFN/4;
  split_w_kernel<<<(n4+255)/256, 256>>>(w1, 0);
  split_w_kernel<<<(n4+255)/256, 256>>>(w2, 1);
  router_kernel<<<T_TOK/8, 256>>>(x, wr);
  scan_kernel<<<1, 256>>>();
  gather_split_kernel<<<NASSIGN, 128>>>(x);
  gemm_split_kernel<1><<<dim3(FFN/128, CAP/128, NEXP), 512, GEMM_SMEM_BYTES>>>();
  gemm_split_kernel<2><<<dim3(HS/128,  CAP/128, NEXP), 512, GEMM_SMEM_BYTES>>>();
  scatter_kernel<<<T_TOK, 128>>>(bias, out);
}

// round 7
// speedup vs baseline: 1.2379x; 1.2379x over previous
#include <cuda_runtime.h>
#include <cuda_bf16.h>
#include <math.h>
#include <stdint.h>

#define T_TOK   16384
#define HS      1024
#define FFN     4096
#define NEXP    8
#define CAP     4096
#define NASSIGN (2*T_TOK)
#define SLOTS   (NEXP*CAP)

// Arch-accelerated feature gate: tcgen05 is only legal in sm_10Xa targets.
// In baseline compute_103 passes this collapses the tcgen05 kernels to empty
// bodies so the PTX stays legal everywhere.
#if defined(__CUDA_ARCH_FEAT_SM103_ALL) || defined(__CUDA_ARCH_FEAT_SM100_ALL) || defined(__CUDA_ARCH_FEAT_SM101_ALL)
#define HAS_TCGEN05 1
#else
#define HAS_TCGEN05 0
#endif

// ---------------- static device scratch ----------------
__device__ __nv_bfloat16 g_xb_hi[(size_t)SLOTS*HS];
__device__ __nv_bfloat16 g_xb_lo[(size_t)SLOTS*HS];
__device__ __nv_bfloat16 g_h_hi[(size_t)SLOTS*FFN];
__device__ __nv_bfloat16 g_h_lo[(size_t)SLOTS*FFN];
__device__ float         g_y[(size_t)SLOTS*HS];
// tcgen05 path: weights transposed to [E][N][K] K-major, split hi/lo
__device__ __nv_bfloat16 g_w1t_hi[(size_t)NEXP*FFN*HS];
__device__ __nv_bfloat16 g_w1t_lo[(size_t)NEXP*FFN*HS];
__device__ __nv_bfloat16 g_w2t_hi[(size_t)NEXP*HS*FFN];
__device__ __nv_bfloat16 g_w2t_lo[(size_t)NEXP*HS*FFN];
// HMMA fallback path: weights in original [E][K][N], split hi/lo
__device__ __nv_bfloat16 g_w1_hi[(size_t)NEXP*HS*FFN];
__device__ __nv_bfloat16 g_w1_lo[(size_t)NEXP*HS*FFN];
__device__ __nv_bfloat16 g_w2_hi[(size_t)NEXP*FFN*HS];
__device__ __nv_bfloat16 g_w2_lo[(size_t)NEXP*FFN*HS];
__device__ int           g_top_e[NASSIGN];
__device__ float         g_top_w[NASSIGN];
__device__ int           g_dst_slot[NASSIGN];

// ---------------- arch-neutral helpers ----------------
__device__ __forceinline__ uint32_t smem_addr32(const void* p){
  return (uint32_t)__cvta_generic_to_shared(p);
}
__device__ __forceinline__ void cp16s(uint32_t dst, const void* src){
  asm volatile("cp.async.cg.shared.global [%0], [%1], 16;\n" :: "r"(dst), "l"(src));
}
__device__ __forceinline__ void cp_commit(){ asm volatile("cp.async.commit_group;\n"); }
template<int NW> __device__ __forceinline__ void cp_wait(){
  asm volatile("cp.async.wait_group %0;\n" :: "n"(NW));
}
__device__ __forceinline__ void ldsm4(uint32_t* r, const __nv_bfloat16* p){
  uint32_t a = smem_addr32(p);
  asm volatile("ldmatrix.sync.aligned.m8n8.x4.shared.b16 {%0,%1,%2,%3}, [%4];\n"
    : "=r"(r[0]),"=r"(r[1]),"=r"(r[2]),"=r"(r[3]) : "r"(a));
}
__device__ __forceinline__ void ldsm4t(uint32_t* r, const __nv_bfloat16* p){
  uint32_t a = smem_addr32(p);
  asm volatile("ldmatrix.sync.aligned.m8n8.x4.trans.shared.b16 {%0,%1,%2,%3}, [%4];\n"
    : "=r"(r[0]),"=r"(r[1]),"=r"(r[2]),"=r"(r[3]) : "r"(a));
}
__device__ __forceinline__ void mma_bf16(float* c, const uint32_t* a, uint32_t b0, uint32_t b1){
  asm volatile("mma.sync.aligned.m16n8k16.row.col.f32.bf16.bf16.f32 "
    "{%0,%1,%2,%3}, {%4,%5,%6,%7}, {%8,%9}, {%0,%1,%2,%3};\n"
    : "+f"(c[0]),"+f"(c[1]),"+f"(c[2]),"+f"(c[3])
    : "r"(a[0]),"r"(a[1]),"r"(a[2]),"r"(a[3]), "r"(b0),"r"(b1));
}
__device__ __forceinline__ uint32_t sw128(uint32_t off){ return off ^ ((off >> 3) & 0x70); }
__device__ __forceinline__ float gelu_tanh(float x){
  float u = 0.7978845608028654f*(x + 0.044715f*x*x*x);
  return 0.5f*x*(1.0f + tanhf(u));
}

// ---------------- tcgen05 helpers (only referenced inside gated bodies) -------
__device__ __forceinline__ uint32_t elect_one(){
  uint32_t pred;
  asm volatile("{\n.reg .pred p;\nelect.sync _|p, 0xFFFFFFFF;\nselp.b32 %0, 1, 0, p;\n}" : "=r"(pred));
  return pred;
}
__device__ __forceinline__ void mbar_init(uint32_t a, uint32_t cnt){
  asm volatile("mbarrier.init.shared.b64 [%0], %1;" :: "r"(a), "r"(cnt) : "memory");
}
__device__ __forceinline__ void mbar_wait(uint32_t a, uint32_t parity){
  asm volatile("{\n.reg .pred P;\nLW%=:\nmbarrier.try_wait.parity.acquire.cta.shared::cta.b64 P, [%0], %1, 0x989680;\n@!P bra LW%=;\n}"
    :: "r"(a), "r"(parity) : "memory");
}
#if HAS_TCGEN05
__device__ __forceinline__ void tcg_alloc(uint32_t dst_smem, uint32_t ncols){
  asm volatile("tcgen05.alloc.cta_group::1.sync.aligned.shared::cta.b32 [%0], %1;" :: "r"(dst_smem), "r"(ncols) : "memory");
}
__device__ __forceinline__ void tcg_dealloc(uint32_t tmem, uint32_t ncols){
  asm volatile("tcgen05.dealloc.cta_group::1.sync.aligned.b32 %0, %1;" :: "r"(tmem), "r"(ncols));
}
__device__ __forceinline__ void tcg_relinquish(){
  asm volatile("tcgen05.relinquish_alloc_permit.cta_group::1.sync.aligned;");
}
__device__ __forceinline__ void tcg_commit(uint32_t mbar){
  asm volatile("tcgen05.commit.cta_group::1.mbarrier::arrive::one.shared::cluster.b64 [%0];" :: "r"(mbar) : "memory");
}
__device__ __forceinline__ void tcg_fence_after(){
  asm volatile("tcgen05.fence::after_thread_sync;" ::: "memory");
}
__device__ __forceinline__ void fence_proxy_async_cta(){
  asm volatile("fence.proxy.async.shared::cta;" ::: "memory");
}
__device__ __forceinline__ void mma_f16_ss(uint32_t d, uint64_t a, uint64_t b, uint32_t idesc, uint32_t en){
  asm volatile("{\n.reg .pred p;\nsetp.ne.u32 p, %4, 0;\n"
    "tcgen05.mma.cta_group::1.kind::f16 [%0], %1, %2, %3, {%5,%5,%5,%5}, p;\n}"
    :: "r"(d), "l"(a), "l"(b), "r"(idesc), "r"(en), "r"(0u) : "memory");
}
__device__ __forceinline__ void ldtm32(uint32_t* r, uint32_t addr){
  asm volatile("tcgen05.ld.sync.aligned.32x32b.x32.b32 "
    "{%0,%1,%2,%3,%4,%5,%6,%7,%8,%9,%10,%11,%12,%13,%14,%15,"
    "%16,%17,%18,%19,%20,%21,%22,%23,%24,%25,%26,%27,%28,%29,%30,%31}, [%32];"
    : "=r"(r[0]),"=r"(r[1]),"=r"(r[2]),"=r"(r[3]),"=r"(r[4]),"=r"(r[5]),"=r"(r[6]),"=r"(r[7]),
      "=r"(r[8]),"=r"(r[9]),"=r"(r[10]),"=r"(r[11]),"=r"(r[12]),"=r"(r[13]),"=r"(r[14]),"=r"(r[15]),
      "=r"(r[16]),"=r"(r[17]),"=r"(r[18]),"=r"(r[19]),"=r"(r[20]),"=r"(r[21]),"=r"(r[22]),"=r"(r[23]),
      "=r"(r[24]),"=r"(r[25]),"=r"(r[26]),"=r"(r[27]),"=r"(r[28]),"=r"(r[29]),"=r"(r[30]),"=r"(r[31])
    : "r"(addr));
}
__device__ __forceinline__ void tcg_wait_ld(){
  asm volatile("tcgen05.wait::ld.sync.aligned;" ::: "memory");
}
__device__ __forceinline__ uint64_t make_desc(uint32_t base_addr){
  const uint64_t BASE = (uint64_t(2) << 61) | (uint64_t(1) << 46) | (uint64_t(64) << 32) | (uint64_t(1) << 16);
  return BASE | ((uint64_t)(base_addr >> 4) & 0x3FFF);
}
#endif

// ---------------- router: fp64 logits + softmax + top-2 ----------------
__global__ void router_kernel(const float* __restrict__ x, const float* __restrict__ wr){
  int widx = (blockIdx.x * blockDim.x + threadIdx.x) >> 5;
  int lane = threadIdx.x & 31;
  if (widx >= T_TOK) return;
  const float* xr = x + (size_t)widx * HS;
  double acc[NEXP];
  #pragma unroll
  for (int e=0;e<NEXP;e++) acc[e]=0.0;
  for (int h = lane; h < HS; h += 32){
    double xv = (double)xr[h];
    const float* wrow = wr + h*NEXP;
    #pragma unroll
    for (int e=0;e<NEXP;e++) acc[e] += xv * (double)wrow[e];
  }
  #pragma unroll
  for (int off=16; off; off>>=1){
    #pragma unroll
    for (int e=0;e<NEXP;e++) acc[e] += __shfl_xor_sync(0xffffffffu, acc[e], off);
  }
  if (lane == 0){
    double m = acc[0];
    #pragma unroll
    for (int e=1;e<NEXP;e++) m = fmax(m, acc[e]);
    double ex[NEXP], s = 0.0;
    #pragma unroll
    for (int e=0;e<NEXP;e++){ ex[e] = exp(acc[e]-m); s += ex[e]; }
    int e0 = 0; double b0 = acc[0];
    #pragma unroll
    for (int e=1;e<NEXP;e++) if (acc[e] > b0){ b0 = acc[e]; e0 = e; }
    int e1 = (e0==0) ? 1 : 0; double b1 = acc[e1];
    #pragma unroll
    for (int e=0;e<NEXP;e++) if (e != e0 && acc[e] > b1){ b1 = acc[e]; e1 = e; }
    g_top_e[2*widx]   = e0;
    g_top_e[2*widx+1] = e1;
    g_top_w[2*widx]   = (float)(ex[e0]/s);
    g_top_w[2*widx+1] = (float)(ex[e1]/s);
  }
}

// ---------------- stable counting sort + capacity (hierarchical scan) ----------------
__global__ void __launch_bounds__(1024,1) scan_kernel(){
  __shared__ int wbase[32][NEXP];
  __shared__ int etot[NEXP];
  __shared__ int starts[NEXP];
  int t = threadIdx.x, lane = t & 31, w = t >> 5;
  const int i0 = t * 32;
  int e_loc[32];
  int cnt[NEXP];
  #pragma unroll
  for (int e=0;e<NEXP;e++) cnt[e]=0;
  #pragma unroll
  for (int j=0;j<32;j++){ e_loc[j] = g_top_e[i0+j]; cnt[e_loc[j]]++; }
  int excl[NEXP];
  #pragma unroll
  for (int e=0;e<NEXP;e++){
    int v = cnt[e], s = v;
    #pragma unroll
    for (int off=1; off<32; off<<=1){
      int n = __shfl_up_sync(0xffffffffu, s, off);
      if (lane >= off) s += n;
    }
    excl[e] = s - v;
    if (lane == 31) wbase[w][e] = s;
  }
  __syncthreads();
  if (w == 0){
    #pragma unroll
    for (int e=0;e<NEXP;e++){
      int v = wbase[lane][e], s = v;
      #pragma unroll
      for (int off=1; off<32; off<<=1){
        int n = __shfl_up_sync(0xffffffffu, s, off);
        if (lane >= off) s += n;
      }
      wbase[lane][e] = s - v;
      if (lane == 31) etot[e] = s;
    }
  }
  __syncthreads();
  if (t == 0){
    int run = 0;
    #pragma unroll
    for (int e=0;e<NEXP;e++){ starts[e] = run; run += etot[e]; }
  }
  __syncthreads();
  int base[NEXP];
  #pragma unroll
  for (int e=0;e<NEXP;e++) base[e] = starts[e] + wbase[w][e] + excl[e];
  #pragma unroll
  for (int j=0;j<32;j++){
    int e = e_loc[j];
    int pos = base[e]++;
    int r = pos - starts[e];
    g_dst_slot[i0+j] = (r < CAP) ? (e*CAP + r) : -1;
  }
}

// ---------------- gather token rows -> slot buffer, split fp32 -> bf16 hi/lo ----------------
__global__ void gather_split_kernel(const float* __restrict__ x){
  int i = blockIdx.x;
  int dst = g_dst_slot[i];
  if (dst < 0) return;
  const float4* src = (const float4*)(x + (size_t)(i>>1)*HS);
  __nv_bfloat16* hi = g_xb_hi + (size_t)dst*HS;
  __nv_bfloat16* lo = g_xb_lo + (size_t)dst*HS;
  for (int j = threadIdx.x; j < HS/4; j += blockDim.x){
    float4 v = src[j];
    __nv_bfloat16 hx=__float2bfloat16(v.x), hy=__float2bfloat16(v.y);
    __nv_bfloat16 hz=__float2bfloat16(v.z), hw=__float2bfloat16(v.w);
    __nv_bfloat16 lx=__float2bfloat16(v.x-__bfloat162float(hx));
    __nv_bfloat16 ly=__float2bfloat16(v.y-__bfloat162float(hy));
    __nv_bfloat16 lz=__float2bfloat16(v.z-__bfloat162float(hz));
    __nv_bfloat16 lw=__float2bfloat16(v.w-__bfloat162float(hw));
    *(__nv_bfloat162*)&hi[j*4]   = __halves2bfloat162(hx,hy);
    *(__nv_bfloat162*)&hi[j*4+2] = __halves2bfloat162(hz,hw);
    *(__nv_bfloat162*)&lo[j*4]   = __halves2bfloat162(lx,ly);
    *(__nv_bfloat162*)&lo[j*4+2] = __halves2bfloat162(lz,lw);
  }
}

// ---------------- tcgen05-path weight transpose [E][K][N] -> [E][N][K] + split ----------
__global__ void transpose_split_kernel(const float* __restrict__ w,
                                       __nv_bfloat16* __restrict__ hi,
                                       __nv_bfloat16* __restrict__ lo,
                                       int K, int N){
#if HAS_TCGEN05
  __shared__ float tile[32][33];
  int e = blockIdx.z;
  int n0 = blockIdx.x*32, k0 = blockIdx.y*32;
  int tx = threadIdx.x, ty = threadIdx.y;   // 32 x 8
  const float* in = w + (size_t)e*K*N;
  #pragma unroll
  for (int r=0;r<4;r++)
    tile[ty+8*r][tx] = in[(size_t)(k0+ty+8*r)*N + n0+tx];
  __syncthreads();
  #pragma unroll
  for (int r=0;r<4;r++){
    float v = tile[tx][ty+8*r];
    __nv_bfloat16 h = __float2bfloat16(v);
    __nv_bfloat16 l = __float2bfloat16(v - __bfloat162float(h));
    size_t o = ((size_t)e*N + n0+ty+8*r)*K + k0+tx;
    hi[o] = h; lo[o] = l;
  }
#endif
}

// ---------------- HMMA-path weight split fp32 -> bf16 hi/lo ([E][K][N]) --------
__global__ void split_w_kernel(const float* __restrict__ w, int which){
#if !HAS_TCGEN05
  __nv_bfloat16* hi = which ? g_w2_hi : g_w1_hi;
  __nv_bfloat16* lo = which ? g_w2_lo : g_w1_lo;
  size_t i = (size_t)blockIdx.x*blockDim.x + threadIdx.x;
  const size_t n4 = (size_t)NEXP*HS*FFN/4;
  if (i >= n4) return;
  float4 v = ((const float4*)w)[i];
  __nv_bfloat16 hx=__float2bfloat16(v.x), hy=__float2bfloat16(v.y);
  __nv_bfloat16 hz=__float2bfloat16(v.z), hw=__float2bfloat16(v.w);
  __nv_bfloat16 lx=__float2bfloat16(v.x-__bfloat162float(hx));
  __nv_bfloat16 ly=__float2bfloat16(v.y-__bfloat162float(hy));
  __nv_bfloat16 lz=__float2bfloat16(v.z-__bfloat162float(hz));
  __nv_bfloat16 lw=__float2bfloat16(v.w-__bfloat162float(hw));
  *(__nv_bfloat162*)&hi[i*4]   = __halves2bfloat162(hx,hy);
  *(__nv_bfloat162*)&hi[i*4+2] = __halves2bfloat162(hz,hw);
  *(__nv_bfloat162*)&lo[i*4]   = __halves2bfloat162(lx,ly);
  *(__nv_bfloat162*)&lo[i*4+2] = __halves2bfloat162(lz,lw);
#endif
}

// =====================================================================
// PATH A: tcgen05 grouped GEMM (128x256 tile, K-chunk 64, 3-product split)
// empty body unless the binary was built for an sm_10Xa target
// =====================================================================
#define GSMEM (197632)
#define STAGE_BYTES 98304

template<int PHASE>
__global__ void __launch_bounds__(256,1) gemm_tc_kernel(){
#if HAS_TCGEN05
  constexpr int Kdim = (PHASE==1) ? HS  : FFN;
  constexpr int Ndim = (PHASE==1) ? FFN : HS;
  constexpr int NKB  = Kdim/64;
  const __nv_bfloat16* __restrict__ Ah_g = (PHASE==1) ? g_xb_hi  : g_h_hi;
  const __nv_bfloat16* __restrict__ Al_g = (PHASE==1) ? g_xb_lo  : g_h_lo;
  const __nv_bfloat16* __restrict__ Bh_g = (PHASE==1) ? g_w1t_hi : g_w2t_hi;
  const __nv_bfloat16* __restrict__ Bl_g = (PHASE==1) ? g_w1t_lo : g_w2t_lo;

  extern __shared__ char dyn[];
  __shared__ uint64_t s_mbar[2];
  __shared__ uint32_t s_tptr;
  uint32_t sbase = (smem_addr32(dyn) + 1023u) & ~1023u;
  uint32_t mbar_a[2] = { smem_addr32(&s_mbar[0]), smem_addr32(&s_mbar[1]) };

  const int tid = threadIdx.x;
  const int wid = tid >> 5, lane = tid & 31;
  const int e  = blockIdx.z;
  const int m0 = blockIdx.y * 128;
  const int n0 = blockIdx.x * 256;
  const size_t Abase = ((size_t)e*CAP  + m0) * Kdim;
  const size_t Bbase = ((size_t)e*Ndim + n0) * Kdim;

  if (wid == 0) tcg_alloc(smem_addr32(&s_tptr), 256);
  if (tid == 0){ mbar_init(mbar_a[0], 1); mbar_init(mbar_a[1], 1); }
  __syncthreads();
  const uint32_t tmem = s_tptr;

  auto load_stage = [&](int buf, int kb){
    uint32_t st = sbase + buf*STAGE_BYTES;
    const int k0 = kb*64;
    #pragma unroll
    for (int i=0;i<4;i++){
      int id = tid*4 + i;
      int r = id >> 3, c8 = id & 7;
      uint32_t sw = sw128((uint32_t)(r*128 + c8*16));
      const size_t g = Abase + (size_t)r*Kdim + k0 + c8*8;
      cp16s(st +         sw, Ah_g + g);
      cp16s(st + 16384 + sw, Al_g + g);
    }
    #pragma unroll
    for (int i=0;i<8;i++){
      int id = tid*8 + i;
      int r = id >> 3, c8 = id & 7;
      uint32_t sw = sw128((uint32_t)(r*128 + c8*16));
      const size_t g = Bbase + (size_t)r*Kdim + k0 + c8*8;
      cp16s(st + 32768 + sw, Bh_g + g);
      cp16s(st + 65536 + sw, Bl_g + g);
    }
    cp_commit();
  };

  load_stage(0, 0);
  load_stage(1, 1);

  const uint32_t idesc = (1u<<4) | (1u<<7) | (1u<<10) | ((256u>>3)<<17) | ((128u>>4)<<24);
  int ph[2] = {0, 0};

  for (int kb = 0; kb < NKB; kb++){
    const int buf = kb & 1;
    if (kb + 1 < NKB) cp_wait<1>(); else cp_wait<0>();
    __syncthreads();
    if (wid == 0 && elect_one()){
      fence_proxy_async_cta();
      uint32_t st = sbase + buf*STAGE_BYTES;
      uint64_t dAh = make_desc(st);
      uint64_t dAl = make_desc(st + 16384);
      uint64_t dBh = make_desc(st + 32768);
      uint64_t dBl = make_desc(st + 65536);
      #pragma unroll
      for (int ks=0; ks<4; ks++){
        uint32_t first = (kb==0 && ks==0) ? 0u : 1u;
        mma_f16_ss(tmem, dAh + ks*2, dBh + ks*2, idesc, first);
        mma_f16_ss(tmem, dAh + ks*2, dBl + ks*2, idesc, 1u);
        mma_f16_ss(tmem, dAl + ks*2, dBh + ks*2, idesc, 1u);
      }
      tcg_commit(mbar_a[buf]);
    }
    if (kb + 2 < NKB){
      mbar_wait(mbar_a[buf], ph[buf]); ph[buf] ^= 1;
      load_stage(buf, kb + 2);
    }
  }
  {
    const int lb = (NKB-1) & 1;
    mbar_wait(mbar_a[lb], ph[lb]);
  }
  tcg_fence_after();

  if (wid < 4){
    const int row = m0 + wid*32 + lane;
    const size_t slot = (size_t)e*CAP + row;
    #pragma unroll
    for (int ch=0; ch<8; ch++){
      uint32_t r[32];
      ldtm32(r, tmem + ch*32);
      tcg_wait_ld();
      const int nc = n0 + ch*32;
      if constexpr (PHASE==1){
        size_t o = slot*FFN + nc;
        #pragma unroll
        for (int j=0;j<32;j+=2){
          float v0 = gelu_tanh(__uint_as_float(r[j]));
          float v1 = gelu_tanh(__uint_as_float(r[j+1]));
          __nv_bfloat16 h0=__float2bfloat16(v0), h1=__float2bfloat16(v1);
          __nv_bfloat16 l0=__float2bfloat16(v0-__bfloat162float(h0));
          __nv_bfloat16 l1=__float2bfloat16(v1-__bfloat162float(h1));
          *(__nv_bfloat162*)&g_h_hi[o+j] = __halves2bfloat162(h0,h1);
          *(__nv_bfloat162*)&g_h_lo[o+j] = __halves2bfloat162(l0,l1);
        }
      } else {
        size_t o = slot*HS + nc;
        #pragma unroll
        for (int j=0;j<32;j+=4){
          float4 v = make_float4(__uint_as_float(r[j]), __uint_as_float(r[j+1]),
                                 __uint_as_float(r[j+2]), __uint_as_float(r[j+3]));
          *(float4*)&g_y[o+j] = v;
        }
      }
    }
  }
  __syncthreads();
  if (wid == 0){
    tcg_relinquish();
    tcg_dealloc(tmem, 256);
  }
#endif
}

// =====================================================================
// PATH B: HMMA mma.sync grouped GEMM (round-1 proven kernel)
// empty body when the tcgen05 binary is the one loaded
// =====================================================================
#define HSMEM 75776
template<int PHASE>
__global__ void __launch_bounds__(512,1) gemm_split_kernel(){
#if !HAS_TCGEN05
  constexpr int K  = (PHASE==1) ? HS  : FFN;
  constexpr int N  = (PHASE==1) ? FFN : HS;
  constexpr int KB = K/32;
  const __nv_bfloat16* __restrict__ Ah_g = (PHASE==1) ? g_xb_hi : g_h_hi;
  const __nv_bfloat16* __restrict__ Al_g = (PHASE==1) ? g_xb_lo : g_h_lo;
  const __nv_bfloat16* __restrict__ Bh_g = (PHASE==1) ? g_w1_hi : g_w2_hi;
  const __nv_bfloat16* __restrict__ Bl_g = (PHASE==1) ? g_w1_lo : g_w2_lo;

  extern __shared__ __align__(16) __nv_bfloat16 sm[];

  const int e  = blockIdx.z;
  const int m0 = blockIdx.y * 128;
  const int n0 = blockIdx.x * 128;
  const size_t Abase = (size_t)e*CAP*K;
  const size_t Bbase = (size_t)e*K*N;
  const size_t Cbase = (size_t)e*CAP*N;

  const int tid = threadIdx.x;
  const int warp = tid >> 5, lane = tid & 31;
  const int wm = warp >> 2, wn = warp & 3;

  const int ar = tid >> 2,  ac = (tid & 3)  * 8;
  const int br = tid >> 4,  bc = (tid & 15) * 8;

  float acc[2][4][4];
  #pragma unroll
  for (int i=0;i<2;i++)
    #pragma unroll
    for (int j=0;j<4;j++)
      #pragma unroll
      for (int k=0;k<4;k++) acc[i][j][k]=0.f;

  {
    __nv_bfloat16* s = sm;
    cp16s(smem_addr32(s +         ar*40 + ac), Ah_g + Abase + (size_t)(m0+ar)*K + ac);
    cp16s(smem_addr32(s + 5120  + ar*40 + ac), Al_g + Abase + (size_t)(m0+ar)*K + ac);
    cp16s(smem_addr32(s + 10240 + br*136 + bc), Bh_g + Bbase + (size_t)br*N + n0 + bc);
    cp16s(smem_addr32(s + 14592 + br*136 + bc), Bl_g + Bbase + (size_t)br*N + n0 + bc);
    cp_commit();
  }
  for (int kb=0; kb<KB; kb++){
    if (kb+1 < KB){
      const int k0 = (kb+1)*32;
      __nv_bfloat16* s = sm + ((kb+1)&1)*18944;
      cp16s(smem_addr32(s +         ar*40 + ac), Ah_g + Abase + (size_t)(m0+ar)*K + k0 + ac);
      cp16s(smem_addr32(s + 5120  + ar*40 + ac), Al_g + Abase + (size_t)(m0+ar)*K + k0 + ac);
      cp16s(smem_addr32(s + 10240 + br*136 + bc), Bh_g + Bbase + (size_t)(k0+br)*N + n0 + bc);
      cp16s(smem_addr32(s + 14592 + br*136 + bc), Bl_g + Bbase + (size_t)(k0+br)*N + n0 + bc);
      cp_commit();
      cp_wait<1>();
    } else {
      cp_wait<0>();
    }
    __syncthreads();
    const __nv_bfloat16* s = sm + (kb&1)*18944;
    #pragma unroll
    for (int ks=0; ks<2; ks++){
      uint32_t ah[2][4], al[2][4];
      #pragma unroll
      for (int mt=0; mt<2; mt++){
        const __nv_bfloat16* p = s + (wm*32 + mt*16 + (lane&15))*40 + ks*16 + (lane>>4)*8;
        ldsm4(ah[mt], p);
        ldsm4(al[mt], p + 5120);
      }
      uint32_t bh[2][4], bl[2][4];
      #pragma unroll
      for (int nh=0; nh<2; nh++){
        const __nv_bfloat16* p = s + 10240 + (ks*16 + (lane&15))*136 + wn*32 + nh*16 + (lane>>4)*8;
        ldsm4t(bh[nh], p);
        ldsm4t(bl[nh], p + 4352);
      }
      #pragma unroll
      for (int mt=0; mt<2; mt++){
        #pragma unroll
        for (int nt=0; nt<4; nt++){
          const int nh = nt>>1, sb = (nt&1)*2;
          mma_bf16(acc[mt][nt], ah[mt], bh[nh][sb], bh[nh][sb+1]);
          mma_bf16(acc[mt][nt], ah[mt], bl[nh][sb], bl[nh][sb+1]);
          mma_bf16(acc[mt][nt], al[mt], bh[nh][sb], bh[nh][sb+1]);
        }
      }
    }
    __syncthreads();
  }
  const int g = lane>>2, tg = lane&3;
  #pragma unroll
  for (int mt=0; mt<2; mt++){
    #pragma unroll
    for (int nt=0; nt<4; nt++){
      const int row = m0 + wm*32 + mt*16 + g;
      const int col = n0 + wn*32 + nt*8 + tg*2;
      float v0=acc[mt][nt][0], v1=acc[mt][nt][1], v2=acc[mt][nt][2], v3=acc[mt][nt][3];
      if constexpr (PHASE==1){
        v0=gelu_tanh(v0); v1=gelu_tanh(v1); v2=gelu_tanh(v2); v3=gelu_tanh(v3);
        __nv_bfloat16 h0=__float2bfloat16(v0), h1=__float2bfloat16(v1);
        __nv_bfloat16 l0=__float2bfloat16(v0-__bfloat162float(h0));
        __nv_bfloat16 l1=__float2bfloat16(v1-__bfloat162float(h1));
        size_t o = Cbase + (size_t)row*N + col;
        *(__nv_bfloat162*)&g_h_hi[o] = __halves2bfloat162(h0,h1);
        *(__nv_bfloat162*)&g_h_lo[o] = __halves2bfloat162(l0,l1);
        __nv_bfloat16 h2=__float2bfloat16(v2), h3=__float2bfloat16(v3);
        __nv_bfloat16 l2=__float2bfloat16(v2-__bfloat162float(h2));
        __nv_bfloat16 l3=__float2bfloat16(v3-__bfloat162float(h3));
        size_t o2 = Cbase + (size_t)(row+8)*N + col;
        *(__nv_bfloat162*)&g_h_hi[o2] = __halves2bfloat162(h2,h3);
        *(__nv_bfloat162*)&g_h_lo[o2] = __halves2bfloat162(l2,l3);
      } else {
        *(float2*)&g_y[Cbase + (size_t)row*N + col]     = make_float2(v0,v1);
        *(float2*)&g_y[Cbase + (size_t)(row+8)*N + col] = make_float2(v2,v3);
      }
    }
  }
#endif
}

// ---------------- per-token weighted combine + bias ----------------
__global__ void scatter_kernel(const float* __restrict__ bias, float* __restrict__ out){
  int t = blockIdx.x;
  int s0 = g_dst_slot[2*t], s1 = g_dst_slot[2*t+1];
  float w0 = g_top_w[2*t], w1 = g_top_w[2*t+1];
  const float4* y0 = (const float4*)(g_y + (size_t)(s0 < 0 ? 0 : s0)*HS);
  const float4* y1 = (const float4*)(g_y + (size_t)(s1 < 0 ? 0 : s1)*HS);
  const float4* b4 = (const float4*)bias;
  float4* o = (float4*)(out + (size_t)t*HS);
  for (int j = threadIdx.x; j < HS/4; j += blockDim.x){
    float4 r = b4[j];
    if (s0 >= 0){ float4 v = y0[j]; r.x += w0*v.x; r.y += w0*v.y; r.z += w0*v.z; r.w += w0*v.w; }
    if (s1 >= 0){ float4 v = y1[j]; r.x += w1*v.x; r.y += w1*v.y; r.z += w1*v.z; r.w += w1*v.w; }
    o[j] = r;
  }
}

// ---------------- launcher ----------------
extern "C" void kernel_launch(void* const* d_in, const int* in_sizes, int n_in,
                              void* d_out, int out_size){
  const float* x    = (const float*)d_in[0];
  const float* wr   = (const float*)d_in[1];
  const float* w1   = (const float*)d_in[2];
  const float* w2   = (const float*)d_in[3];
  const float* bias = (const float*)d_in[4];
  float* out = (float*)d_out;

  cudaFuncSetAttribute(gemm_tc_kernel<1>, cudaFuncAttributeMaxDynamicSharedMemorySize, GSMEM);
  cudaFuncSetAttribute(gemm_tc_kernel<2>, cudaFuncAttributeMaxDynamicSharedMemorySize, GSMEM);
  cudaFuncSetAttribute(gemm_split_kernel<1>, cudaFuncAttributeMaxDynamicSharedMemorySize, HSMEM);
  cudaFuncSetAttribute(gemm_split_kernel<2>, cudaFuncAttributeMaxDynamicSharedMemorySize, HSMEM);

  __nv_bfloat16 *w1t_hi, *w1t_lo, *w2t_hi, *w2t_lo;
  cudaGetSymbolAddress((void**)&w1t_hi, g_w1t_hi);
  cudaGetSymbolAddress((void**)&w1t_lo, g_w1t_lo);
  cudaGetSymbolAddress((void**)&w2t_hi, g_w2t_hi);
  cudaGetSymbolAddress((void**)&w2t_lo, g_w2t_lo);

  // weight preprocessing — each variant is a no-op in the binary that doesn't use it
  const int n4 = NEXP*HS*FFN/4;
  split_w_kernel<<<(n4+255)/256, 256>>>(w1, 0);
  split_w_kernel<<<(n4+255)/256, 256>>>(w2, 1);
  transpose_split_kernel<<<dim3(FFN/32, HS/32, NEXP), dim3(32,8)>>>(w1, w1t_hi, w1t_lo, HS, FFN);
  transpose_split_kernel<<<dim3(HS/32, FFN/32, NEXP), dim3(32,8)>>>(w2, w2t_hi, w2t_lo, FFN, HS);

  router_kernel<<<T_TOK/8, 256>>>(x, wr);
  scan_kernel<<<1, 1024>>>();
  gather_split_kernel<<<NASSIGN, 128>>>(x);

  // phase 1 (both variants; exactly one is non-empty in the loaded binary)
  gemm_tc_kernel<1><<<dim3(FFN/256, CAP/128, NEXP), 256, GSMEM>>>();
  gemm_split_kernel<1><<<dim3(FFN/128, CAP/128, NEXP), 512, HSMEM>>>();
  // phase 2
  gemm_tc_kernel<2><<<dim3(HS/256,  CAP/128, NEXP), 256, GSMEM>>>();
  gemm_split_kernel<2><<<dim3(HS/128,  CAP/128, NEXP), 512, HSMEM>>>();

  scatter_kernel<<<T_TOK, 128>>>(bias, out);
}

// round 8
// speedup vs baseline: 1.4687x; 1.1864x over previous
#include <cuda_runtime.h>
#include <cuda_bf16.h>
#include <math.h>
#include <stdint.h>

#define T_TOK   16384
#define HS      1024
#define FFN     4096
#define NEXP    8
#define CAP     4096
#define NASSIGN (2*T_TOK)
#define SLOTS   (NEXP*CAP)

#if defined(__CUDA_ARCH_FEAT_SM103_ALL) || defined(__CUDA_ARCH_FEAT_SM100_ALL) || defined(__CUDA_ARCH_FEAT_SM101_ALL)
#define HAS_TCGEN05 1
#else
#define HAS_TCGEN05 0
#endif

// ---------------- static device scratch ----------------
__device__ __nv_bfloat16 g_xb_hi[(size_t)SLOTS*HS];
__device__ __nv_bfloat16 g_xb_lo[(size_t)SLOTS*HS];
__device__ __nv_bfloat16 g_h_hi[(size_t)SLOTS*FFN];
__device__ __nv_bfloat16 g_h_lo[(size_t)SLOTS*FFN];
__device__ float         g_y[(size_t)SLOTS*HS];
// tcgen05 path: weights transposed to [E][N][K] K-major, split hi/lo
__device__ __nv_bfloat16 g_w1t_hi[(size_t)NEXP*FFN*HS];
__device__ __nv_bfloat16 g_w1t_lo[(size_t)NEXP*FFN*HS];
__device__ __nv_bfloat16 g_w2t_hi[(size_t)NEXP*HS*FFN];
__device__ __nv_bfloat16 g_w2t_lo[(size_t)NEXP*HS*FFN];
// HMMA fallback path: weights in original [E][K][N], split hi/lo
__device__ __nv_bfloat16 g_w1_hi[(size_t)NEXP*HS*FFN];
__device__ __nv_bfloat16 g_w1_lo[(size_t)NEXP*HS*FFN];
__device__ __nv_bfloat16 g_w2_hi[(size_t)NEXP*FFN*HS];
__device__ __nv_bfloat16 g_w2_lo[(size_t)NEXP*FFN*HS];
__device__ int           g_top_e[NASSIGN];
__device__ float         g_top_w[NASSIGN];
__device__ int           g_dst_slot[NASSIGN];

// ---------------- arch-neutral helpers ----------------
__device__ __forceinline__ uint32_t smem_addr32(const void* p){
  return (uint32_t)__cvta_generic_to_shared(p);
}
__device__ __forceinline__ void cp16s(uint32_t dst, const void* src){
  asm volatile("cp.async.cg.shared.global [%0], [%1], 16;\n" :: "r"(dst), "l"(src));
}
__device__ __forceinline__ void cp_commit(){ asm volatile("cp.async.commit_group;\n"); }
template<int NW> __device__ __forceinline__ void cp_wait(){
  asm volatile("cp.async.wait_group %0;\n" :: "n"(NW));
}
__device__ __forceinline__ void ldsm4(uint32_t* r, const __nv_bfloat16* p){
  uint32_t a = smem_addr32(p);
  asm volatile("ldmatrix.sync.aligned.m8n8.x4.shared.b16 {%0,%1,%2,%3}, [%4];\n"
    : "=r"(r[0]),"=r"(r[1]),"=r"(r[2]),"=r"(r[3]) : "r"(a));
}
__device__ __forceinline__ void ldsm4t(uint32_t* r, const __nv_bfloat16* p){
  uint32_t a = smem_addr32(p);
  asm volatile("ldmatrix.sync.aligned.m8n8.x4.trans.shared.b16 {%0,%1,%2,%3}, [%4];\n"
    : "=r"(r[0]),"=r"(r[1]),"=r"(r[2]),"=r"(r[3]) : "r"(a));
}
__device__ __forceinline__ void mma_bf16(float* c, const uint32_t* a, uint32_t b0, uint32_t b1){
  asm volatile("mma.sync.aligned.m16n8k16.row.col.f32.bf16.bf16.f32 "
    "{%0,%1,%2,%3}, {%4,%5,%6,%7}, {%8,%9}, {%0,%1,%2,%3};\n"
    : "+f"(c[0]),"+f"(c[1]),"+f"(c[2]),"+f"(c[3])
    : "r"(a[0]),"r"(a[1]),"r"(a[2]),"r"(a[3]), "r"(b0),"r"(b1));
}
__device__ __forceinline__ uint32_t sw64(uint32_t off){ return off ^ ((off >> 3) & 0x30); }
__device__ __forceinline__ float gelu_tanh(float x){
  float u = 0.7978845608028654f*(x + 0.044715f*x*x*x);
  return 0.5f*x*(1.0f + tanhf(u));
}
__device__ __forceinline__ uint32_t elect_one(){
  uint32_t pred;
  asm volatile("{\n.reg .pred p;\nelect.sync _|p, 0xFFFFFFFF;\nselp.b32 %0, 1, 0, p;\n}" : "=r"(pred));
  return pred;
}
__device__ __forceinline__ void mbar_init(uint32_t a, uint32_t cnt){
  asm volatile("mbarrier.init.shared.b64 [%0], %1;" :: "r"(a), "r"(cnt) : "memory");
}
__device__ __forceinline__ void mbar_wait(uint32_t a, uint32_t parity){
  asm volatile("{\n.reg .pred P;\nLW%=:\nmbarrier.try_wait.parity.acquire.cta.shared::cta.b64 P, [%0], %1, 0x989680;\n@!P bra LW%=;\n}"
    :: "r"(a), "r"(parity) : "memory");
}
#if HAS_TCGEN05
__device__ __forceinline__ void tcg_alloc(uint32_t dst_smem, uint32_t ncols){
  asm volatile("tcgen05.alloc.cta_group::1.sync.aligned.shared::cta.b32 [%0], %1;" :: "r"(dst_smem), "r"(ncols) : "memory");
}
__device__ __forceinline__ void tcg_dealloc(uint32_t tmem, uint32_t ncols){
  asm volatile("tcgen05.dealloc.cta_group::1.sync.aligned.b32 %0, %1;" :: "r"(tmem), "r"(ncols));
}
__device__ __forceinline__ void tcg_relinquish(){
  asm volatile("tcgen05.relinquish_alloc_permit.cta_group::1.sync.aligned;");
}
__device__ __forceinline__ void tcg_commit(uint32_t mbar){
  asm volatile("tcgen05.commit.cta_group::1.mbarrier::arrive::one.shared::cluster.b64 [%0];" :: "r"(mbar) : "memory");
}
__device__ __forceinline__ void tcg_fence_after(){
  asm volatile("tcgen05.fence::after_thread_sync;" ::: "memory");
}
__device__ __forceinline__ void fence_proxy_async_cta(){
  asm volatile("fence.proxy.async.shared::cta;" ::: "memory");
}
__device__ __forceinline__ void mma_f16_ss(uint32_t d, uint64_t a, uint64_t b, uint32_t idesc, uint32_t en){
  asm volatile("{\n.reg .pred p;\nsetp.ne.u32 p, %4, 0;\n"
    "tcgen05.mma.cta_group::1.kind::f16 [%0], %1, %2, %3, {%5,%5,%5,%5}, p;\n}"
    :: "r"(d), "l"(a), "l"(b), "r"(idesc), "r"(en), "r"(0u) : "memory");
}
__device__ __forceinline__ void ldtm32(uint32_t* r, uint32_t addr){
  asm volatile("tcgen05.ld.sync.aligned.32x32b.x32.b32 "
    "{%0,%1,%2,%3,%4,%5,%6,%7,%8,%9,%10,%11,%12,%13,%14,%15,"
    "%16,%17,%18,%19,%20,%21,%22,%23,%24,%25,%26,%27,%28,%29,%30,%31}, [%32];"
    : "=r"(r[0]),"=r"(r[1]),"=r"(r[2]),"=r"(r[3]),"=r"(r[4]),"=r"(r[5]),"=r"(r[6]),"=r"(r[7]),
      "=r"(r[8]),"=r"(r[9]),"=r"(r[10]),"=r"(r[11]),"=r"(r[12]),"=r"(r[13]),"=r"(r[14]),"=r"(r[15]),
      "=r"(r[16]),"=r"(r[17]),"=r"(r[18]),"=r"(r[19]),"=r"(r[20]),"=r"(r[21]),"=r"(r[22]),"=r"(r[23]),
      "=r"(r[24]),"=r"(r[25]),"=r"(r[26]),"=r"(r[27]),"=r"(r[28]),"=r"(r[29]),"=r"(r[30]),"=r"(r[31])
    : "r"(addr));
}
__device__ __forceinline__ void tcg_wait_ld(){
  asm volatile("tcgen05.wait::ld.sync.aligned;" ::: "memory");
}
// SW64 K-major smem descriptor: layout=4, SBO=32 (8 rows x 64B atom), LBO=1
__device__ __forceinline__ uint64_t make_desc_sw64(uint32_t base_addr){
  const uint64_t BASE = (uint64_t(4) << 61) | (uint64_t(1) << 46) | (uint64_t(32) << 32) | (uint64_t(1) << 16);
  return BASE | ((uint64_t)(base_addr >> 4) & 0x3FFF);
}
#endif

// ---------------- router: fp64 logits + softmax + top-2 ----------------
__global__ void router_kernel(const float* __restrict__ x, const float* __restrict__ wr){
  int widx = (blockIdx.x * blockDim.x + threadIdx.x) >> 5;
  int lane = threadIdx.x & 31;
  if (widx >= T_TOK) return;
  const float* xr = x + (size_t)widx * HS;
  double acc[NEXP];
  #pragma unroll
  for (int e=0;e<NEXP;e++) acc[e]=0.0;
  for (int h = lane; h < HS; h += 32){
    double xv = (double)xr[h];
    const float* wrow = wr + h*NEXP;
    #pragma unroll
    for (int e=0;e<NEXP;e++) acc[e] += xv * (double)wrow[e];
  }
  #pragma unroll
  for (int off=16; off; off>>=1){
    #pragma unroll
    for (int e=0;e<NEXP;e++) acc[e] += __shfl_xor_sync(0xffffffffu, acc[e], off);
  }
  if (lane == 0){
    double m = acc[0];
    #pragma unroll
    for (int e=1;e<NEXP;e++) m = fmax(m, acc[e]);
    double ex[NEXP], s = 0.0;
    #pragma unroll
    for (int e=0;e<NEXP;e++){ ex[e] = exp(acc[e]-m); s += ex[e]; }
    int e0 = 0; double b0 = acc[0];
    #pragma unroll
    for (int e=1;e<NEXP;e++) if (acc[e] > b0){ b0 = acc[e]; e0 = e; }
    int e1 = (e0==0) ? 1 : 0; double b1 = acc[e1];
    #pragma unroll
    for (int e=0;e<NEXP;e++) if (e != e0 && acc[e] > b1){ b1 = acc[e]; e1 = e; }
    g_top_e[2*widx]   = e0;
    g_top_e[2*widx+1] = e1;
    g_top_w[2*widx]   = (float)(ex[e0]/s);
    g_top_w[2*widx+1] = (float)(ex[e1]/s);
  }
}

// ---------------- stable counting sort + capacity (hierarchical scan) ----------------
__global__ void __launch_bounds__(1024,1) scan_kernel(){
  __shared__ int wbase[32][NEXP];
  __shared__ int etot[NEXP];
  __shared__ int starts[NEXP];
  int t = threadIdx.x, lane = t & 31, w = t >> 5;
  const int i0 = t * 32;
  int e_loc[32];
  int cnt[NEXP];
  #pragma unroll
  for (int e=0;e<NEXP;e++) cnt[e]=0;
  #pragma unroll
  for (int j=0;j<32;j++){ e_loc[j] = g_top_e[i0+j]; cnt[e_loc[j]]++; }
  int excl[NEXP];
  #pragma unroll
  for (int e=0;e<NEXP;e++){
    int v = cnt[e], s = v;
    #pragma unroll
    for (int off=1; off<32; off<<=1){
      int n = __shfl_up_sync(0xffffffffu, s, off);
      if (lane >= off) s += n;
    }
    excl[e] = s - v;
    if (lane == 31) wbase[w][e] = s;
  }
  __syncthreads();
  if (w == 0){
    #pragma unroll
    for (int e=0;e<NEXP;e++){
      int v = wbase[lane][e], s = v;
      #pragma unroll
      for (int off=1; off<32; off<<=1){
        int n = __shfl_up_sync(0xffffffffu, s, off);
        if (lane >= off) s += n;
      }
      wbase[lane][e] = s - v;
      if (lane == 31) etot[e] = s;
    }
  }
  __syncthreads();
  if (t == 0){
    int run = 0;
    #pragma unroll
    for (int e=0;e<NEXP;e++){ starts[e] = run; run += etot[e]; }
  }
  __syncthreads();
  int base[NEXP];
  #pragma unroll
  for (int e=0;e<NEXP;e++) base[e] = starts[e] + wbase[w][e] + excl[e];
  #pragma unroll
  for (int j=0;j<32;j++){
    int e = e_loc[j];
    int pos = base[e]++;
    int r = pos - starts[e];
    g_dst_slot[i0+j] = (r < CAP) ? (e*CAP + r) : -1;
  }
}

// ---------------- gather token rows -> slot buffer, split fp32 -> bf16 hi/lo ----------------
__global__ void gather_split_kernel(const float* __restrict__ x){
  int i = blockIdx.x;
  int dst = g_dst_slot[i];
  if (dst < 0) return;
  const float4* src = (const float4*)(x + (size_t)(i>>1)*HS);
  __nv_bfloat16* hi = g_xb_hi + (size_t)dst*HS;
  __nv_bfloat16* lo = g_xb_lo + (size_t)dst*HS;
  for (int j = threadIdx.x; j < HS/4; j += blockDim.x){
    float4 v = src[j];
    __nv_bfloat16 hx=__float2bfloat16(v.x), hy=__float2bfloat16(v.y);
    __nv_bfloat16 hz=__float2bfloat16(v.z), hw=__float2bfloat16(v.w);
    __nv_bfloat16 lx=__float2bfloat16(v.x-__bfloat162float(hx));
    __nv_bfloat16 ly=__float2bfloat16(v.y-__bfloat162float(hy));
    __nv_bfloat16 lz=__float2bfloat16(v.z-__bfloat162float(hz));
    __nv_bfloat16 lw=__float2bfloat16(v.w-__bfloat162float(hw));
    *(__nv_bfloat162*)&hi[j*4]   = __halves2bfloat162(hx,hy);
    *(__nv_bfloat162*)&hi[j*4+2] = __halves2bfloat162(hz,hw);
    *(__nv_bfloat162*)&lo[j*4]   = __halves2bfloat162(lx,ly);
    *(__nv_bfloat162*)&lo[j*4+2] = __halves2bfloat162(lz,lw);
  }
}

// ---------------- tcgen05-path weight transpose [E][K][N] -> [E][N][K] + split ----------
// which = 0 -> w1 (K=HS, N=FFN); which = 1 -> w2 (K=FFN, N=HS). grid.z = 2*NEXP.
__global__ void transpose_split_kernel(const float* __restrict__ w1,
                                       const float* __restrict__ w2){
#if HAS_TCGEN05
  __shared__ float tile[32][33];
  int which = blockIdx.z >= NEXP;
  int e = blockIdx.z - (which ? NEXP : 0);
  const int K = which ? FFN : HS;
  const int N = which ? HS  : FFN;
  const float* w = which ? w2 : w1;
  __nv_bfloat16* hi = which ? g_w2t_hi : g_w1t_hi;
  __nv_bfloat16* lo = which ? g_w2t_lo : g_w1t_lo;
  int n0 = blockIdx.x*32, k0 = blockIdx.y*32;
  if (n0 >= N || k0 >= K) return;
  int tx = threadIdx.x, ty = threadIdx.y;   // 32 x 8
  const float* in = w + (size_t)e*K*N;
  #pragma unroll
  for (int r=0;r<4;r++)
    tile[ty+8*r][tx] = in[(size_t)(k0+ty+8*r)*N + n0+tx];
  __syncthreads();
  #pragma unroll
  for (int r=0;r<4;r++){
    float v = tile[tx][ty+8*r];
    __nv_bfloat16 h = __float2bfloat16(v);
    __nv_bfloat16 l = __float2bfloat16(v - __bfloat162float(h));
    size_t o = ((size_t)e*N + n0+ty+8*r)*K + k0+tx;
    hi[o] = h; lo[o] = l;
  }
#endif
}

// ---------------- HMMA-path weight split fp32 -> bf16 hi/lo ([E][K][N]) --------
__global__ void split_w_kernel(const float* __restrict__ w, int which){
#if !HAS_TCGEN05
  __nv_bfloat16* hi = which ? g_w2_hi : g_w1_hi;
  __nv_bfloat16* lo = which ? g_w2_lo : g_w1_lo;
  size_t i = (size_t)blockIdx.x*blockDim.x + threadIdx.x;
  const size_t n4 = (size_t)NEXP*HS*FFN/4;
  if (i >= n4) return;
  float4 v = ((const float4*)w)[i];
  __nv_bfloat16 hx=__float2bfloat16(v.x), hy=__float2bfloat16(v.y);
  __nv_bfloat16 hz=__float2bfloat16(v.z), hw=__float2bfloat16(v.w);
  __nv_bfloat16 lx=__float2bfloat16(v.x-__bfloat162float(hx));
  __nv_bfloat16 ly=__float2bfloat16(v.y-__bfloat162float(hy));
  __nv_bfloat16 lz=__float2bfloat16(v.z-__bfloat162float(hz));
  __nv_bfloat16 lw=__float2bfloat16(v.w-__bfloat162float(hw));
  *(__nv_bfloat162*)&hi[i*4]   = __halves2bfloat162(hx,hy);
  *(__nv_bfloat162*)&hi[i*4+2] = __halves2bfloat162(hz,hw);
  *(__nv_bfloat162*)&lo[i*4]   = __halves2bfloat162(lx,ly);
  *(__nv_bfloat162*)&lo[i*4+2] = __halves2bfloat162(lz,lw);
#endif
}

// =====================================================================
// PATH A: tcgen05 grouped GEMM, tile 256x256, K-chunk 32, 3-stage ring
// smem/stage (SW64, 64B rows): Ah 16KB | Al 16KB | Bh 16KB | Bl 16KB = 64KB
// TMEM: D0 (M rows 0-127) cols 0-255, D1 (rows 128-255) cols 256-511
// =====================================================================
#define GSMEM (3*65536 + 1024)

template<int PHASE>
__global__ void __launch_bounds__(256,1) gemm_tc_kernel(){
#if HAS_TCGEN05
  constexpr int Kdim = (PHASE==1) ? HS  : FFN;
  constexpr int Ndim = (PHASE==1) ? FFN : HS;
  constexpr int NKB  = Kdim/32;                  // K-chunks of 32
  const __nv_bfloat16* __restrict__ Ah_g = (PHASE==1) ? g_xb_hi  : g_h_hi;
  const __nv_bfloat16* __restrict__ Al_g = (PHASE==1) ? g_xb_lo  : g_h_lo;
  const __nv_bfloat16* __restrict__ Bh_g = (PHASE==1) ? g_w1t_hi : g_w2t_hi;
  const __nv_bfloat16* __restrict__ Bl_g = (PHASE==1) ? g_w1t_lo : g_w2t_lo;

  extern __shared__ char dyn[];
  __shared__ uint64_t s_mbar[3];
  __shared__ uint32_t s_tptr;
  uint32_t sbase = (smem_addr32(dyn) + 1023u) & ~1023u;
  uint32_t mb[3] = { smem_addr32(&s_mbar[0]), smem_addr32(&s_mbar[1]), smem_addr32(&s_mbar[2]) };

  const int tid = threadIdx.x;
  const int wid = tid >> 5, lane = tid & 31;
  const int e  = blockIdx.z;
  const int m0 = blockIdx.y * 256;
  const int n0 = blockIdx.x * 256;
  const size_t Abase = ((size_t)e*CAP  + m0) * Kdim;
  const size_t Bbase = ((size_t)e*Ndim + n0) * Kdim;

  if (wid == 0) tcg_alloc(smem_addr32(&s_tptr), 512);
  if (tid == 0){ mbar_init(mb[0],1); mbar_init(mb[1],1); mbar_init(mb[2],1); }
  __syncthreads();
  const uint32_t tmem = s_tptr;

  // stage: 256 rows x 64B per operand array; each thread 4 x 16B chunks per array
  auto load_stage = [&](int buf, int kb){
    uint32_t st = sbase + buf*65536;
    const int k0 = kb*32;
    #pragma unroll
    for (int i=0;i<4;i++){
      int id = tid*4 + i;                 // 0..1023
      int r = id >> 2, c = id & 3;        // row 0..255, 16B chunk 0..3
      uint32_t sw = sw64((uint32_t)(r*64 + c*16));
      const size_t ga = Abase + (size_t)r*Kdim + k0 + c*8;
      const size_t gb = Bbase + (size_t)r*Kdim + k0 + c*8;
      cp16s(st +         sw, Ah_g + ga);
      cp16s(st + 16384 + sw, Al_g + ga);
      cp16s(st + 32768 + sw, Bh_g + gb);
      cp16s(st + 49152 + sw, Bl_g + gb);
    }
    cp_commit();
  };

  load_stage(0,0); load_stage(1,1); load_stage(2,2);

  const uint32_t idesc = (1u<<4) | (1u<<7) | (1u<<10) | ((256u>>3)<<17) | ((128u>>4)<<24);
  int ph[3] = {0,0,0};

  for (int kb = 0; kb < NKB; kb++){
    const int buf = kb % 3;
    if (kb == 0)            cp_wait<2>();
    else if (kb < NKB-1)    cp_wait<1>();
    else                    cp_wait<0>();
    __syncthreads();
    if (wid == 0 && elect_one()){
      fence_proxy_async_cta();
      uint32_t st = sbase + buf*65536;
      #pragma unroll
      for (int half=0; half<2; half++){
        uint64_t dAh = make_desc_sw64(st +         half*8192);
        uint64_t dAl = make_desc_sw64(st + 16384 + half*8192);
        uint64_t dBh = make_desc_sw64(st + 32768);
        uint64_t dBl = make_desc_sw64(st + 49152);
        uint32_t d   = tmem + half*256;
        #pragma unroll
        for (int ks=0; ks<2; ks++){
          uint32_t first = (kb==0 && ks==0) ? 0u : 1u;
          mma_f16_ss(d, dAh + ks*2, dBh + ks*2, idesc, first);
          mma_f16_ss(d, dAh + ks*2, dBl + ks*2, idesc, 1u);
          mma_f16_ss(d, dAl + ks*2, dBh + ks*2, idesc, 1u);
        }
      }
      tcg_commit(mb[buf]);
    }
    // refill: stage kb+2 overwrites buf (kb+2)%3 = (kb-1)%3 -> needs MMA(kb-1) done
    if (kb >= 1 && kb+2 < NKB){
      const int pb = (kb-1) % 3;
      mbar_wait(mb[pb], ph[pb]); ph[pb] ^= 1;
      load_stage(pb, kb+2);
    }
  }
  { // final: wait last chunk's commit (in-order completion covers all)
    const int lb = (NKB-1) % 3;
    mbar_wait(mb[lb], ph[lb]);
  }
  tcg_fence_after();

  // epilogue: warps 0-3 -> D0 (rows m0+0..127), warps 4-7 -> D1 (rows m0+128..255)
  {
    const int half = wid >> 2;
    const int row  = m0 + half*128 + (wid&3)*32 + lane;
    const size_t slot = (size_t)e*CAP + row;
    const uint32_t tbase = tmem + half*256;
    #pragma unroll
    for (int ch=0; ch<8; ch++){
      uint32_t r[32];
      ldtm32(r, tbase + ch*32);
      tcg_wait_ld();
      const int nc = n0 + ch*32;
      if constexpr (PHASE==1){
        size_t o = slot*FFN + nc;
        #pragma unroll
        for (int j=0;j<32;j+=2){
          float v0 = gelu_tanh(__uint_as_float(r[j]));
          float v1 = gelu_tanh(__uint_as_float(r[j+1]));
          __nv_bfloat16 h0=__float2bfloat16(v0), h1=__float2bfloat16(v1);
          __nv_bfloat16 l0=__float2bfloat16(v0-__bfloat162float(h0));
          __nv_bfloat16 l1=__float2bfloat16(v1-__bfloat162float(h1));
          *(__nv_bfloat162*)&g_h_hi[o+j] = __halves2bfloat162(h0,h1);
          *(__nv_bfloat162*)&g_h_lo[o+j] = __halves2bfloat162(l0,l1);
        }
      } else {
        size_t o = slot*HS + nc;
        #pragma unroll
        for (int j=0;j<32;j+=4){
          float4 v = make_float4(__uint_as_float(r[j]), __uint_as_float(r[j+1]),
                                 __uint_as_float(r[j+2]), __uint_as_float(r[j+3]));
          *(float4*)&g_y[o+j] = v;
        }
      }
    }
  }
  __syncthreads();
  if (wid == 0){
    tcg_relinquish();
    tcg_dealloc(tmem, 512);
  }
#endif
}

// =====================================================================
// PATH B: HMMA mma.sync grouped GEMM (round-1 proven fallback)
// =====================================================================
#define HSMEM 75776
template<int PHASE>
__global__ void __launch_bounds__(512,1) gemm_split_kernel(){
#if !HAS_TCGEN05
  constexpr int K  = (PHASE==1) ? HS  : FFN;
  constexpr int N  = (PHASE==1) ? FFN : HS;
  constexpr int KB = K/32;
  const __nv_bfloat16* __restrict__ Ah_g = (PHASE==1) ? g_xb_hi : g_h_hi;
  const __nv_bfloat16* __restrict__ Al_g = (PHASE==1) ? g_xb_lo : g_h_lo;
  const __nv_bfloat16* __restrict__ Bh_g = (PHASE==1) ? g_w1_hi : g_w2_hi;
  const __nv_bfloat16* __restrict__ Bl_g = (PHASE==1) ? g_w1_lo : g_w2_lo;

  extern __shared__ __align__(16) __nv_bfloat16 sm[];

  const int e  = blockIdx.z;
  const int m0 = blockIdx.y * 128;
  const int n0 = blockIdx.x * 128;
  const size_t Abase = (size_t)e*CAP*K;
  const size_t Bbase = (size_t)e*K*N;
  const size_t Cbase = (size_t)e*CAP*N;

  const int tid = threadIdx.x;
  const int warp = tid >> 5, lane = tid & 31;
  const int wm = warp >> 2, wn = warp & 3;

  const int ar = tid >> 2,  ac = (tid & 3)  * 8;
  const int br = tid >> 4,  bc = (tid & 15) * 8;

  float acc[2][4][4];
  #pragma unroll
  for (int i=0;i<2;i++)
    #pragma unroll
    for (int j=0;j<4;j++)
      #pragma unroll
      for (int k=0;k<4;k++) acc[i][j][k]=0.f;

  {
    __nv_bfloat16* s = sm;
    cp16s(smem_addr32(s +         ar*40 + ac), Ah_g + Abase + (size_t)(m0+ar)*K + ac);
    cp16s(smem_addr32(s + 5120  + ar*40 + ac), Al_g + Abase + (size_t)(m0+ar)*K + ac);
    cp16s(smem_addr32(s + 10240 + br*136 + bc), Bh_g + Bbase + (size_t)br*N + n0 + bc);
    cp16s(smem_addr32(s + 14592 + br*136 + bc), Bl_g + Bbase + (size_t)br*N + n0 + bc);
    cp_commit();
  }
  for (int kb=0; kb<KB; kb++){
    if (kb+1 < KB){
      const int k0 = (kb+1)*32;
      __nv_bfloat16* s = sm + ((kb+1)&1)*18944;
      cp16s(smem_addr32(s +         ar*40 + ac), Ah_g + Abase + (size_t)(m0+ar)*K + k0 + ac);
      cp16s(smem_addr32(s + 5120  + ar*40 + ac), Al_g + Abase + (size_t)(m0+ar)*K + k0 + ac);
      cp16s(smem_addr32(s + 10240 + br*136 + bc), Bh_g + Bbase + (size_t)(k0+br)*N + n0 + bc);
      cp16s(smem_addr32(s + 14592 + br*136 + bc), Bl_g + Bbase + (size_t)(k0+br)*N + n0 + bc);
      cp_commit();
      cp_wait<1>();
    } else {
      cp_wait<0>();
    }
    __syncthreads();
    const __nv_bfloat16* s = sm + (kb&1)*18944;
    #pragma unroll
    for (int ks=0; ks<2; ks++){
      uint32_t ah[2][4], al[2][4];
      #pragma unroll
      for (int mt=0; mt<2; mt++){
        const __nv_bfloat16* p = s + (wm*32 + mt*16 + (lane&15))*40 + ks*16 + (lane>>4)*8;
        ldsm4(ah[mt], p);
        ldsm4(al[mt], p + 5120);
      }
      uint32_t bh[2][4], bl[2][4];
      #pragma unroll
      for (int nh=0; nh<2; nh++){
        const __nv_bfloat16* p = s + 10240 + (ks*16 + (lane&15))*136 + wn*32 + nh*16 + (lane>>4)*8;
        ldsm4t(bh[nh], p);
        ldsm4t(bl[nh], p + 4352);
      }
      #pragma unroll
      for (int mt=0; mt<2; mt++){
        #pragma unroll
        for (int nt=0; nt<4; nt++){
          const int nh = nt>>1, sb = (nt&1)*2;
          mma_bf16(acc[mt][nt], ah[mt], bh[nh][sb], bh[nh][sb+1]);
          mma_bf16(acc[mt][nt], ah[mt], bl[nh][sb], bl[nh][sb+1]);
          mma_bf16(acc[mt][nt], al[mt], bh[nh][sb], bh[nh][sb+1]);
        }
      }
    }
    __syncthreads();
  }
  const int g = lane>>2, tg = lane&3;
  #pragma unroll
  for (int mt=0; mt<2; mt++){
    #pragma unroll
    for (int nt=0; nt<4; nt++){
      const int row = m0 + wm*32 + mt*16 + g;
      const int col = n0 + wn*32 + nt*8 + tg*2;
      float v0=acc[mt][nt][0], v1=acc[mt][nt][1], v2=acc[mt][nt][2], v3=acc[mt][nt][3];
      if constexpr (PHASE==1){
        v0=gelu_tanh(v0); v1=gelu_tanh(v1); v2=gelu_tanh(v2); v3=gelu_tanh(v3);
        __nv_bfloat16 h0=__float2bfloat16(v0), h1=__float2bfloat16(v1);
        __nv_bfloat16 l0=__float2bfloat16(v0-__bfloat162float(h0));
        __nv_bfloat16 l1=__float2bfloat16(v1-__bfloat162float(h1));
        size_t o = Cbase + (size_t)row*N + col;
        *(__nv_bfloat162*)&g_h_hi[o] = __halves2bfloat162(h0,h1);
        *(__nv_bfloat162*)&g_h_lo[o] = __halves2bfloat162(l0,l1);
        __nv_bfloat16 h2=__float2bfloat16(v2), h3=__float2bfloat16(v3);
        __nv_bfloat16 l2=__float2bfloat16(v2-__bfloat162float(h2));
        __nv_bfloat16 l3=__float2bfloat16(v3-__bfloat162float(h3));
        size_t o2 = Cbase + (size_t)(row+8)*N + col;
        *(__nv_bfloat162*)&g_h_hi[o2] = __halves2bfloat162(h2,h3);
        *(__nv_bfloat162*)&g_h_lo[o2] = __halves2bfloat162(l2,l3);
      } else {
        *(float2*)&g_y[Cbase + (size_t)row*N + col]     = make_float2(v0,v1);
        *(float2*)&g_y[Cbase + (size_t)(row+8)*N + col] = make_float2(v2,v3);
      }
    }
  }
#endif
}

// ---------------- per-token weighted combine + bias ----------------
__global__ void scatter_kernel(const float* __restrict__ bias, float* __restrict__ out){
  int t = blockIdx.x;
  int s0 = g_dst_slot[2*t], s1 = g_dst_slot[2*t+1];
  float w0 = g_top_w[2*t], w1 = g_top_w[2*t+1];
  const float4* y0 = (const float4*)(g_y + (size_t)(s0 < 0 ? 0 : s0)*HS);
  const float4* y1 = (const float4*)(g_y + (size_t)(s1 < 0 ? 0 : s1)*HS);
  const float4* b4 = (const float4*)bias;
  float4* o = (float4*)(out + (size_t)t*HS);
  for (int j = threadIdx.x; j < HS/4; j += blockDim.x){
    float4 r = b4[j];
    if (s0 >= 0){ float4 v = y0[j]; r.x += w0*v.x; r.y += w0*v.y; r.z += w0*v.z; r.w += w0*v.w; }
    if (s1 >= 0){ float4 v = y1[j]; r.x += w1*v.x; r.y += w1*v.y; r.z += w1*v.z; r.w += w1*v.w; }
    o[j] = r;
  }
}

// ---------------- launcher ----------------
extern "C" void kernel_launch(void* const* d_in, const int* in_sizes, int n_in,
                              void* d_out, int out_size){
  const float* x    = (const float*)d_in[0];
  const float* wr   = (const float*)d_in[1];
  const float* w1   = (const float*)d_in[2];
  const float* w2   = (const float*)d_in[3];
  const float* bias = (const float*)d_in[4];
  float* out = (float*)d_out;

  cudaFuncSetAttribute(gemm_tc_kernel<1>, cudaFuncAttributeMaxDynamicSharedMemorySize, GSMEM);
  cudaFuncSetAttribute(gemm_tc_kernel<2>, cudaFuncAttributeMaxDynamicSharedMemorySize, GSMEM);
  cudaFuncSetAttribute(gemm_split_kernel<1>, cudaFuncAttributeMaxDynamicSharedMemorySize, HSMEM);
  cudaFuncSetAttribute(gemm_split_kernel<2>, cudaFuncAttributeMaxDynamicSharedMemorySize, HSMEM);

  // 1: fused transpose+split for both weights (tcgen05 path; empty otherwise)
  //    grid covers the larger (FFN x HS) shape; small shape bounds-checked.
  transpose_split_kernel<<<dim3(FFN/32, FFN/32, 2*NEXP), dim3(32,8)>>>(w1, w2);
  // 2-4: routing pipeline
  router_kernel<<<T_TOK/8, 256>>>(x, wr);
  scan_kernel<<<1, 1024>>>();
  gather_split_kernel<<<NASSIGN, 128>>>(x);
  // 5: phase-1 tcgen05 GEMM (target for ncu capture window)
  gemm_tc_kernel<1><<<dim3(FFN/256, CAP/256, NEXP), 256, GSMEM>>>();
  // HMMA fallback path (empty bodies on sm_103a binary)
  const int n4 = NEXP*HS*FFN/4;
  split_w_kernel<<<(n4+255)/256, 256>>>(w1, 0);
  split_w_kernel<<<(n4+255)/256, 256>>>(w2, 1);
  gemm_split_kernel<1><<<dim3(FFN/128, CAP/128, NEXP), 512, HSMEM>>>();
  // phase 2
  gemm_tc_kernel<2><<<dim3(HS/256, CAP/256, NEXP), 256, GSMEM>>>();
  gemm_split_kernel<2><<<dim3(HS/128, CAP/128, NEXP), 512, HSMEM>>>();

  scatter_kernel<<<T_TOK, 128>>>(bias, out);
}

// round 9
// speedup vs baseline: 1.6564x; 1.1278x over previous
#include <cuda_runtime.h>
#include <cuda_bf16.h>
#include <math.h>
#include <stdint.h>

#define T_TOK   16384
#define HS      1024
#define FFN     4096
#define NEXP    8
#define CAP     4096
#define NASSIGN (2*T_TOK)
#define SLOTS   (NEXP*CAP)

#if defined(__CUDA_ARCH_FEAT_SM103_ALL) || defined(__CUDA_ARCH_FEAT_SM100_ALL) || defined(__CUDA_ARCH_FEAT_SM101_ALL)
#define HAS_TCGEN05 1
#else
#define HAS_TCGEN05 0
#endif

// ---------------- static device scratch ----------------
__device__ __nv_bfloat16 g_xb_hi[(size_t)SLOTS*HS];
__device__ __nv_bfloat16 g_xb_lo[(size_t)SLOTS*HS];
__device__ __nv_bfloat16 g_h_hi[(size_t)SLOTS*FFN];
__device__ __nv_bfloat16 g_h_lo[(size_t)SLOTS*FFN];
__device__ float         g_y[(size_t)SLOTS*HS];
// tcgen05 path: weights transposed to [E][N][K] K-major, split hi/lo
__device__ __nv_bfloat16 g_w1t_hi[(size_t)NEXP*FFN*HS];
__device__ __nv_bfloat16 g_w1t_lo[(size_t)NEXP*FFN*HS];
__device__ __nv_bfloat16 g_w2t_hi[(size_t)NEXP*HS*FFN];
__device__ __nv_bfloat16 g_w2t_lo[(size_t)NEXP*HS*FFN];
// HMMA fallback path: weights in original [E][K][N], split hi/lo
__device__ __nv_bfloat16 g_w1_hi[(size_t)NEXP*HS*FFN];
__device__ __nv_bfloat16 g_w1_lo[(size_t)NEXP*HS*FFN];
__device__ __nv_bfloat16 g_w2_hi[(size_t)NEXP*FFN*HS];
__device__ __nv_bfloat16 g_w2_lo[(size_t)NEXP*FFN*HS];
__device__ int           g_top_e[NASSIGN];
__device__ float         g_top_w[NASSIGN];
__device__ int           g_dst_slot[NASSIGN];

// ---------------- arch-neutral helpers ----------------
__device__ __forceinline__ uint32_t smem_addr32(const void* p){
  return (uint32_t)__cvta_generic_to_shared(p);
}
__device__ __forceinline__ void cp16s(uint32_t dst, const void* src){
  asm volatile("cp.async.cg.shared.global [%0], [%1], 16;\n" :: "r"(dst), "l"(src));
}
__device__ __forceinline__ void cp_commit(){ asm volatile("cp.async.commit_group;\n"); }
template<int NW> __device__ __forceinline__ void cp_wait(){
  asm volatile("cp.async.wait_group %0;\n" :: "n"(NW));
}
__device__ __forceinline__ void ldsm4(uint32_t* r, const __nv_bfloat16* p){
  uint32_t a = smem_addr32(p);
  asm volatile("ldmatrix.sync.aligned.m8n8.x4.shared.b16 {%0,%1,%2,%3}, [%4];\n"
    : "=r"(r[0]),"=r"(r[1]),"=r"(r[2]),"=r"(r[3]) : "r"(a));
}
__device__ __forceinline__ void ldsm4t(uint32_t* r, const __nv_bfloat16* p){
  uint32_t a = smem_addr32(p);
  asm volatile("ldmatrix.sync.aligned.m8n8.x4.trans.shared.b16 {%0,%1,%2,%3}, [%4];\n"
    : "=r"(r[0]),"=r"(r[1]),"=r"(r[2]),"=r"(r[3]) : "r"(a));
}
__device__ __forceinline__ void mma_bf16(float* c, const uint32_t* a, uint32_t b0, uint32_t b1){
  asm volatile("mma.sync.aligned.m16n8k16.row.col.f32.bf16.bf16.f32 "
    "{%0,%1,%2,%3}, {%4,%5,%6,%7}, {%8,%9}, {%0,%1,%2,%3};\n"
    : "+f"(c[0]),"+f"(c[1]),"+f"(c[2]),"+f"(c[3])
    : "r"(a[0]),"r"(a[1]),"r"(a[2]),"r"(a[3]), "r"(b0),"r"(b1));
}
__device__ __forceinline__ uint32_t sw64(uint32_t off){ return off ^ ((off >> 3) & 0x30); }

// fast gelu: 1 MUFU.TANH + ~5 FMA/ALU (vs tanhf's 2 MUFU + ~12 ALU)
__device__ __forceinline__ float gelu_fast(float x){
  float t = x*x;
  float u = x*(0.7978845608f + 0.0356774081f*t);
  float th;
  asm("tanh.approx.f32 %0, %1;" : "=f"(th) : "f"(u));
  return 0.5f*__fmaf_rn(x, th, x);
}
__device__ __forceinline__ uint32_t elect_one(){
  uint32_t pred;
  asm volatile("{\n.reg .pred p;\nelect.sync _|p, 0xFFFFFFFF;\nselp.b32 %0, 1, 0, p;\n}" : "=r"(pred));
  return pred;
}
__device__ __forceinline__ void mbar_init(uint32_t a, uint32_t cnt){
  asm volatile("mbarrier.init.shared.b64 [%0], %1;" :: "r"(a), "r"(cnt) : "memory");
}
__device__ __forceinline__ void mbar_wait(uint32_t a, uint32_t parity){
  asm volatile("{\n.reg .pred P;\nLW%=:\nmbarrier.try_wait.parity.acquire.cta.shared::cta.b64 P, [%0], %1, 0x989680;\n@!P bra LW%=;\n}"
    :: "r"(a), "r"(parity) : "memory");
}
#if HAS_TCGEN05
__device__ __forceinline__ void tcg_alloc(uint32_t dst_smem, uint32_t ncols){
  asm volatile("tcgen05.alloc.cta_group::1.sync.aligned.shared::cta.b32 [%0], %1;" :: "r"(dst_smem), "r"(ncols) : "memory");
}
__device__ __forceinline__ void tcg_dealloc(uint32_t tmem, uint32_t ncols){
  asm volatile("tcgen05.dealloc.cta_group::1.sync.aligned.b32 %0, %1;" :: "r"(tmem), "r"(ncols));
}
__device__ __forceinline__ void tcg_relinquish(){
  asm volatile("tcgen05.relinquish_alloc_permit.cta_group::1.sync.aligned;");
}
__device__ __forceinline__ void tcg_commit(uint32_t mbar){
  asm volatile("tcgen05.commit.cta_group::1.mbarrier::arrive::one.shared::cluster.b64 [%0];" :: "r"(mbar) : "memory");
}
__device__ __forceinline__ void tcg_fence_after(){
  asm volatile("tcgen05.fence::after_thread_sync;" ::: "memory");
}
__device__ __forceinline__ void fence_proxy_async_cta(){
  asm volatile("fence.proxy.async.shared::cta;" ::: "memory");
}
__device__ __forceinline__ void mma_f16_ss(uint32_t d, uint64_t a, uint64_t b, uint32_t idesc, uint32_t en){
  asm volatile("{\n.reg .pred p;\nsetp.ne.u32 p, %4, 0;\n"
    "tcgen05.mma.cta_group::1.kind::f16 [%0], %1, %2, %3, {%5,%5,%5,%5}, p;\n}"
    :: "r"(d), "l"(a), "l"(b), "r"(idesc), "r"(en), "r"(0u) : "memory");
}
__device__ __forceinline__ void ldtm32(uint32_t* r, uint32_t addr){
  asm volatile("tcgen05.ld.sync.aligned.32x32b.x32.b32 "
    "{%0,%1,%2,%3,%4,%5,%6,%7,%8,%9,%10,%11,%12,%13,%14,%15,"
    "%16,%17,%18,%19,%20,%21,%22,%23,%24,%25,%26,%27,%28,%29,%30,%31}, [%32];"
    : "=r"(r[0]),"=r"(r[1]),"=r"(r[2]),"=r"(r[3]),"=r"(r[4]),"=r"(r[5]),"=r"(r[6]),"=r"(r[7]),
      "=r"(r[8]),"=r"(r[9]),"=r"(r[10]),"=r"(r[11]),"=r"(r[12]),"=r"(r[13]),"=r"(r[14]),"=r"(r[15]),
      "=r"(r[16]),"=r"(r[17]),"=r"(r[18]),"=r"(r[19]),"=r"(r[20]),"=r"(r[21]),"=r"(r[22]),"=r"(r[23]),
      "=r"(r[24]),"=r"(r[25]),"=r"(r[26]),"=r"(r[27]),"=r"(r[28]),"=r"(r[29]),"=r"(r[30]),"=r"(r[31])
    : "r"(addr));
}
__device__ __forceinline__ void tcg_wait_ld(){
  asm volatile("tcgen05.wait::ld.sync.aligned;" ::: "memory");
}
// SW64 K-major smem descriptor: layout=4, SBO=32 (8 rows x 64B atom), LBO=1
__device__ __forceinline__ uint64_t make_desc_sw64(uint32_t base_addr){
  const uint64_t BASE = (uint64_t(4) << 61) | (uint64_t(1) << 46) | (uint64_t(32) << 32) | (uint64_t(1) << 16);
  return BASE | ((uint64_t)(base_addr >> 4) & 0x3FFF);
}
#endif

// ---------------- router: fp64 logits + softmax + top-2 ----------------
__global__ void router_kernel(const float* __restrict__ x, const float* __restrict__ wr){
  int widx = (blockIdx.x * blockDim.x + threadIdx.x) >> 5;
  int lane = threadIdx.x & 31;
  if (widx >= T_TOK) return;
  const float* xr = x + (size_t)widx * HS;
  double acc[NEXP];
  #pragma unroll
  for (int e=0;e<NEXP;e++) acc[e]=0.0;
  for (int h = lane; h < HS; h += 32){
    double xv = (double)xr[h];
    const float* wrow = wr + h*NEXP;
    #pragma unroll
    for (int e=0;e<NEXP;e++) acc[e] += xv * (double)wrow[e];
  }
  #pragma unroll
  for (int off=16; off; off>>=1){
    #pragma unroll
    for (int e=0;e<NEXP;e++) acc[e] += __shfl_xor_sync(0xffffffffu, acc[e], off);
  }
  if (lane == 0){
    double m = acc[0];
    #pragma unroll
    for (int e=1;e<NEXP;e++) m = fmax(m, acc[e]);
    double ex[NEXP], s = 0.0;
    #pragma unroll
    for (int e=0;e<NEXP;e++){ ex[e] = exp(acc[e]-m); s += ex[e]; }
    int e0 = 0; double b0 = acc[0];
    #pragma unroll
    for (int e=1;e<NEXP;e++) if (acc[e] > b0){ b0 = acc[e]; e0 = e; }
    int e1 = (e0==0) ? 1 : 0; double b1 = acc[e1];
    #pragma unroll
    for (int e=0;e<NEXP;e++) if (e != e0 && acc[e] > b1){ b1 = acc[e]; e1 = e; }
    g_top_e[2*widx]   = e0;
    g_top_e[2*widx+1] = e1;
    g_top_w[2*widx]   = (float)(ex[e0]/s);
    g_top_w[2*widx+1] = (float)(ex[e1]/s);
  }
}

// ---------------- stable counting sort + capacity (hierarchical scan) ----------------
__global__ void __launch_bounds__(1024,1) scan_kernel(){
  __shared__ int wbase[32][NEXP];
  __shared__ int etot[NEXP];
  __shared__ int starts[NEXP];
  int t = threadIdx.x, lane = t & 31, w = t >> 5;
  const int i0 = t * 32;
  int e_loc[32];
  int cnt[NEXP];
  #pragma unroll
  for (int e=0;e<NEXP;e++) cnt[e]=0;
  #pragma unroll
  for (int j=0;j<32;j++){ e_loc[j] = g_top_e[i0+j]; cnt[e_loc[j]]++; }
  int excl[NEXP];
  #pragma unroll
  for (int e=0;e<NEXP;e++){
    int v = cnt[e], s = v;
    #pragma unroll
    for (int off=1; off<32; off<<=1){
      int n = __shfl_up_sync(0xffffffffu, s, off);
      if (lane >= off) s += n;
    }
    excl[e] = s - v;
    if (lane == 31) wbase[w][e] = s;
  }
  __syncthreads();
  if (w == 0){
    #pragma unroll
    for (int e=0;e<NEXP;e++){
      int v = wbase[lane][e], s = v;
      #pragma unroll
      for (int off=1; off<32; off<<=1){
        int n = __shfl_up_sync(0xffffffffu, s, off);
        if (lane >= off) s += n;
      }
      wbase[lane][e] = s - v;
      if (lane == 31) etot[e] = s;
    }
  }
  __syncthreads();
  if (t == 0){
    int run = 0;
    #pragma unroll
    for (int e=0;e<NEXP;e++){ starts[e] = run; run += etot[e]; }
  }
  __syncthreads();
  int base[NEXP];
  #pragma unroll
  for (int e=0;e<NEXP;e++) base[e] = starts[e] + wbase[w][e] + excl[e];
  #pragma unroll
  for (int j=0;j<32;j++){
    int e = e_loc[j];
    int pos = base[e]++;
    int r = pos - starts[e];
    g_dst_slot[i0+j] = (r < CAP) ? (e*CAP + r) : -1;
  }
}

// ---------------- fused prep: weight transpose+split (tcgen05) AND token gather+split ----
// grid (128,128,17), block 256 flat.
//   z in [0,16): transpose slice, which = z>=8 (w2), e = z&7   [tcgen05 binaries only]
//   z == 16   : gather, 2 assignments per block (128 threads each)
__global__ void prep_kernel(const float* __restrict__ x,
                            const float* __restrict__ w1,
                            const float* __restrict__ w2){
  if (blockIdx.z < 16){
#if HAS_TCGEN05
    __shared__ float tile[32][33];
    int which = blockIdx.z >= 8;
    int e = blockIdx.z & 7;
    const int K = which ? FFN : HS;
    const int N = which ? HS  : FFN;
    const float* w = which ? w2 : w1;
    __nv_bfloat16* hi = which ? g_w2t_hi : g_w1t_hi;
    __nv_bfloat16* lo = which ? g_w2t_lo : g_w1t_lo;
    int n0 = blockIdx.x*32, k0 = blockIdx.y*32;
    if (n0 >= N || k0 >= K) return;
    int tx = threadIdx.x & 31, ty = threadIdx.x >> 5;   // 32 x 8
    const float* in = w + (size_t)e*K*N;
    #pragma unroll
    for (int r=0;r<4;r++)
      tile[ty+8*r][tx] = in[(size_t)(k0+ty+8*r)*N + n0+tx];
    __syncthreads();
    #pragma unroll
    for (int r=0;r<4;r++){
      float v = tile[tx][ty+8*r];
      __nv_bfloat16 h = __float2bfloat16(v);
      __nv_bfloat16 l = __float2bfloat16(v - __bfloat162float(h));
      size_t o = ((size_t)e*N + n0+ty+8*r)*K + k0+tx;
      hi[o] = h; lo[o] = l;
    }
#endif
    return;
  }
  // ---- gather: assignment i -> slot, split x row into bf16 hi/lo ----
  int base2 = (blockIdx.y*gridDim.x + blockIdx.x)*2;
  int i = base2 + (threadIdx.x >> 7);
  int t128 = threadIdx.x & 127;
  int dst = g_dst_slot[i];
  if (dst < 0) return;
  const float4* src = (const float4*)(x + (size_t)(i>>1)*HS);
  __nv_bfloat16* hi = g_xb_hi + (size_t)dst*HS;
  __nv_bfloat16* lo = g_xb_lo + (size_t)dst*HS;
  for (int j = t128; j < HS/4; j += 128){
    float4 v = src[j];
    __nv_bfloat16 hx=__float2bfloat16(v.x), hy=__float2bfloat16(v.y);
    __nv_bfloat16 hz=__float2bfloat16(v.z), hw=__float2bfloat16(v.w);
    __nv_bfloat16 lx=__float2bfloat16(v.x-__bfloat162float(hx));
    __nv_bfloat16 ly=__float2bfloat16(v.y-__bfloat162float(hy));
    __nv_bfloat16 lz=__float2bfloat16(v.z-__bfloat162float(hz));
    __nv_bfloat16 lw=__float2bfloat16(v.w-__bfloat162float(hw));
    *(__nv_bfloat162*)&hi[j*4]   = __halves2bfloat162(hx,hy);
    *(__nv_bfloat162*)&hi[j*4+2] = __halves2bfloat162(hz,hw);
    *(__nv_bfloat162*)&lo[j*4]   = __halves2bfloat162(lx,ly);
    *(__nv_bfloat162*)&lo[j*4+2] = __halves2bfloat162(lz,lw);
  }
}

// ---------------- HMMA-path weight split fp32 -> bf16 hi/lo ([E][K][N]) --------
__global__ void split_w_kernel(const float* __restrict__ w, int which){
#if !HAS_TCGEN05
  __nv_bfloat16* hi = which ? g_w2_hi : g_w1_hi;
  __nv_bfloat16* lo = which ? g_w2_lo : g_w1_lo;
  size_t i = (size_t)blockIdx.x*blockDim.x + threadIdx.x;
  const size_t n4 = (size_t)NEXP*HS*FFN/4;
  if (i >= n4) return;
  float4 v = ((const float4*)w)[i];
  __nv_bfloat16 hx=__float2bfloat16(v.x), hy=__float2bfloat16(v.y);
  __nv_bfloat16 hz=__float2bfloat16(v.z), hw=__float2bfloat16(v.w);
  __nv_bfloat16 lx=__float2bfloat16(v.x-__bfloat162float(hx));
  __nv_bfloat16 ly=__float2bfloat16(v.y-__bfloat162float(hy));
  __nv_bfloat16 lz=__float2bfloat16(v.z-__bfloat162float(hz));
  __nv_bfloat16 lw=__float2bfloat16(v.w-__bfloat162float(hw));
  *(__nv_bfloat162*)&hi[i*4]   = __halves2bfloat162(hx,hy);
  *(__nv_bfloat162*)&hi[i*4+2] = __halves2bfloat162(hz,hw);
  *(__nv_bfloat162*)&lo[i*4]   = __halves2bfloat162(lx,ly);
  *(__nv_bfloat162*)&lo[i*4+2] = __halves2bfloat162(lz,lw);
#endif
}

// =====================================================================
// PATH A: tcgen05 grouped GEMM, tile 256x256, K-chunk 32, 3-stage ring
// =====================================================================
#define GSMEM (3*65536 + 1024)

template<int PHASE>
__global__ void __launch_bounds__(256,1) gemm_tc_kernel(){
#if HAS_TCGEN05
  constexpr int Kdim = (PHASE==1) ? HS  : FFN;
  constexpr int Ndim = (PHASE==1) ? FFN : HS;
  constexpr int NKB  = Kdim/32;
  const __nv_bfloat16* __restrict__ Ah_g = (PHASE==1) ? g_xb_hi  : g_h_hi;
  const __nv_bfloat16* __restrict__ Al_g = (PHASE==1) ? g_xb_lo  : g_h_lo;
  const __nv_bfloat16* __restrict__ Bh_g = (PHASE==1) ? g_w1t_hi : g_w2t_hi;
  const __nv_bfloat16* __restrict__ Bl_g = (PHASE==1) ? g_w1t_lo : g_w2t_lo;

  extern __shared__ char dyn[];
  __shared__ uint64_t s_mbar[3];
  __shared__ uint32_t s_tptr;
  uint32_t sbase = (smem_addr32(dyn) + 1023u) & ~1023u;
  uint32_t mb[3] = { smem_addr32(&s_mbar[0]), smem_addr32(&s_mbar[1]), smem_addr32(&s_mbar[2]) };

  const int tid = threadIdx.x;
  const int wid = tid >> 5, lane = tid & 31;
  const int e  = blockIdx.z;
  const int m0 = blockIdx.y * 256;
  const int n0 = blockIdx.x * 256;
  const size_t Abase = ((size_t)e*CAP  + m0) * Kdim;
  const size_t Bbase = ((size_t)e*Ndim + n0) * Kdim;

  if (wid == 0) tcg_alloc(smem_addr32(&s_tptr), 512);
  if (tid == 0){ mbar_init(mb[0],1); mbar_init(mb[1],1); mbar_init(mb[2],1); }
  __syncthreads();
  const uint32_t tmem = s_tptr;

  auto load_stage = [&](int buf, int kb){
    uint32_t st = sbase + buf*65536;
    const int k0 = kb*32;
    #pragma unroll
    for (int i=0;i<4;i++){
      int id = tid*4 + i;
      int r = id >> 2, c = id & 3;
      uint32_t sw = sw64((uint32_t)(r*64 + c*16));
      const size_t ga = Abase + (size_t)r*Kdim + k0 + c*8;
      const size_t gb = Bbase + (size_t)r*Kdim + k0 + c*8;
      cp16s(st +         sw, Ah_g + ga);
      cp16s(st + 16384 + sw, Al_g + ga);
      cp16s(st + 32768 + sw, Bh_g + gb);
      cp16s(st + 49152 + sw, Bl_g + gb);
    }
    cp_commit();
  };

  load_stage(0,0); load_stage(1,1); load_stage(2,2);

  const uint32_t idesc = (1u<<4) | (1u<<7) | (1u<<10) | ((256u>>3)<<17) | ((128u>>4)<<24);
  int ph[3] = {0,0,0};

  for (int kb = 0; kb < NKB; kb++){
    const int buf = kb % 3;
    if (kb == 0)            cp_wait<2>();
    else if (kb < NKB-1)    cp_wait<1>();
    else                    cp_wait<0>();
    __syncthreads();
    if (wid == 0 && elect_one()){
      fence_proxy_async_cta();
      uint32_t st = sbase + buf*65536;
      #pragma unroll
      for (int half=0; half<2; half++){
        uint64_t dAh = make_desc_sw64(st +         half*8192);
        uint64_t dAl = make_desc_sw64(st + 16384 + half*8192);
        uint64_t dBh = make_desc_sw64(st + 32768);
        uint64_t dBl = make_desc_sw64(st + 49152);
        uint32_t d   = tmem + half*256;
        #pragma unroll
        for (int ks=0; ks<2; ks++){
          uint32_t first = (kb==0 && ks==0) ? 0u : 1u;
          mma_f16_ss(d, dAh + ks*2, dBh + ks*2, idesc, first);
          mma_f16_ss(d, dAh + ks*2, dBl + ks*2, idesc, 1u);
          mma_f16_ss(d, dAl + ks*2, dBh + ks*2, idesc, 1u);
        }
      }
      tcg_commit(mb[buf]);
    }
    if (kb >= 1 && kb+2 < NKB){
      const int pb = (kb-1) % 3;
      mbar_wait(mb[pb], ph[pb]); ph[pb] ^= 1;
      load_stage(pb, kb+2);
    }
  }
  {
    const int lb = (NKB-1) % 3;
    mbar_wait(mb[lb], ph[lb]);
  }
  tcg_fence_after();

  // epilogue: warps 0-3 -> rows m0+0..127 (tmem cols 0-255), warps 4-7 -> rows +128..255
  {
    const int half = wid >> 2;
    const int row  = m0 + half*128 + (wid&3)*32 + lane;
    const size_t slot = (size_t)e*CAP + row;
    const uint32_t tbase = tmem + half*256;
    #pragma unroll
    for (int ch=0; ch<8; ch++){
      uint32_t r[32];
      ldtm32(r, tbase + ch*32);
      tcg_wait_ld();
      const int nc = n0 + ch*32;
      if constexpr (PHASE==1){
        size_t o = slot*FFN + nc;
        uint32_t hip[16], lop[16];
        #pragma unroll
        for (int j=0;j<32;j+=2){
          float g0 = gelu_fast(__uint_as_float(r[j]));
          float g1 = gelu_fast(__uint_as_float(r[j+1]));
          uint32_t h0 = __float_as_uint(g0) & 0xffff0000u;   // truncation split
          uint32_t h1 = __float_as_uint(g1) & 0xffff0000u;
          float l0 = g0 - __uint_as_float(h0);
          float l1 = g1 - __uint_as_float(h1);
          hip[j>>1] = __byte_perm(h0, h1, 0x7632);           // pack two bf16 hi
          uint32_t lp;
          asm("cvt.rn.bf16x2.f32 %0, %1, %2;" : "=r"(lp) : "f"(l1), "f"(l0));
          lop[j>>1] = lp;
        }
        #pragma unroll
        for (int q=0;q<4;q++){
          *(uint4*)&g_h_hi[o + q*8] = make_uint4(hip[q*4],hip[q*4+1],hip[q*4+2],hip[q*4+3]);
          *(uint4*)&g_h_lo[o + q*8] = make_uint4(lop[q*4],lop[q*4+1],lop[q*4+2],lop[q*4+3]);
        }
      } else {
        size_t o = slot*HS + nc;
        #pragma unroll
        for (int j=0;j<32;j+=4){
          float4 v = make_float4(__uint_as_float(r[j]), __uint_as_float(r[j+1]),
                                 __uint_as_float(r[j+2]), __uint_as_float(r[j+3]));
          *(float4*)&g_y[o+j] = v;
        }
      }
    }
  }
  __syncthreads();
  if (wid == 0){
    tcg_relinquish();
    tcg_dealloc(tmem, 512);
  }
#endif
}

// =====================================================================
// PATH B: HMMA mma.sync grouped GEMM (fallback)
// =====================================================================
#define HSMEM 75776
template<int PHASE>
__global__ void __launch_bounds__(512,1) gemm_split_kernel(){
#if !HAS_TCGEN05
  constexpr int K  = (PHASE==1) ? HS  : FFN;
  constexpr int N  = (PHASE==1) ? FFN : HS;
  constexpr int KB = K/32;
  const __nv_bfloat16* __restrict__ Ah_g = (PHASE==1) ? g_xb_hi : g_h_hi;
  const __nv_bfloat16* __restrict__ Al_g = (PHASE==1) ? g_xb_lo : g_h_lo;
  const __nv_bfloat16* __restrict__ Bh_g = (PHASE==1) ? g_w1_hi : g_w2_hi;
  const __nv_bfloat16* __restrict__ Bl_g = (PHASE==1) ? g_w1_lo : g_w2_lo;

  extern __shared__ __align__(16) __nv_bfloat16 sm[];

  const int e  = blockIdx.z;
  const int m0 = blockIdx.y * 128;
  const int n0 = blockIdx.x * 128;
  const size_t Abase = (size_t)e*CAP*K;
  const size_t Bbase = (size_t)e*K*N;
  const size_t Cbase = (size_t)e*CAP*N;

  const int tid = threadIdx.x;
  const int warp = tid >> 5, lane = tid & 31;
  const int wm = warp >> 2, wn = warp & 3;

  const int ar = tid >> 2,  ac = (tid & 3)  * 8;
  const int br = tid >> 4,  bc = (tid & 15) * 8;

  float acc[2][4][4];
  #pragma unroll
  for (int i=0;i<2;i++)
    #pragma unroll
    for (int j=0;j<4;j++)
      #pragma unroll
      for (int k=0;k<4;k++) acc[i][j][k]=0.f;

  {
    __nv_bfloat16* s = sm;
    cp16s(smem_addr32(s +         ar*40 + ac), Ah_g + Abase + (size_t)(m0+ar)*K + ac);
    cp16s(smem_addr32(s + 5120  + ar*40 + ac), Al_g + Abase + (size_t)(m0+ar)*K + ac);
    cp16s(smem_addr32(s + 10240 + br*136 + bc), Bh_g + Bbase + (size_t)br*N + n0 + bc);
    cp16s(smem_addr32(s + 14592 + br*136 + bc), Bl_g + Bbase + (size_t)br*N + n0 + bc);
    cp_commit();
  }
  for (int kb=0; kb<KB; kb++){
    if (kb+1 < KB){
      const int k0 = (kb+1)*32;
      __nv_bfloat16* s = sm + ((kb+1)&1)*18944;
      cp16s(smem_addr32(s +         ar*40 + ac), Ah_g + Abase + (size_t)(m0+ar)*K + k0 + ac);
      cp16s(smem_addr32(s + 5120  + ar*40 + ac), Al_g + Abase + (size_t)(m0+ar)*K + k0 + ac);
      cp16s(smem_addr32(s + 10240 + br*136 + bc), Bh_g + Bbase + (size_t)(k0+br)*N + n0 + bc);
      cp16s(smem_addr32(s + 14592 + br*136 + bc), Bl_g + Bbase + (size_t)(k0+br)*N + n0 + bc);
      cp_commit();
      cp_wait<1>();
    } else {
      cp_wait<0>();
    }
    __syncthreads();
    const __nv_bfloat16* s = sm + (kb&1)*18944;
    #pragma unroll
    for (int ks=0; ks<2; ks++){
      uint32_t ah[2][4], al[2][4];
      #pragma unroll
      for (int mt=0; mt<2; mt++){
        const __nv_bfloat16* p = s + (wm*32 + mt*16 + (lane&15))*40 + ks*16 + (lane>>4)*8;
        ldsm4(ah[mt], p);
        ldsm4(al[mt], p + 5120);
      }
      uint32_t bh[2][4], bl[2][4];
      #pragma unroll
      for (int nh=0; nh<2; nh++){
        const __nv_bfloat16* p = s + 10240 + (ks*16 + (lane&15))*136 + wn*32 + nh*16 + (lane>>4)*8;
        ldsm4t(bh[nh], p);
        ldsm4t(bl[nh], p + 4352);
      }
      #pragma unroll
      for (int mt=0; mt<2; mt++){
        #pragma unroll
        for (int nt=0; nt<4; nt++){
          const int nh = nt>>1, sb = (nt&1)*2;
          mma_bf16(acc[mt][nt], ah[mt], bh[nh][sb], bh[nh][sb+1]);
          mma_bf16(acc[mt][nt], ah[mt], bl[nh][sb], bl[nh][sb+1]);
          mma_bf16(acc[mt][nt], al[mt], bh[nh][sb], bh[nh][sb+1]);
        }
      }
    }
    __syncthreads();
  }
  const int g = lane>>2, tg = lane&3;
  #pragma unroll
  for (int mt=0; mt<2; mt++){
    #pragma unroll
    for (int nt=0; nt<4; nt++){
      const int row = m0 + wm*32 + mt*16 + g;
      const int col = n0 + wn*32 + nt*8 + tg*2;
      float v0=acc[mt][nt][0], v1=acc[mt][nt][1], v2=acc[mt][nt][2], v3=acc[mt][nt][3];
      if constexpr (PHASE==1){
        v0=gelu_fast(v0); v1=gelu_fast(v1); v2=gelu_fast(v2); v3=gelu_fast(v3);
        __nv_bfloat16 h0=__float2bfloat16(v0), h1=__float2bfloat16(v1);
        __nv_bfloat16 l0=__float2bfloat16(v0-__bfloat162float(h0));
        __nv_bfloat16 l1=__float2bfloat16(v1-__bfloat162float(h1));
        size_t o = Cbase + (size_t)row*N + col;
        *(__nv_bfloat162*)&g_h_hi[o] = __halves2bfloat162(h0,h1);
        *(__nv_bfloat162*)&g_h_lo[o] = __halves2bfloat162(l0,l1);
        __nv_bfloat16 h2=__float2bfloat16(v2), h3=__float2bfloat16(v3);
        __nv_bfloat16 l2=__float2bfloat16(v2-__bfloat162float(h2));
        __nv_bfloat16 l3=__float2bfloat16(v3-__bfloat162float(h3));
        size_t o2 = Cbase + (size_t)(row+8)*N + col;
        *(__nv_bfloat162*)&g_h_hi[o2] = __halves2bfloat162(h2,h3);
        *(__nv_bfloat162*)&g_h_lo[o2] = __halves2bfloat162(l2,l3);
      } else {
        *(float2*)&g_y[Cbase + (size_t)row*N + col]     = make_float2(v0,v1);
        *(float2*)&g_y[Cbase + (size_t)(row+8)*N + col] = make_float2(v2,v3);
      }
    }
  }
#endif
}

// ---------------- per-token weighted combine + bias ----------------
__global__ void scatter_kernel(const float* __restrict__ bias, float* __restrict__ out){
  int t = blockIdx.x;
  int s0 = g_dst_slot[2*t], s1 = g_dst_slot[2*t+1];
  float w0 = g_top_w[2*t], w1 = g_top_w[2*t+1];
  const float4* y0 = (const float4*)(g_y + (size_t)(s0 < 0 ? 0 : s0)*HS);
  const float4* y1 = (const float4*)(g_y + (size_t)(s1 < 0 ? 0 : s1)*HS);
  const float4* b4 = (const float4*)bias;
  float4* o = (float4*)(out + (size_t)t*HS);
  for (int j = threadIdx.x; j < HS/4; j += blockDim.x){
    float4 r = b4[j];
    if (s0 >= 0){ float4 v = y0[j]; r.x += w0*v.x; r.y += w0*v.y; r.z += w0*v.z; r.w += w0*v.w; }
    if (s1 >= 0){ float4 v = y1[j]; r.x += w1*v.x; r.y += w1*v.y; r.z += w1*v.z; r.w += w1*v.w; }
    o[j] = r;
  }
}

// ---------------- launcher ----------------
extern "C" void kernel_launch(void* const* d_in, const int* in_sizes, int n_in,
                              void* d_out, int out_size){
  const float* x    = (const float*)d_in[0];
  const float* wr   = (const float*)d_in[1];
  const float* w1   = (const float*)d_in[2];
  const float* w2   = (const float*)d_in[3];
  const float* bias = (const float*)d_in[4];
  float* out = (float*)d_out;

  cudaFuncSetAttribute(gemm_tc_kernel<1>, cudaFuncAttributeMaxDynamicSharedMemorySize, GSMEM);
  cudaFuncSetAttribute(gemm_tc_kernel<2>, cudaFuncAttributeMaxDynamicSharedMemorySize, GSMEM);
  cudaFuncSetAttribute(gemm_split_kernel<1>, cudaFuncAttributeMaxDynamicSharedMemorySize, HSMEM);
  cudaFuncSetAttribute(gemm_split_kernel<2>, cudaFuncAttributeMaxDynamicSharedMemorySize, HSMEM);

  // launch order places gemm_tc<1> at index 3 — the ncu capture slot
  router_kernel<<<T_TOK/8, 256>>>(x, wr);                         // 0
  scan_kernel<<<1, 1024>>>();                                     // 1
  prep_kernel<<<dim3(128,128,17), 256>>>(x, w1, w2);              // 2 (transpose+gather)
  gemm_tc_kernel<1><<<dim3(FFN/256, CAP/256, NEXP), 256, GSMEM>>>(); // 3 <- profiled
  // HMMA fallback (empty bodies in the tcgen05 binary)
  const int n4 = NEXP*HS*FFN/4;
  split_w_kernel<<<(n4+255)/256, 256>>>(w1, 0);
  split_w_kernel<<<(n4+255)/256, 256>>>(w2, 1);
  gemm_split_kernel<1><<<dim3(FFN/128, CAP/128, NEXP), 512, HSMEM>>>();
  gemm_tc_kernel<2><<<dim3(HS/256, CAP/256, NEXP), 256, GSMEM>>>();
  gemm_split_kernel<2><<<dim3(HS/128, CAP/128, NEXP), 512, HSMEM>>>();
  scatter_kernel<<<T_TOK, 128>>>(bias, out);
}

// round 10
// speedup vs baseline: 2.5910x; 1.5642x over previous
#include <cuda_runtime.h>
#include <cuda_bf16.h>
#include <cuda_fp16.h>
#include <math.h>
#include <stdint.h>

#define T_TOK   16384
#define HS      1024
#define FFN     4096
#define NEXP    8
#define CAP     4096
#define NASSIGN (2*T_TOK)
#define SLOTS   (NEXP*CAP)

#if defined(__CUDA_ARCH_FEAT_SM103_ALL) || defined(__CUDA_ARCH_FEAT_SM100_ALL) || defined(__CUDA_ARCH_FEAT_SM101_ALL)
#define HAS_TCGEN05 1
#else
#define HAS_TCGEN05 0
#endif

// ---------------- static device scratch (fp16 single-precision operands) ------
__device__ __half g_xb[(size_t)SLOTS*HS];
__device__ __half g_h [(size_t)SLOTS*FFN];
__device__ float  g_y [(size_t)SLOTS*HS];
// tcgen05 path: weights transposed to [E][N][K] K-major
__device__ __half g_w1t[(size_t)NEXP*FFN*HS];
__device__ __half g_w2t[(size_t)NEXP*HS*FFN];
// HMMA fallback path: weights in original [E][K][N]
__device__ __half g_w1 [(size_t)NEXP*HS*FFN];
__device__ __half g_w2 [(size_t)NEXP*FFN*HS];
__device__ int    g_top_e[NASSIGN];
__device__ float  g_top_w[NASSIGN];
__device__ int    g_dst_slot[NASSIGN];

// ---------------- arch-neutral helpers ----------------
__device__ __forceinline__ uint32_t smem_addr32(const void* p){
  return (uint32_t)__cvta_generic_to_shared(p);
}
__device__ __forceinline__ void cp16s(uint32_t dst, const void* src){
  asm volatile("cp.async.cg.shared.global [%0], [%1], 16;\n" :: "r"(dst), "l"(src));
}
__device__ __forceinline__ void cp_commit(){ asm volatile("cp.async.commit_group;\n"); }
template<int NW> __device__ __forceinline__ void cp_wait(){
  asm volatile("cp.async.wait_group %0;\n" :: "n"(NW));
}
__device__ __forceinline__ void ldsm4(uint32_t* r, const __half* p){
  uint32_t a = smem_addr32(p);
  asm volatile("ldmatrix.sync.aligned.m8n8.x4.shared.b16 {%0,%1,%2,%3}, [%4];\n"
    : "=r"(r[0]),"=r"(r[1]),"=r"(r[2]),"=r"(r[3]) : "r"(a));
}
__device__ __forceinline__ void ldsm4t(uint32_t* r, const __half* p){
  uint32_t a = smem_addr32(p);
  asm volatile("ldmatrix.sync.aligned.m8n8.x4.trans.shared.b16 {%0,%1,%2,%3}, [%4];\n"
    : "=r"(r[0]),"=r"(r[1]),"=r"(r[2]),"=r"(r[3]) : "r"(a));
}
__device__ __forceinline__ void mma_f16_hmma(float* c, const uint32_t* a, uint32_t b0, uint32_t b1){
  asm volatile("mma.sync.aligned.m16n8k16.row.col.f32.f16.f16.f32 "
    "{%0,%1,%2,%3}, {%4,%5,%6,%7}, {%8,%9}, {%0,%1,%2,%3};\n"
    : "+f"(c[0]),"+f"(c[1]),"+f"(c[2]),"+f"(c[3])
    : "r"(a[0]),"r"(a[1]),"r"(a[2]),"r"(a[3]), "r"(b0),"r"(b1));
}
__device__ __forceinline__ uint32_t sw64(uint32_t off){ return off ^ ((off >> 3) & 0x30); }

__device__ __forceinline__ float gelu_fast(float x){
  float t = x*x;
  float u = x*(0.7978845608f + 0.0356774081f*t);
  float th;
  asm("tanh.approx.f32 %0, %1;" : "=f"(th) : "f"(u));
  return 0.5f*__fmaf_rn(x, th, x);
}
__device__ __forceinline__ uint32_t elect_one(){
  uint32_t pred;
  asm volatile("{\n.reg .pred p;\nelect.sync _|p, 0xFFFFFFFF;\nselp.b32 %0, 1, 0, p;\n}" : "=r"(pred));
  return pred;
}
__device__ __forceinline__ void mbar_init(uint32_t a, uint32_t cnt){
  asm volatile("mbarrier.init.shared.b64 [%0], %1;" :: "r"(a), "r"(cnt) : "memory");
}
__device__ __forceinline__ void mbar_wait(uint32_t a, uint32_t parity){
  asm volatile("{\n.reg .pred P;\nLW%=:\nmbarrier.try_wait.parity.acquire.cta.shared::cta.b64 P, [%0], %1, 0x989680;\n@!P bra LW%=;\n}"
    :: "r"(a), "r"(parity) : "memory");
}
#if HAS_TCGEN05
__device__ __forceinline__ void tcg_alloc(uint32_t dst_smem, uint32_t ncols){
  asm volatile("tcgen05.alloc.cta_group::1.sync.aligned.shared::cta.b32 [%0], %1;" :: "r"(dst_smem), "r"(ncols) : "memory");
}
__device__ __forceinline__ void tcg_dealloc(uint32_t tmem, uint32_t ncols){
  asm volatile("tcgen05.dealloc.cta_group::1.sync.aligned.b32 %0, %1;" :: "r"(tmem), "r"(ncols));
}
__device__ __forceinline__ void tcg_relinquish(){
  asm volatile("tcgen05.relinquish_alloc_permit.cta_group::1.sync.aligned;");
}
__device__ __forceinline__ void tcg_commit(uint32_t mbar){
  asm volatile("tcgen05.commit.cta_group::1.mbarrier::arrive::one.shared::cluster.b64 [%0];" :: "r"(mbar) : "memory");
}
__device__ __forceinline__ void tcg_fence_after(){
  asm volatile("tcgen05.fence::after_thread_sync;" ::: "memory");
}
__device__ __forceinline__ void fence_proxy_async_cta(){
  asm volatile("fence.proxy.async.shared::cta;" ::: "memory");
}
__device__ __forceinline__ void mma_f16_ss(uint32_t d, uint64_t a, uint64_t b, uint32_t idesc, uint32_t en){
  asm volatile("{\n.reg .pred p;\nsetp.ne.u32 p, %4, 0;\n"
    "tcgen05.mma.cta_group::1.kind::f16 [%0], %1, %2, %3, {%5,%5,%5,%5}, p;\n}"
    :: "r"(d), "l"(a), "l"(b), "r"(idesc), "r"(en), "r"(0u) : "memory");
}
__device__ __forceinline__ void ldtm32(uint32_t* r, uint32_t addr){
  asm volatile("tcgen05.ld.sync.aligned.32x32b.x32.b32 "
    "{%0,%1,%2,%3,%4,%5,%6,%7,%8,%9,%10,%11,%12,%13,%14,%15,"
    "%16,%17,%18,%19,%20,%21,%22,%23,%24,%25,%26,%27,%28,%29,%30,%31}, [%32];"
    : "=r"(r[0]),"=r"(r[1]),"=r"(r[2]),"=r"(r[3]),"=r"(r[4]),"=r"(r[5]),"=r"(r[6]),"=r"(r[7]),
      "=r"(r[8]),"=r"(r[9]),"=r"(r[10]),"=r"(r[11]),"=r"(r[12]),"=r"(r[13]),"=r"(r[14]),"=r"(r[15]),
      "=r"(r[16]),"=r"(r[17]),"=r"(r[18]),"=r"(r[19]),"=r"(r[20]),"=r"(r[21]),"=r"(r[22]),"=r"(r[23]),
      "=r"(r[24]),"=r"(r[25]),"=r"(r[26]),"=r"(r[27]),"=r"(r[28]),"=r"(r[29]),"=r"(r[30]),"=r"(r[31])
    : "r"(addr));
}
__device__ __forceinline__ void tcg_wait_ld(){
  asm volatile("tcgen05.wait::ld.sync.aligned;" ::: "memory");
}
// SW64 K-major smem descriptor: layout=4, SBO=32 (8 rows x 64B atom), LBO=1
__device__ __forceinline__ uint64_t make_desc_sw64(uint32_t base_addr){
  const uint64_t BASE = (uint64_t(4) << 61) | (uint64_t(1) << 46) | (uint64_t(32) << 32) | (uint64_t(1) << 16);
  return BASE | ((uint64_t)(base_addr >> 4) & 0x3FFF);
}
#endif

// ---------------- router: fp64 logits + softmax + top-2 ----------------
__global__ void router_kernel(const float* __restrict__ x, const float* __restrict__ wr){
  int widx = (blockIdx.x * blockDim.x + threadIdx.x) >> 5;
  int lane = threadIdx.x & 31;
  if (widx >= T_TOK) return;
  const float* xr = x + (size_t)widx * HS;
  double acc[NEXP];
  #pragma unroll
  for (int e=0;e<NEXP;e++) acc[e]=0.0;
  for (int h = lane; h < HS; h += 32){
    double xv = (double)xr[h];
    const float* wrow = wr + h*NEXP;
    #pragma unroll
    for (int e=0;e<NEXP;e++) acc[e] += xv * (double)wrow[e];
  }
  #pragma unroll
  for (int off=16; off; off>>=1){
    #pragma unroll
    for (int e=0;e<NEXP;e++) acc[e] += __shfl_xor_sync(0xffffffffu, acc[e], off);
  }
  if (lane == 0){
    double m = acc[0];
    #pragma unroll
    for (int e=1;e<NEXP;e++) m = fmax(m, acc[e]);
    double ex[NEXP], s = 0.0;
    #pragma unroll
    for (int e=0;e<NEXP;e++){ ex[e] = exp(acc[e]-m); s += ex[e]; }
    int e0 = 0; double b0 = acc[0];
    #pragma unroll
    for (int e=1;e<NEXP;e++) if (acc[e] > b0){ b0 = acc[e]; e0 = e; }
    int e1 = (e0==0) ? 1 : 0; double b1 = acc[e1];
    #pragma unroll
    for (int e=0;e<NEXP;e++) if (e != e0 && acc[e] > b1){ b1 = acc[e]; e1 = e; }
    g_top_e[2*widx]   = e0;
    g_top_e[2*widx+1] = e1;
    g_top_w[2*widx]   = (float)(ex[e0]/s);
    g_top_w[2*widx+1] = (float)(ex[e1]/s);
  }
}

// ---------------- stable counting sort + capacity (hierarchical scan) ----------------
__global__ void __launch_bounds__(1024,1) scan_kernel(){
  __shared__ int wbase[32][NEXP];
  __shared__ int etot[NEXP];
  __shared__ int starts[NEXP];
  int t = threadIdx.x, lane = t & 31, w = t >> 5;
  const int i0 = t * 32;
  int e_loc[32];
  int cnt[NEXP];
  #pragma unroll
  for (int e=0;e<NEXP;e++) cnt[e]=0;
  #pragma unroll
  for (int j=0;j<32;j++){ e_loc[j] = g_top_e[i0+j]; cnt[e_loc[j]]++; }
  int excl[NEXP];
  #pragma unroll
  for (int e=0;e<NEXP;e++){
    int v = cnt[e], s = v;
    #pragma unroll
    for (int off=1; off<32; off<<=1){
      int n = __shfl_up_sync(0xffffffffu, s, off);
      if (lane >= off) s += n;
    }
    excl[e] = s - v;
    if (lane == 31) wbase[w][e] = s;
  }
  __syncthreads();
  if (w == 0){
    #pragma unroll
    for (int e=0;e<NEXP;e++){
      int v = wbase[lane][e], s = v;
      #pragma unroll
      for (int off=1; off<32; off<<=1){
        int n = __shfl_up_sync(0xffffffffu, s, off);
        if (lane >= off) s += n;
      }
      wbase[lane][e] = s - v;
      if (lane == 31) etot[e] = s;
    }
  }
  __syncthreads();
  if (t == 0){
    int run = 0;
    #pragma unroll
    for (int e=0;e<NEXP;e++){ starts[e] = run; run += etot[e]; }
  }
  __syncthreads();
  int base[NEXP];
  #pragma unroll
  for (int e=0;e<NEXP;e++) base[e] = starts[e] + wbase[w][e] + excl[e];
  #pragma unroll
  for (int j=0;j<32;j++){
    int e = e_loc[j];
    int pos = base[e]++;
    int r = pos - starts[e];
    g_dst_slot[i0+j] = (r < CAP) ? (e*CAP + r) : -1;
  }
}

// ---------------- fused prep: weight transpose->fp16 (tcgen05) AND token gather->fp16 ----
// grid (128,128,17), block 256 flat.
__global__ void prep_kernel(const float* __restrict__ x,
                            const float* __restrict__ w1,
                            const float* __restrict__ w2){
  if (blockIdx.z < 16){
#if HAS_TCGEN05
    __shared__ float tile[32][33];
    int which = blockIdx.z >= 8;
    int e = blockIdx.z & 7;
    const int K = which ? FFN : HS;
    const int N = which ? HS  : FFN;
    const float* w = which ? w2 : w1;
    __half* dst = which ? g_w2t : g_w1t;
    int n0 = blockIdx.x*32, k0 = blockIdx.y*32;
    if (n0 >= N || k0 >= K) return;
    int tx = threadIdx.x & 31, ty = threadIdx.x >> 5;   // 32 x 8
    const float* in = w + (size_t)e*K*N;
    #pragma unroll
    for (int r=0;r<4;r++)
      tile[ty+8*r][tx] = in[(size_t)(k0+ty+8*r)*N + n0+tx];
    __syncthreads();
    #pragma unroll
    for (int r=0;r<4;r++){
      float v = tile[tx][ty+8*r];
      size_t o = ((size_t)e*N + n0+ty+8*r)*K + k0+tx;
      dst[o] = __float2half_rn(v);
    }
#endif
    return;
  }
  // ---- gather: assignment i -> slot, fp32 row -> fp16 ----
  int base2 = (blockIdx.y*gridDim.x + blockIdx.x)*2;
  int i = base2 + (threadIdx.x >> 7);
  int t128 = threadIdx.x & 127;
  int dst = g_dst_slot[i];
  if (dst < 0) return;
  const float4* src = (const float4*)(x + (size_t)(i>>1)*HS);
  __half* xb = g_xb + (size_t)dst*HS;
  for (int j = t128; j < HS/4; j += 128){
    float4 v = src[j];
    __half2 p0 = __floats2half2_rn(v.x, v.y);
    __half2 p1 = __floats2half2_rn(v.z, v.w);
    *(__half2*)&xb[j*4]   = p0;
    *(__half2*)&xb[j*4+2] = p1;
  }
}

// ---------------- HMMA-path weight convert fp32 -> fp16 ([E][K][N]) --------
__global__ void split_w_kernel(const float* __restrict__ w, int which){
#if !HAS_TCGEN05
  __half* dst = which ? g_w2 : g_w1;
  size_t i = (size_t)blockIdx.x*blockDim.x + threadIdx.x;
  const size_t n4 = (size_t)NEXP*HS*FFN/4;
  if (i >= n4) return;
  float4 v = ((const float4*)w)[i];
  *(__half2*)&dst[i*4]   = __floats2half2_rn(v.x, v.y);
  *(__half2*)&dst[i*4+2] = __floats2half2_rn(v.z, v.w);
#endif
}

// =====================================================================
// PATH A: tcgen05 fp16 grouped GEMM, tile 256x256, K-chunk 32, 4-stage ring
// stage (SW64, 64B rows): A 16KB | B 16KB = 32KB; 4 stages = 128KB
// TMEM: D0 (rows 0-127) cols 0-255, D1 (rows 128-255) cols 256-511
// =====================================================================
#define GSMEM (4*32768 + 1024)

template<int PHASE>
__global__ void __launch_bounds__(256,1) gemm_tc_kernel(){
#if HAS_TCGEN05
  constexpr int Kdim = (PHASE==1) ? HS  : FFN;
  constexpr int Ndim = (PHASE==1) ? FFN : HS;
  constexpr int NKB  = Kdim/32;
  const __half* __restrict__ A_g = (PHASE==1) ? g_xb  : g_h;
  const __half* __restrict__ B_g = (PHASE==1) ? g_w1t : g_w2t;

  extern __shared__ char dyn[];
  __shared__ uint64_t s_mbar[4];
  __shared__ uint32_t s_tptr;
  uint32_t sbase = (smem_addr32(dyn) + 1023u) & ~1023u;
  uint32_t mb[4] = { smem_addr32(&s_mbar[0]), smem_addr32(&s_mbar[1]),
                     smem_addr32(&s_mbar[2]), smem_addr32(&s_mbar[3]) };

  const int tid = threadIdx.x;
  const int wid = tid >> 5, lane = tid & 31;
  const int e  = blockIdx.z;
  const int m0 = blockIdx.y * 256;
  const int n0 = blockIdx.x * 256;
  const size_t Abase = ((size_t)e*CAP  + m0) * Kdim;
  const size_t Bbase = ((size_t)e*Ndim + n0) * Kdim;

  if (wid == 0) tcg_alloc(smem_addr32(&s_tptr), 512);
  if (tid == 0){ mbar_init(mb[0],1); mbar_init(mb[1],1); mbar_init(mb[2],1); mbar_init(mb[3],1); }
  __syncthreads();
  const uint32_t tmem = s_tptr;

  // stage: A 256 rows x 64B @0, B 256 rows x 64B @16384. thread -> one row (4x16B) per array
  auto load_stage = [&](int buf, int kb){
    uint32_t st = sbase + buf*32768;
    const int k0 = kb*32;
    #pragma unroll
    for (int i=0;i<4;i++){
      int id = tid*4 + i;                  // row = tid, chunk i
      int r = id >> 2, c = id & 3;
      uint32_t sw = sw64((uint32_t)(r*64 + c*16));
      cp16s(st +         sw, A_g + Abase + (size_t)r*Kdim + k0 + c*8);
      cp16s(st + 16384 + sw, B_g + Bbase + (size_t)r*Kdim + k0 + c*8);
    }
    cp_commit();
  };

  load_stage(0,0); load_stage(1,1); load_stage(2,2);

  // idesc: fp16 inputs (atype/btype=0), f32 accum, M=128 atom, N=256
  const uint32_t idesc = (1u<<4) | ((256u>>3)<<17) | ((128u>>4)<<24);
  int ph[4] = {0,0,0,0};

  for (int kb = 0; kb < NKB; kb++){
    const int buf = kb & 3;
    if (kb < NKB-2)      cp_wait<2>();
    else if (kb == NKB-2) cp_wait<1>();
    else                  cp_wait<0>();
    __syncthreads();
    if (wid == 0 && elect_one()){
      fence_proxy_async_cta();
      uint32_t st = sbase + buf*32768;
      uint64_t dB = make_desc_sw64(st + 16384);
      #pragma unroll
      for (int half=0; half<2; half++){
        uint64_t dA = make_desc_sw64(st + half*8192);
        uint32_t d  = tmem + half*256;
        #pragma unroll
        for (int ks=0; ks<2; ks++){
          uint32_t first = (kb==0 && ks==0) ? 0u : 1u;
          mma_f16_ss(d, dA + ks*2, dB + ks*2, idesc, first);
        }
      }
      tcg_commit(mb[buf]);
    }
    if (kb == 0){
      if (3 < NKB) load_stage(3, 3);
    } else if (kb+3 < NKB){
      const int pb = (kb-1) & 3;          // == (kb+3)&3
      mbar_wait(mb[pb], ph[pb]); ph[pb] ^= 1;
      load_stage(pb, kb+3);
    }
  }
  {
    const int lb = (NKB-1) & 3;
    mbar_wait(mb[lb], ph[lb]);
  }
  tcg_fence_after();

  // epilogue: warps 0-3 -> rows m0+0..127 (cols 0-255), warps 4-7 -> rows +128..255
  {
    const int half = wid >> 2;
    const int row  = m0 + half*128 + (wid&3)*32 + lane;
    const size_t slot = (size_t)e*CAP + row;
    const uint32_t tbase = tmem + half*256;
    #pragma unroll
    for (int ch=0; ch<8; ch++){
      uint32_t r[32];
      ldtm32(r, tbase + ch*32);
      tcg_wait_ld();
      const int nc = n0 + ch*32;
      if constexpr (PHASE==1){
        size_t o = slot*FFN + nc;
        uint32_t hp[16];
        #pragma unroll
        for (int j=0;j<32;j+=2){
          float g0 = gelu_fast(__uint_as_float(r[j]));
          float g1 = gelu_fast(__uint_as_float(r[j+1]));
          uint32_t p;
          asm("cvt.rn.f16x2.f32 %0, %1, %2;" : "=r"(p) : "f"(g1), "f"(g0));
          hp[j>>1] = p;
        }
        #pragma unroll
        for (int q=0;q<4;q++)
          *(uint4*)&g_h[o + q*8] = make_uint4(hp[q*4],hp[q*4+1],hp[q*4+2],hp[q*4+3]);
      } else {
        size_t o = slot*HS + nc;
        #pragma unroll
        for (int j=0;j<32;j+=4){
          float4 v = make_float4(__uint_as_float(r[j]), __uint_as_float(r[j+1]),
                                 __uint_as_float(r[j+2]), __uint_as_float(r[j+3]));
          *(float4*)&g_y[o+j] = v;
        }
      }
    }
  }
  __syncthreads();
  if (wid == 0){
    tcg_relinquish();
    tcg_dealloc(tmem, 512);
  }
#endif
}

// =====================================================================
// PATH B: HMMA mma.sync fp16 grouped GEMM (fallback, single product)
// stage elems: A 128x40=5120 | B 32x136=4352 -> 9472; 2 stages
// =====================================================================
#define HSMEM (2*9472*2)
template<int PHASE>
__global__ void __launch_bounds__(512,1) gemm_split_kernel(){
#if !HAS_TCGEN05
  constexpr int K  = (PHASE==1) ? HS  : FFN;
  constexpr int N  = (PHASE==1) ? FFN : HS;
  constexpr int KB = K/32;
  const __half* __restrict__ A_g = (PHASE==1) ? g_xb : g_h;
  const __half* __restrict__ B_g = (PHASE==1) ? g_w1 : g_w2;

  extern __shared__ __align__(16) __half sm[];

  const int e  = blockIdx.z;
  const int m0 = blockIdx.y * 128;
  const int n0 = blockIdx.x * 128;
  const size_t Abase = (size_t)e*CAP*K;
  const size_t Bbase = (size_t)e*K*N;
  const size_t Cbase = (size_t)e*CAP*N;

  const int tid = threadIdx.x;
  const int warp = tid >> 5, lane = tid & 31;
  const int wm = warp >> 2, wn = warp & 3;

  const int ar = tid >> 2,  ac = (tid & 3)  * 8;
  const int br = tid >> 4,  bc = (tid & 15) * 8;

  float acc[2][4][4];
  #pragma unroll
  for (int i=0;i<2;i++)
    #pragma unroll
    for (int j=0;j<4;j++)
      #pragma unroll
      for (int k=0;k<4;k++) acc[i][j][k]=0.f;

  {
    __half* s = sm;
    cp16s(smem_addr32(s +        ar*40 + ac), A_g + Abase + (size_t)(m0+ar)*K + ac);
    cp16s(smem_addr32(s + 5120 + br*136 + bc), B_g + Bbase + (size_t)br*N + n0 + bc);
    cp_commit();
  }
  for (int kb=0; kb<KB; kb++){
    if (kb+1 < KB){
      const int k0 = (kb+1)*32;
      __half* s = sm + ((kb+1)&1)*9472;
      cp16s(smem_addr32(s +        ar*40 + ac), A_g + Abase + (size_t)(m0+ar)*K + k0 + ac);
      cp16s(smem_addr32(s + 5120 + br*136 + bc), B_g + Bbase + (size_t)(k0+br)*N + n0 + bc);
      cp_commit();
      cp_wait<1>();
    } else {
      cp_wait<0>();
    }
    __syncthreads();
    const __half* s = sm + (kb&1)*9472;
    #pragma unroll
    for (int ks=0; ks<2; ks++){
      uint32_t a[2][4];
      #pragma unroll
      for (int mt=0; mt<2; mt++){
        const __half* p = s + (wm*32 + mt*16 + (lane&15))*40 + ks*16 + (lane>>4)*8;
        ldsm4(a[mt], p);
      }
      uint32_t b[2][4];
      #pragma unroll
      for (int nh=0; nh<2; nh++){
        const __half* p = s + 5120 + (ks*16 + (lane&15))*136 + wn*32 + nh*16 + (lane>>4)*8;
        ldsm4t(b[nh], p);
      }
      #pragma unroll
      for (int mt=0; mt<2; mt++){
        #pragma unroll
        for (int nt=0; nt<4; nt++){
          const int nh = nt>>1, sb = (nt&1)*2;
          mma_f16_hmma(acc[mt][nt], a[mt], b[nh][sb], b[nh][sb+1]);
        }
      }
    }
    __syncthreads();
  }
  const int g = lane>>2, tg = lane&3;
  #pragma unroll
  for (int mt=0; mt<2; mt++){
    #pragma unroll
    for (int nt=0; nt<4; nt++){
      const int row = m0 + wm*32 + mt*16 + g;
      const int col = n0 + wn*32 + nt*8 + tg*2;
      float v0=acc[mt][nt][0], v1=acc[mt][nt][1], v2=acc[mt][nt][2], v3=acc[mt][nt][3];
      if constexpr (PHASE==1){
        v0=gelu_fast(v0); v1=gelu_fast(v1); v2=gelu_fast(v2); v3=gelu_fast(v3);
        size_t o  = Cbase + (size_t)row*N + col;
        size_t o2 = Cbase + (size_t)(row+8)*N + col;
        *(__half2*)&g_h[o]  = __floats2half2_rn(v0, v1);
        *(__half2*)&g_h[o2] = __floats2half2_rn(v2, v3);
      } else {
        *(float2*)&g_y[Cbase + (size_t)row*N + col]     = make_float2(v0,v1);
        *(float2*)&g_y[Cbase + (size_t)(row+8)*N + col] = make_float2(v2,v3);
      }
    }
  }
#endif
}

// ---------------- per-token weighted combine + bias ----------------
__global__ void scatter_kernel(const float* __restrict__ bias, float* __restrict__ out){
  int t = blockIdx.x;
  int s0 = g_dst_slot[2*t], s1 = g_dst_slot[2*t+1];
  float w0 = g_top_w[2*t], w1 = g_top_w[2*t+1];
  const float4* y0 = (const float4*)(g_y + (size_t)(s0 < 0 ? 0 : s0)*HS);
  const float4* y1 = (const float4*)(g_y + (size_t)(s1 < 0 ? 0 : s1)*HS);
  const float4* b4 = (const float4*)bias;
  float4* o = (float4*)(out + (size_t)t*HS);
  for (int j = threadIdx.x; j < HS/4; j += blockDim.x){
    float4 r = b4[j];
    if (s0 >= 0){ float4 v = y0[j]; r.x += w0*v.x; r.y += w0*v.y; r.z += w0*v.z; r.w += w0*v.w; }
    if (s1 >= 0){ float4 v = y1[j]; r.x += w1*v.x; r.y += w1*v.y; r.z += w1*v.z; r.w += w1*v.w; }
    o[j] = r;
  }
}

// ---------------- launcher ----------------
extern "C" void kernel_launch(void* const* d_in, const int* in_sizes, int n_in,
                              void* d_out, int out_size){
  const float* x    = (const float*)d_in[0];
  const float* wr   = (const float*)d_in[1];
  const float* w1   = (const float*)d_in[2];
  const float* w2   = (const float*)d_in[3];
  const float* bias = (const float*)d_in[4];
  float* out = (float*)d_out;

  cudaFuncSetAttribute(gemm_tc_kernel<1>, cudaFuncAttributeMaxDynamicSharedMemorySize, GSMEM);
  cudaFuncSetAttribute(gemm_tc_kernel<2>, cudaFuncAttributeMaxDynamicSharedMemorySize, GSMEM);
  cudaFuncSetAttribute(gemm_split_kernel<1>, cudaFuncAttributeMaxDynamicSharedMemorySize, HSMEM);
  cudaFuncSetAttribute(gemm_split_kernel<2>, cudaFuncAttributeMaxDynamicSharedMemorySize, HSMEM);

  // order keeps gemm_tc<1> at launch index 3 (ncu capture slot)
  router_kernel<<<T_TOK/8, 256>>>(x, wr);                            // 0
  scan_kernel<<<1, 1024>>>();                                        // 1
  prep_kernel<<<dim3(128,128,17), 256>>>(x, w1, w2);                 // 2
  gemm_tc_kernel<1><<<dim3(FFN/256, CAP/256, NEXP), 256, GSMEM>>>(); // 3 <- profiled
  // HMMA fallback (empty bodies in the sm_103a binary)
  const int n4 = NEXP*HS*FFN/4;
  split_w_kernel<<<(n4+255)/256, 256>>>(w1, 0);
  split_w_kernel<<<(n4+255)/256, 256>>>(w2, 1);
  gemm_split_kernel<1><<<dim3(FFN/128, CAP/128, NEXP), 512, HSMEM>>>();
  gemm_tc_kernel<2><<<dim3(HS/256, CAP/256, NEXP), 256, GSMEM>>>();
  gemm_split_kernel<2><<<dim3(HS/128, CAP/128, NEXP), 512, HSMEM>>>();
  scatter_kernel<<<T_TOK, 128>>>(bias, out);
}

// round 12
// speedup vs baseline: 3.6232x; 1.3984x over previous
#include <cuda_runtime.h>
#include <cuda_bf16.h>
#include <cuda_fp16.h>
#include <math.h>
#include <stdint.h>

#define T_TOK   16384
#define HS      1024
#define FFN     4096
#define NEXP    8
#define CAP     4096
#define NASSIGN (2*T_TOK)
#define SLOTS   (NEXP*CAP)

#if defined(__CUDA_ARCH_FEAT_SM103_ALL) || defined(__CUDA_ARCH_FEAT_SM100_ALL) || defined(__CUDA_ARCH_FEAT_SM101_ALL)
#define HAS_TCGEN05 1
#else
#define HAS_TCGEN05 0
#endif

// ---------------- static device scratch ----------------
// tcgen05 path: A/B operands stored as contiguous pre-swizzled smem-image blocks:
//   A blocks: [e][m_tile][kb][128 rows x 32 cols fp16, SW64] = 8KB each
//   B blocks: [e][n_tile][kb][256 rows x 32 cols fp16, SW64] = 16KB each
// (fallback path uses the same arrays with plain row-major layout)
__device__ __half g_xb[(size_t)SLOTS*HS];
__device__ __half g_h [(size_t)SLOTS*FFN];
__device__ float  g_y [(size_t)SLOTS*HS];
__device__ __half g_w1t[(size_t)NEXP*FFN*HS];
__device__ __half g_w2t[(size_t)NEXP*HS*FFN];
__device__ __half g_w1 [(size_t)NEXP*HS*FFN];   // fallback row-major
__device__ __half g_w2 [(size_t)NEXP*FFN*HS];   // fallback row-major
__device__ int    g_top_e[NASSIGN];
__device__ float  g_top_w[NASSIGN];
__device__ int    g_dst_slot[NASSIGN];

// ---------------- helpers ----------------
__device__ __forceinline__ uint32_t smem_addr32(const void* p){
  return (uint32_t)__cvta_generic_to_shared(p);
}
__device__ __forceinline__ void cp16s(uint32_t dst, const void* src){
  asm volatile("cp.async.cg.shared.global [%0], [%1], 16;\n" :: "r"(dst), "l"(src));
}
__device__ __forceinline__ void cp_commit(){ asm volatile("cp.async.commit_group;\n"); }
template<int NW> __device__ __forceinline__ void cp_wait(){
  asm volatile("cp.async.wait_group %0;\n" :: "n"(NW));
}
__device__ __forceinline__ void ldsm4(uint32_t* r, const __half* p){
  uint32_t a = smem_addr32(p);
  asm volatile("ldmatrix.sync.aligned.m8n8.x4.shared.b16 {%0,%1,%2,%3}, [%4];\n"
    : "=r"(r[0]),"=r"(r[1]),"=r"(r[2]),"=r"(r[3]) : "r"(a));
}
__device__ __forceinline__ void ldsm4t(uint32_t* r, const __half* p){
  uint32_t a = smem_addr32(p);
  asm volatile("ldmatrix.sync.aligned.m8n8.x4.trans.shared.b16 {%0,%1,%2,%3}, [%4];\n"
    : "=r"(r[0]),"=r"(r[1]),"=r"(r[2]),"=r"(r[3]) : "r"(a));
}
__device__ __forceinline__ void mma_f16_hmma(float* c, const uint32_t* a, uint32_t b0, uint32_t b1){
  asm volatile("mma.sync.aligned.m16n8k16.row.col.f32.f16.f16.f32 "
    "{%0,%1,%2,%3}, {%4,%5,%6,%7}, {%8,%9}, {%0,%1,%2,%3};\n"
    : "+f"(c[0]),"+f"(c[1]),"+f"(c[2]),"+f"(c[3])
    : "r"(a[0]),"r"(a[1]),"r"(a[2]),"r"(a[3]), "r"(b0),"r"(b1));
}
__device__ __forceinline__ uint32_t sw64(uint32_t off){ return off ^ ((off >> 3) & 0x30); }

__device__ __forceinline__ float gelu_fast(float x){
  float t = x*x;
  float u = x*(0.7978845608f + 0.0356774081f*t);
  float th;
  asm("tanh.approx.f32 %0, %1;" : "=f"(th) : "f"(u));
  return 0.5f*__fmaf_rn(x, th, x);
}
__device__ __forceinline__ uint32_t elect_one(){
  uint32_t pred;
  asm volatile("{\n.reg .pred p;\nelect.sync _|p, 0xFFFFFFFF;\nselp.b32 %0, 1, 0, p;\n}" : "=r"(pred));
  return pred;
}
__device__ __forceinline__ void mbar_init(uint32_t a, uint32_t cnt){
  asm volatile("mbarrier.init.shared.b64 [%0], %1;" :: "r"(a), "r"(cnt) : "memory");
}
__device__ __forceinline__ void mbar_expect_tx(uint32_t a, uint32_t bytes){
  asm volatile("mbarrier.arrive.expect_tx.shared.b64 _, [%0], %1;" :: "r"(a), "r"(bytes) : "memory");
}
__device__ __forceinline__ void mbar_wait(uint32_t a, uint32_t parity){
  asm volatile("{\n.reg .pred P;\nLW%=:\nmbarrier.try_wait.parity.acquire.cta.shared::cta.b64 P, [%0], %1, 0x989680;\n@!P bra LW%=;\n}"
    :: "r"(a), "r"(parity) : "memory");
}
#if HAS_TCGEN05
__device__ __forceinline__ void bulkcp(uint32_t dst, const void* src, uint32_t bytes, uint32_t mbar){
  asm volatile("cp.async.bulk.shared::cluster.global.mbarrier::complete_tx::bytes [%0], [%1], %2, [%3];"
    :: "r"(dst), "l"(src), "r"(bytes), "r"(mbar) : "memory");
}
__device__ __forceinline__ void tcg_alloc(uint32_t dst_smem, uint32_t ncols){
  asm volatile("tcgen05.alloc.cta_group::1.sync.aligned.shared::cta.b32 [%0], %1;" :: "r"(dst_smem), "r"(ncols) : "memory");
}
__device__ __forceinline__ void tcg_dealloc(uint32_t tmem, uint32_t ncols){
  asm volatile("tcgen05.dealloc.cta_group::1.sync.aligned.b32 %0, %1;" :: "r"(tmem), "r"(ncols));
}
__device__ __forceinline__ void tcg_relinquish(){
  asm volatile("tcgen05.relinquish_alloc_permit.cta_group::1.sync.aligned;");
}
__device__ __forceinline__ void tcg_commit(uint32_t mbar){
  asm volatile("tcgen05.commit.cta_group::1.mbarrier::arrive::one.shared::cluster.b64 [%0];" :: "r"(mbar) : "memory");
}
__device__ __forceinline__ void tcg_fence_after(){
  asm volatile("tcgen05.fence::after_thread_sync;" ::: "memory");
}
__device__ __forceinline__ void mma_f16_ss(uint32_t d, uint64_t a, uint64_t b, uint32_t idesc, uint32_t en){
  asm volatile("{\n.reg .pred p;\nsetp.ne.u32 p, %4, 0;\n"
    "tcgen05.mma.cta_group::1.kind::f16 [%0], %1, %2, %3, {%5,%5,%5,%5}, p;\n}"
    :: "r"(d), "l"(a), "l"(b), "r"(idesc), "r"(en), "r"(0u) : "memory");
}
__device__ __forceinline__ void ldtm32(uint32_t* r, uint32_t addr){
  asm volatile("tcgen05.ld.sync.aligned.32x32b.x32.b32 "
    "{%0,%1,%2,%3,%4,%5,%6,%7,%8,%9,%10,%11,%12,%13,%14,%15,"
    "%16,%17,%18,%19,%20,%21,%22,%23,%24,%25,%26,%27,%28,%29,%30,%31}, [%32];"
    : "=r"(r[0]),"=r"(r[1]),"=r"(r[2]),"=r"(r[3]),"=r"(r[4]),"=r"(r[5]),"=r"(r[6]),"=r"(r[7]),
      "=r"(r[8]),"=r"(r[9]),"=r"(r[10]),"=r"(r[11]),"=r"(r[12]),"=r"(r[13]),"=r"(r[14]),"=r"(r[15]),
      "=r"(r[16]),"=r"(r[17]),"=r"(r[18]),"=r"(r[19]),"=r"(r[20]),"=r"(r[21]),"=r"(r[22]),"=r"(r[23]),
      "=r"(r[24]),"=r"(r[25]),"=r"(r[26]),"=r"(r[27]),"=r"(r[28]),"=r"(r[29]),"=r"(r[30]),"=r"(r[31])
    : "r"(addr));
}
__device__ __forceinline__ void tcg_wait_ld(){
  asm volatile("tcgen05.wait::ld.sync.aligned;" ::: "memory");
}
// SW64 K-major smem descriptor: layout=4, SBO=32 (8 rows x 64B atom), LBO=1
__device__ __forceinline__ uint64_t make_desc_sw64(uint32_t base_addr){
  const uint64_t BASE = (uint64_t(4) << 61) | (uint64_t(1) << 46) | (uint64_t(32) << 32) | (uint64_t(1) << 16);
  return BASE | ((uint64_t)(base_addr >> 4) & 0x3FFF);
}
#endif

// ---------------- router: fp64 logits + softmax + top-2 ----------------
__global__ void router_kernel(const float* __restrict__ x, const float* __restrict__ wr){
  int widx = (blockIdx.x * blockDim.x + threadIdx.x) >> 5;
  int lane = threadIdx.x & 31;
  if (widx >= T_TOK) return;
  const float* xr = x + (size_t)widx * HS;
  double acc[NEXP];
  #pragma unroll
  for (int e=0;e<NEXP;e++) acc[e]=0.0;
  for (int h = lane; h < HS; h += 32){
    double xv = (double)xr[h];
    const float* wrow = wr + h*NEXP;
    #pragma unroll
    for (int e=0;e<NEXP;e++) acc[e] += xv * (double)wrow[e];
  }
  #pragma unroll
  for (int off=16; off; off>>=1){
    #pragma unroll
    for (int e=0;e<NEXP;e++) acc[e] += __shfl_xor_sync(0xffffffffu, acc[e], off);
  }
  if (lane == 0){
    double m = acc[0];
    #pragma unroll
    for (int e=1;e<NEXP;e++) m = fmax(m, acc[e]);
    double ex[NEXP], s = 0.0;
    #pragma unroll
    for (int e=0;e<NEXP;e++){ ex[e] = exp(acc[e]-m); s += ex[e]; }
    int e0 = 0; double b0 = acc[0];
    #pragma unroll
    for (int e=1;e<NEXP;e++) if (acc[e] > b0){ b0 = acc[e]; e0 = e; }
    int e1 = (e0==0) ? 1 : 0; double b1 = acc[e1];
    #pragma unroll
    for (int e=0;e<NEXP;e++) if (e != e0 && acc[e] > b1){ b1 = acc[e]; e1 = e; }
    g_top_e[2*widx]   = e0;
    g_top_e[2*widx+1] = e1;
    g_top_w[2*widx]   = (float)(ex[e0]/s);
    g_top_w[2*widx+1] = (float)(ex[e1]/s);
  }
}

// ---------------- stable counting sort + capacity (hierarchical scan) ----------------
__global__ void __launch_bounds__(1024,1) scan_kernel(){
  __shared__ int wbase[32][NEXP];
  __shared__ int etot[NEXP];
  __shared__ int starts[NEXP];
  int t = threadIdx.x, lane = t & 31, w = t >> 5;
  const int i0 = t * 32;
  int e_loc[32];
  int cnt[NEXP];
  #pragma unroll
  for (int e=0;e<NEXP;e++) cnt[e]=0;
  #pragma unroll
  for (int j=0;j<32;j++){ e_loc[j] = g_top_e[i0+j]; cnt[e_loc[j]]++; }
  int excl[NEXP];
  #pragma unroll
  for (int e=0;e<NEXP;e++){
    int v = cnt[e], s = v;
    #pragma unroll
    for (int off=1; off<32; off<<=1){
      int n = __shfl_up_sync(0xffffffffu, s, off);
      if (lane >= off) s += n;
    }
    excl[e] = s - v;
    if (lane == 31) wbase[w][e] = s;
  }
  __syncthreads();
  if (w == 0){
    #pragma unroll
    for (int e=0;e<NEXP;e++){
      int v = wbase[lane][e], s = v;
      #pragma unroll
      for (int off=1; off<32; off<<=1){
        int n = __shfl_up_sync(0xffffffffu, s, off);
        if (lane >= off) s += n;
      }
      wbase[lane][e] = s - v;
      if (lane == 31) etot[e] = s;
    }
  }
  __syncthreads();
  if (t == 0){
    int run = 0;
    #pragma unroll
    for (int e=0;e<NEXP;e++){ starts[e] = run; run += etot[e]; }
  }
  __syncthreads();
  int base[NEXP];
  #pragma unroll
  for (int e=0;e<NEXP;e++) base[e] = starts[e] + wbase[w][e] + excl[e];
  #pragma unroll
  for (int j=0;j<32;j++){
    int e = e_loc[j];
    int pos = base[e]++;
    int r = pos - starts[e];
    g_dst_slot[i0+j] = (r < CAP) ? (e*CAP + r) : -1;
  }
}

// ---------------- fused prep: weight transpose->tiled fp16 AND token gather->tiled fp16 --
// grid (128,128,17), block 256 flat.
__global__ void prep_kernel(const float* __restrict__ x,
                            const float* __restrict__ w1,
                            const float* __restrict__ w2){
  if (blockIdx.z < 16){
#if HAS_TCGEN05
    __shared__ float tile[32][33];
    int which = blockIdx.z >= 8;
    int e = blockIdx.z & 7;
    const int K = which ? FFN : HS;
    const int N = which ? HS  : FFN;
    const int NT = N/256, KBn = K/32;
    const float* w = which ? w2 : w1;
    char* dstb = which ? (char*)g_w2t : (char*)g_w1t;
    int n0 = blockIdx.x*32, k0 = blockIdx.y*32;
    if (n0 >= N || k0 >= K) return;
    int tx = threadIdx.x & 31, ty = threadIdx.x >> 5;   // 32 x 8
    const float* in = w + (size_t)e*K*N;
    #pragma unroll
    for (int r=0;r<4;r++)
      tile[ty+8*r][tx] = in[(size_t)(k0+ty+8*r)*N + n0+tx];
    __syncthreads();
    #pragma unroll
    for (int r=0;r<4;r++){
      float v = tile[tx][ty+8*r];
      int n = n0 + ty + 8*r, k = k0 + tx;
      // B block layout: [e][n/256][k/32][256 x 32 SW64] 16KB blocks
      size_t blk = ((size_t)(e*NT + (n>>8)))*KBn + (k>>5);
      uint32_t inner = sw64((uint32_t)((n & 255)*64 + (k & 31)*2));
      *(__half*)(dstb + blk*16384 + inner) = __float2half_rn(v);
    }
#endif
    return;
  }
  // ---- gather: assignment i -> slot ----
  int base2 = (blockIdx.y*gridDim.x + blockIdx.x)*2;
  int i = base2 + (threadIdx.x >> 7);
  int t128 = threadIdx.x & 127;
  int dst = g_dst_slot[i];
  if (dst < 0) return;
  const float4* src = (const float4*)(x + (size_t)(i>>1)*HS);
#if HAS_TCGEN05
  // A block layout: [e][m_tile][kb][128 x 32 SW64] 8KB blocks; HS -> 32 kb chunks
  int e = dst >> 12;               // /CAP
  int mt = (dst & 4095) >> 7;      // within-expert tile of 128
  int r  = dst & 127;
  char* ab = (char*)g_xb + (((size_t)(e*32 + mt))*32)*8192;  // kb blocks follow
  // thread t handles 16B chunk t: kb = t/4, c = t%4; elements t*8 .. t*8+7
  float4 a = src[t128*2], b = src[t128*2+1];
  union { uint4 u; __half2 h[4]; } pk;
  pk.h[0] = __floats2half2_rn(a.x, a.y);
  pk.h[1] = __floats2half2_rn(a.z, a.w);
  pk.h[2] = __floats2half2_rn(b.x, b.y);
  pk.h[3] = __floats2half2_rn(b.z, b.w);
  int kb = t128 >> 2, c = t128 & 3;
  uint32_t inner = sw64((uint32_t)(r*64 + c*16));
  *(uint4*)(ab + (size_t)kb*8192 + inner) = pk.u;
#else
  __half* xb = g_xb + (size_t)dst*HS;
  for (int j = t128; j < HS/4; j += 128){
    float4 v = src[j];
    *(__half2*)&xb[j*4]   = __floats2half2_rn(v.x, v.y);
    *(__half2*)&xb[j*4+2] = __floats2half2_rn(v.z, v.w);
  }
#endif
}

// ---------------- HMMA-path weight convert fp32 -> fp16 ([E][K][N]) --------
__global__ void split_w_kernel(const float* __restrict__ w, int which){
#if !HAS_TCGEN05
  __half* dst = which ? g_w2 : g_w1;
  size_t i = (size_t)blockIdx.x*blockDim.x + threadIdx.x;
  const size_t n4 = (size_t)NEXP*HS*FFN/4;
  if (i >= n4) return;
  float4 v = ((const float4*)w)[i];
  *(__half2*)&dst[i*4]   = __floats2half2_rn(v.x, v.y);
  *(__half2*)&dst[i*4+2] = __floats2half2_rn(v.z, v.w);
#endif
}

// =====================================================================
// PATH A: tcgen05 fp16 GEMM, tile 128x256, K-chunk 32, cp.async.bulk feed
// 4-stage ring of (A 8KB | B 16KB) = 24KB; warp-specialized loader/MMA.
// 2 CTAs/SM (99KB smem, 256 TMEM cols each).
// =====================================================================
#define STAGEB 24576
#define GSMEM (4*STAGEB + 1024)

template<int PHASE>
__global__ void __launch_bounds__(256,2) gemm_tc_kernel(){
#if HAS_TCGEN05
  constexpr int Kdim = (PHASE==1) ? HS  : FFN;
  constexpr int Ndim = (PHASE==1) ? FFN : HS;
  constexpr int NKB  = Kdim/32;
  constexpr int NT   = Ndim/256;
  const char* A_g = (const char*)((PHASE==1) ? g_xb  : g_h);
  const char* B_g = (const char*)((PHASE==1) ? g_w1t : g_w2t);

  extern __shared__ char dyn[];
  __shared__ uint64_t s_mbar[8];     // [0..3] full, [4..7] mma-done
  __shared__ uint32_t s_tptr;
  uint32_t sbase = (smem_addr32(dyn) + 1023u) & ~1023u;

  const int tid = threadIdx.x;
  const int wid = tid >> 5, lane = tid & 31;
  const int e = blockIdx.z, bx = blockIdx.x, by = blockIdx.y;
  const size_t Ablk = ((size_t)(e*32 + by))*NKB;
  const size_t Bblk = ((size_t)(e*NT + bx))*NKB;

  uint32_t fullb[4], mmab[4];
  #pragma unroll
  for (int s=0;s<4;s++){ fullb[s]=smem_addr32(&s_mbar[s]); mmab[s]=smem_addr32(&s_mbar[4+s]); }

  if (wid == 0) tcg_alloc(smem_addr32(&s_tptr), 256);
  if (tid == 0){
    #pragma unroll
    for (int s=0;s<4;s++){ mbar_init(fullb[s],1); mbar_init(mmab[s],1); }
  }
  __syncthreads();
  const uint32_t tmem = s_tptr;
  const uint32_t idesc = (1u<<4) | ((256u>>3)<<17) | ((128u>>4)<<24);

  if (wid == 1 && elect_one()){
    // ---- loader thread ----
    #pragma unroll
    for (int s=0;s<4;s++){
      uint32_t st = sbase + s*STAGEB;
      mbar_expect_tx(fullb[s], STAGEB);
      bulkcp(st,        A_g + (Ablk + s)*8192,  8192,  fullb[s]);
      bulkcp(st + 8192, B_g + (Bblk + s)*16384, 16384, fullb[s]);
    }
    int phm[4] = {0,0,0,0};
    for (int s = 4; s < NKB; s++){
      int pb = s & 3;
      mbar_wait(mmab[pb], phm[pb]); phm[pb] ^= 1;   // mma(s-4) done -> buffer free
      uint32_t st = sbase + pb*STAGEB;
      mbar_expect_tx(fullb[pb], STAGEB);
      bulkcp(st,        A_g + (Ablk + s)*8192,  8192,  fullb[pb]);
      bulkcp(st + 8192, B_g + (Bblk + s)*16384, 16384, fullb[pb]);
    }
  } else if (wid == 0 && elect_one()){
    // ---- MMA thread ----
    for (int kb = 0; kb < NKB; kb++){
      int buf = kb & 3;
      mbar_wait(fullb[buf], (kb>>2)&1);
      uint32_t st = sbase + buf*STAGEB;
      uint64_t dA = make_desc_sw64(st);
      uint64_t dB = make_desc_sw64(st + 8192);
      #pragma unroll
      for (int ks=0; ks<2; ks++)
        mma_f16_ss(tmem, dA + ks*2, dB + ks*2, idesc, (kb==0 && ks==0) ? 0u : 1u);
      tcg_commit(mmab[buf]);
    }
    // final commit covers all prior MMAs; buf (NKB-1)&3 = 3, wait count NKB/4 -> parity (NKB/4-1)&1
    mbar_wait(mmab[(NKB-1)&3], ((NKB/4)-1)&1);
  }
  __syncthreads();
  tcg_fence_after();

  // ---- epilogue: 8 warps; row = (wid&3)*32+lane, col half = (wid>>2)*128 ----
  {
    const int half = wid >> 2;
    const int r = (wid & 3)*32 + lane;
    #pragma unroll
    for (int ch=0; ch<4; ch++){
      uint32_t rg[32];
      ldtm32(rg, tmem + half*128 + ch*32);
      tcg_wait_ld();
      if constexpr (PHASE==1){
        // write gelu(h) into phase-2 A-tile layout: [e][by][kb2][128x32 SW64]
        int kb2 = bx*8 + half*4 + ch;           // (bx*256)/32 + ...
        char* dst = (char*)g_h + (((size_t)(e*32 + by))*(FFN/32) + kb2)*8192;
        uint32_t hp[16];
        #pragma unroll
        for (int j=0;j<32;j+=2){
          float g0 = gelu_fast(__uint_as_float(rg[j]));
          float g1 = gelu_fast(__uint_as_float(rg[j+1]));
          uint32_t p;
          asm("cvt.rn.f16x2.f32 %0, %1, %2;" : "=r"(p) : "f"(g1), "f"(g0));
          hp[j>>1] = p;
        }
        #pragma unroll
        for (int i=0;i<4;i++){
          uint32_t inner = sw64((uint32_t)(r*64 + i*16));
          *(uint4*)(dst + inner) = make_uint4(hp[i*4],hp[i*4+1],hp[i*4+2],hp[i*4+3]);
        }
      } else {
        int nc = bx*256 + half*128 + ch*32;
        size_t o = ((size_t)e*CAP + by*128 + r)*HS + nc;
        #pragma unroll
        for (int j=0;j<32;j+=4){
          *(float4*)&g_y[o+j] = make_float4(__uint_as_float(rg[j]),  __uint_as_float(rg[j+1]),
                                            __uint_as_float(rg[j+2]),__uint_as_float(rg[j+3]));
        }
      }
    }
  }
  __syncthreads();
  if (wid == 0){
    tcg_relinquish();
    tcg_dealloc(tmem, 256);
  }
#endif
}

// =====================================================================
// PATH B: HMMA mma.sync fp16 grouped GEMM (fallback, row-major layouts)
// =====================================================================
#define HSMEM (2*9472*2)
template<int PHASE>
__global__ void __launch_bounds__(512,1) gemm_split_kernel(){
#if !HAS_TCGEN05
  constexpr int K  = (PHASE==1) ? HS  : FFN;
  constexpr int N  = (PHASE==1) ? FFN : HS;
  constexpr int KB = K/32;
  const __half* __restrict__ A_g = (PHASE==1) ? g_xb : g_h;
  const __half* __restrict__ B_g = (PHASE==1) ? g_w1 : g_w2;

  extern __shared__ __align__(16) __half sm[];

  const int e  = blockIdx.z;
  const int m0 = blockIdx.y * 128;
  const int n0 = blockIdx.x * 128;
  const size_t Abase = (size_t)e*CAP*K;
  const size_t Bbase = (size_t)e*K*N;
  const size_t Cbase = (size_t)e*CAP*N;

  const int tid = threadIdx.x;
  const int warp = tid >> 5, lane = tid & 31;
  const int wm = warp >> 2, wn = warp & 3;
  const int ar = tid >> 2,  ac = (tid & 3)  * 8;
  const int br = tid >> 4,  bc = (tid & 15) * 8;

  float acc[2][4][4];
  #pragma unroll
  for (int i=0;i<2;i++)
    #pragma unroll
    for (int j=0;j<4;j++)
      #pragma unroll
      for (int k=0;k<4;k++) acc[i][j][k]=0.f;

  {
    __half* s = sm;
    cp16s(smem_addr32(s +        ar*40 + ac), A_g + Abase + (size_t)(m0+ar)*K + ac);
    cp16s(smem_addr32(s + 5120 + br*136 + bc), B_g + Bbase + (size_t)br*N + n0 + bc);
    cp_commit();
  }
  for (int kb=0; kb<KB; kb++){
    if (kb+1 < KB){
      const int k0 = (kb+1)*32;
      __half* s = sm + ((kb+1)&1)*9472;
      cp16s(smem_addr32(s +        ar*40 + ac), A_g + Abase + (size_t)(m0+ar)*K + k0 + ac);
      cp16s(smem_addr32(s + 5120 + br*136 + bc), B_g + Bbase + (size_t)(k0+br)*N + n0 + bc);
      cp_commit();
      cp_wait<1>();
    } else {
      cp_wait<0>();
    }
    __syncthreads();
    const __half* s = sm + (kb&1)*9472;
    #pragma unroll
    for (int ks=0; ks<2; ks++){
      uint32_t a[2][4];
      #pragma unroll
      for (int mt=0; mt<2; mt++){
        const __half* p = s + (wm*32 + mt*16 + (lane&15))*40 + ks*16 + (lane>>4)*8;
        ldsm4(a[mt], p);
      }
      uint32_t b[2][4];
      #pragma unroll
      for (int nh=0; nh<2; nh++){
        const __half* p = s + 5120 + (ks*16 + (lane&15))*136 + wn*32 + nh*16 + (lane>>4)*8;
        ldsm4t(b[nh], p);
      }
      #pragma unroll
      for (int mt=0; mt<2; mt++){
        #pragma unroll
        for (int nt=0; nt<4; nt++){
          const int nh = nt>>1, sb = (nt&1)*2;
          mma_f16_hmma(acc[mt][nt], a[mt], b[nh][sb], b[nh][sb+1]);
        }
      }
    }
    __syncthreads();
  }
  const int g = lane>>2, tg = lane&3;
  #pragma unroll
  for (int mt=0; mt<2; mt++){
    #pragma unroll
    for (int nt=0; nt<4; nt++){
      const int row = m0 + wm*32 + mt*16 + g;
      const int col = n0 + wn*32 + nt*8 + tg*2;
      float v0=acc[mt][nt][0], v1=acc[mt][nt][1], v2=acc[mt][nt][2], v3=acc[mt][nt][3];
      if constexpr (PHASE==1){
        v0=gelu_fast(v0); v1=gelu_fast(v1); v2=gelu_fast(v2); v3=gelu_fast(v3);
        size_t o  = Cbase + (size_t)row*N + col;
        size_t o2 = Cbase + (size_t)(row+8)*N + col;
        *(__half2*)&g_h[o]  = __floats2half2_rn(v0, v1);
        *(__half2*)&g_h[o2] = __floats2half2_rn(v2, v3);
      } else {
        *(float2*)&g_y[Cbase + (size_t)row*N + col]     = make_float2(v0,v1);
        *(float2*)&g_y[Cbase + (size_t)(row+8)*N + col] = make_float2(v2,v3);
      }
    }
  }
#endif
}

// ---------------- per-token weighted combine + bias ----------------
__global__ void scatter_kernel(const float* __restrict__ bias, float* __restrict__ out){
  int t = blockIdx.x;
  int s0 = g_dst_slot[2*t], s1 = g_dst_slot[2*t+1];
  float w0 = g_top_w[2*t], w1 = g_top_w[2*t+1];
  const float4* y0 = (const float4*)(g_y + (size_t)(s0 < 0 ? 0 : s0)*HS);
  const float4* y1 = (const float4*)(g_y + (size_t)(s1 < 0 ? 0 : s1)*HS);
  const float4* b4 = (const float4*)bias;
  float4* o = (float4*)(out + (size_t)t*HS);
  for (int j = threadIdx.x; j < HS/4; j += blockDim.x){
    float4 r = b4[j];
    if (s0 >= 0){ float4 v = y0[j]; r.x += w0*v.x; r.y += w0*v.y; r.z += w0*v.z; r.w += w0*v.w; }
    if (s1 >= 0){ float4 v = y1[j]; r.x += w1*v.x; r.y += w1*v.y; r.z += w1*v.z; r.w += w1*v.w; }
    o[j] = r;
  }
}

// ---------------- launcher ----------------
extern "C" void kernel_launch(void* const* d_in, const int* in_sizes, int n_in,
                              void* d_out, int out_size){
  const float* x    = (const float*)d_in[0];
  const float* wr   = (const float*)d_in[1];
  const float* w1   = (const float*)d_in[2];
  const float* w2   = (const float*)d_in[3];
  const float* bias = (const float*)d_in[4];
  float* out = (float*)d_out;

  cudaFuncSetAttribute(gemm_tc_kernel<1>, cudaFuncAttributeMaxDynamicSharedMemorySize, GSMEM);
  cudaFuncSetAttribute(gemm_tc_kernel<2>, cudaFuncAttributeMaxDynamicSharedMemorySize, GSMEM);
  cudaFuncSetAttribute(gemm_split_kernel<1>, cudaFuncAttributeMaxDynamicSharedMemorySize, HSMEM);
  cudaFuncSetAttribute(gemm_split_kernel<2>, cudaFuncAttributeMaxDynamicSharedMemorySize, HSMEM);

  // order keeps gemm_tc<1> at launch index 3 (ncu capture slot)
  router_kernel<<<T_TOK/8, 256>>>(x, wr);                             // 0
  scan_kernel<<<1, 1024>>>();                                         // 1
  prep_kernel<<<dim3(128,128,17), 256>>>(x, w1, w2);                  // 2
  gemm_tc_kernel<1><<<dim3(FFN/256, CAP/128, NEXP), 256, GSMEM>>>();  // 3 <- profiled
  // HMMA fallback (empty bodies in the sm_103a binary)
  const int n4 = NEXP*HS*FFN/4;
  split_w_kernel<<<(n4+255)/256, 256>>>(w1, 0);
  split_w_kernel<<<(n4+255)/256, 256>>>(w2, 1);
  gemm_split_kernel<1><<<dim3(FFN/128, CAP/128, NEXP), 512, HSMEM>>>();
  gemm_tc_kernel<2><<<dim3(HS/256, CAP/128, NEXP), 256, GSMEM>>>();
  gemm_split_kernel<2><<<dim3(HS/128, CAP/128, NEXP), 512, HSMEM>>>();
  scatter_kernel<<<T_TOK, 128>>>(bias, out);
}

// round 13
// speedup vs baseline: 4.2411x; 1.1705x over previous
#include <cuda_runtime.h>
#include <cuda_bf16.h>
#include <cuda_fp16.h>
#include <math.h>
#include <stdint.h>

#define T_TOK   16384
#define HS      1024
#define FFN     4096
#define NEXP    8
#define CAP     4096
#define NASSIGN (2*T_TOK)
#define SLOTS   (NEXP*CAP)

#if defined(__CUDA_ARCH_FEAT_SM103_ALL) || defined(__CUDA_ARCH_FEAT_SM100_ALL) || defined(__CUDA_ARCH_FEAT_SM101_ALL)
#define HAS_TCGEN05 1
#else
#define HAS_TCGEN05 0
#endif

// ---------------- static device scratch ----------------
// tcgen05 path layouts (pre-swizzled smem-image blocks):
//   A blocks: [e][m_tile(16)][kb][256 rows x 32 cols fp16, SW64] = 16KB each
//   B blocks: [e][n_tile]    [kb][256 rows x 32 cols fp16, SW64] = 16KB each
// fallback path uses plain row-major in the same arrays.
__device__ __half g_xb[(size_t)SLOTS*HS];
__device__ __half g_h [(size_t)SLOTS*FFN];
__device__ float  g_y [(size_t)SLOTS*HS];
__device__ __half g_w1t[(size_t)NEXP*FFN*HS];
__device__ __half g_w2t[(size_t)NEXP*HS*FFN];
__device__ __half g_w1 [(size_t)NEXP*HS*FFN];   // fallback row-major
__device__ __half g_w2 [(size_t)NEXP*FFN*HS];   // fallback row-major
__device__ int    g_top_e[NASSIGN];
__device__ float  g_top_w[NASSIGN];
__device__ int    g_dst_slot[NASSIGN];

// ---------------- helpers ----------------
__device__ __forceinline__ uint32_t smem_addr32(const void* p){
  return (uint32_t)__cvta_generic_to_shared(p);
}
__device__ __forceinline__ void cp16s(uint32_t dst, const void* src){
  asm volatile("cp.async.cg.shared.global [%0], [%1], 16;\n" :: "r"(dst), "l"(src));
}
__device__ __forceinline__ void cp_commit(){ asm volatile("cp.async.commit_group;\n"); }
template<int NW> __device__ __forceinline__ void cp_wait(){
  asm volatile("cp.async.wait_group %0;\n" :: "n"(NW));
}
__device__ __forceinline__ void ldsm4(uint32_t* r, const __half* p){
  uint32_t a = smem_addr32(p);
  asm volatile("ldmatrix.sync.aligned.m8n8.x4.shared.b16 {%0,%1,%2,%3}, [%4];\n"
    : "=r"(r[0]),"=r"(r[1]),"=r"(r[2]),"=r"(r[3]) : "r"(a));
}
__device__ __forceinline__ void ldsm4t(uint32_t* r, const __half* p){
  uint32_t a = smem_addr32(p);
  asm volatile("ldmatrix.sync.aligned.m8n8.x4.trans.shared.b16 {%0,%1,%2,%3}, [%4];\n"
    : "=r"(r[0]),"=r"(r[1]),"=r"(r[2]),"=r"(r[3]) : "r"(a));
}
__device__ __forceinline__ void mma_f16_hmma(float* c, const uint32_t* a, uint32_t b0, uint32_t b1){
  asm volatile("mma.sync.aligned.m16n8k16.row.col.f32.f16.f16.f32 "
    "{%0,%1,%2,%3}, {%4,%5,%6,%7}, {%8,%9}, {%0,%1,%2,%3};\n"
    : "+f"(c[0]),"+f"(c[1]),"+f"(c[2]),"+f"(c[3])
    : "r"(a[0]),"r"(a[1]),"r"(a[2]),"r"(a[3]), "r"(b0),"r"(b1));
}
__device__ __forceinline__ uint32_t sw64(uint32_t off){ return off ^ ((off >> 3) & 0x30); }

__device__ __forceinline__ float gelu_fast(float x){
  float t = x*x;
  float u = x*(0.7978845608f + 0.0356774081f*t);
  float th;
  asm("tanh.approx.f32 %0, %1;" : "=f"(th) : "f"(u));
  return 0.5f*__fmaf_rn(x, th, x);
}
__device__ __forceinline__ uint32_t elect_one(){
  uint32_t pred;
  asm volatile("{\n.reg .pred p;\nelect.sync _|p, 0xFFFFFFFF;\nselp.b32 %0, 1, 0, p;\n}" : "=r"(pred));
  return pred;
}
__device__ __forceinline__ void mbar_init(uint32_t a, uint32_t cnt){
  asm volatile("mbarrier.init.shared.b64 [%0], %1;" :: "r"(a), "r"(cnt) : "memory");
}
__device__ __forceinline__ void mbar_expect_tx(uint32_t a, uint32_t bytes){
  asm volatile("mbarrier.arrive.expect_tx.shared.b64 _, [%0], %1;" :: "r"(a), "r"(bytes) : "memory");
}
__device__ __forceinline__ void mbar_wait(uint32_t a, uint32_t parity){
  asm volatile("{\n.reg .pred P;\nLW%=:\nmbarrier.try_wait.parity.acquire.cta.shared::cta.b64 P, [%0], %1, 0x989680;\n@!P bra LW%=;\n}"
    :: "r"(a), "r"(parity) : "memory");
}
#if HAS_TCGEN05
__device__ __forceinline__ void bulkcp(uint32_t dst, const void* src, uint32_t bytes, uint32_t mbar){
  asm volatile("cp.async.bulk.shared::cluster.global.mbarrier::complete_tx::bytes [%0], [%1], %2, [%3];"
    :: "r"(dst), "l"(src), "r"(bytes), "r"(mbar) : "memory");
}
__device__ __forceinline__ void tcg_alloc(uint32_t dst_smem, uint32_t ncols){
  asm volatile("tcgen05.alloc.cta_group::1.sync.aligned.shared::cta.b32 [%0], %1;" :: "r"(dst_smem), "r"(ncols) : "memory");
}
__device__ __forceinline__ void tcg_dealloc(uint32_t tmem, uint32_t ncols){
  asm volatile("tcgen05.dealloc.cta_group::1.sync.aligned.b32 %0, %1;" :: "r"(tmem), "r"(ncols));
}
__device__ __forceinline__ void tcg_relinquish(){
  asm volatile("tcgen05.relinquish_alloc_permit.cta_group::1.sync.aligned;");
}
__device__ __forceinline__ void tcg_commit(uint32_t mbar){
  asm volatile("tcgen05.commit.cta_group::1.mbarrier::arrive::one.shared::cluster.b64 [%0];" :: "r"(mbar) : "memory");
}
__device__ __forceinline__ void tcg_fence_after(){
  asm volatile("tcgen05.fence::after_thread_sync;" ::: "memory");
}
__device__ __forceinline__ void mma_f16_ss(uint32_t d, uint64_t a, uint64_t b, uint32_t idesc, uint32_t en){
  asm volatile("{\n.reg .pred p;\nsetp.ne.u32 p, %4, 0;\n"
    "tcgen05.mma.cta_group::1.kind::f16 [%0], %1, %2, %3, {%5,%5,%5,%5}, p;\n}"
    :: "r"(d), "l"(a), "l"(b), "r"(idesc), "r"(en), "r"(0u) : "memory");
}
__device__ __forceinline__ void ldtm32(uint32_t* r, uint32_t addr){
  asm volatile("tcgen05.ld.sync.aligned.32x32b.x32.b32 "
    "{%0,%1,%2,%3,%4,%5,%6,%7,%8,%9,%10,%11,%12,%13,%14,%15,"
    "%16,%17,%18,%19,%20,%21,%22,%23,%24,%25,%26,%27,%28,%29,%30,%31}, [%32];"
    : "=r"(r[0]),"=r"(r[1]),"=r"(r[2]),"=r"(r[3]),"=r"(r[4]),"=r"(r[5]),"=r"(r[6]),"=r"(r[7]),
      "=r"(r[8]),"=r"(r[9]),"=r"(r[10]),"=r"(r[11]),"=r"(r[12]),"=r"(r[13]),"=r"(r[14]),"=r"(r[15]),
      "=r"(r[16]),"=r"(r[17]),"=r"(r[18]),"=r"(r[19]),"=r"(r[20]),"=r"(r[21]),"=r"(r[22]),"=r"(r[23]),
      "=r"(r[24]),"=r"(r[25]),"=r"(r[26]),"=r"(r[27]),"=r"(r[28]),"=r"(r[29]),"=r"(r[30]),"=r"(r[31])
    : "r"(addr));
}
__device__ __forceinline__ void tcg_wait_ld(){
  asm volatile("tcgen05.wait::ld.sync.aligned;" ::: "memory");
}
// SW64 K-major smem descriptor: layout=4, SBO=32 (8 rows x 64B atom), LBO=1
__device__ __forceinline__ uint64_t make_desc_sw64(uint32_t base_addr){
  const uint64_t BASE = (uint64_t(4) << 61) | (uint64_t(1) << 46) | (uint64_t(32) << 32) | (uint64_t(1) << 16);
  return BASE | ((uint64_t)(base_addr >> 4) & 0x3FFF);
}
#endif

// ---------------- router: fp64 logits + softmax + top-2 ----------------
__global__ void router_kernel(const float* __restrict__ x, const float* __restrict__ wr){
  int widx = (blockIdx.x * blockDim.x + threadIdx.x) >> 5;
  int lane = threadIdx.x & 31;
  if (widx >= T_TOK) return;
  const float* xr = x + (size_t)widx * HS;
  double acc[NEXP];
  #pragma unroll
  for (int e=0;e<NEXP;e++) acc[e]=0.0;
  for (int h = lane; h < HS; h += 32){
    double xv = (double)xr[h];
    const float* wrow = wr + h*NEXP;
    #pragma unroll
    for (int e=0;e<NEXP;e++) acc[e] += xv * (double)wrow[e];
  }
  #pragma unroll
  for (int off=16; off; off>>=1){
    #pragma unroll
    for (int e=0;e<NEXP;e++) acc[e] += __shfl_xor_sync(0xffffffffu, acc[e], off);
  }
  if (lane == 0){
    double m = acc[0];
    #pragma unroll
    for (int e=1;e<NEXP;e++) m = fmax(m, acc[e]);
    double ex[NEXP], s = 0.0;
    #pragma unroll
    for (int e=0;e<NEXP;e++){ ex[e] = exp(acc[e]-m); s += ex[e]; }
    int e0 = 0; double b0 = acc[0];
    #pragma unroll
    for (int e=1;e<NEXP;e++) if (acc[e] > b0){ b0 = acc[e]; e0 = e; }
    int e1 = (e0==0) ? 1 : 0; double b1 = acc[e1];
    #pragma unroll
    for (int e=0;e<NEXP;e++) if (e != e0 && acc[e] > b1){ b1 = acc[e]; e1 = e; }
    g_top_e[2*widx]   = e0;
    g_top_e[2*widx+1] = e1;
    g_top_w[2*widx]   = (float)(ex[e0]/s);
    g_top_w[2*widx+1] = (float)(ex[e1]/s);
  }
}

// ---------------- stable counting sort + capacity (hierarchical scan) ----------------
__global__ void __launch_bounds__(1024,1) scan_kernel(){
  __shared__ int wbase[32][NEXP];
  __shared__ int etot[NEXP];
  __shared__ int starts[NEXP];
  int t = threadIdx.x, lane = t & 31, w = t >> 5;
  const int i0 = t * 32;
  int e_loc[32];
  int cnt[NEXP];
  #pragma unroll
  for (int e=0;e<NEXP;e++) cnt[e]=0;
  #pragma unroll
  for (int j=0;j<32;j++){ e_loc[j] = g_top_e[i0+j]; cnt[e_loc[j]]++; }
  int excl[NEXP];
  #pragma unroll
  for (int e=0;e<NEXP;e++){
    int v = cnt[e], s = v;
    #pragma unroll
    for (int off=1; off<32; off<<=1){
      int n = __shfl_up_sync(0xffffffffu, s, off);
      if (lane >= off) s += n;
    }
    excl[e] = s - v;
    if (lane == 31) wbase[w][e] = s;
  }
  __syncthreads();
  if (w == 0){
    #pragma unroll
    for (int e=0;e<NEXP;e++){
      int v = wbase[lane][e], s = v;
      #pragma unroll
      for (int off=1; off<32; off<<=1){
        int n = __shfl_up_sync(0xffffffffu, s, off);
        if (lane >= off) s += n;
      }
      wbase[lane][e] = s - v;
      if (lane == 31) etot[e] = s;
    }
  }
  __syncthreads();
  if (t == 0){
    int run = 0;
    #pragma unroll
    for (int e=0;e<NEXP;e++){ starts[e] = run; run += etot[e]; }
  }
  __syncthreads();
  int base[NEXP];
  #pragma unroll
  for (int e=0;e<NEXP;e++) base[e] = starts[e] + wbase[w][e] + excl[e];
  #pragma unroll
  for (int j=0;j<32;j++){
    int e = e_loc[j];
    int pos = base[e]++;
    int r = pos - starts[e];
    g_dst_slot[i0+j] = (r < CAP) ? (e*CAP + r) : -1;
  }
}

// ---------------- fused prep, EXACT grid (128,32,20), block 256 ----------------
//   z in [0,8)  : w1 transpose, e=z,   x=n-block(128), y=k-block(32)
//   z in [8,16) : w2 transpose, e=z-8, x=k-block(128), y=n-block(32)
//   z in [16,20): gather, bid=(z-16)*4096 + y*128 + x, 2 assignments/block
__global__ void prep_kernel(const float* __restrict__ x,
                            const float* __restrict__ w1,
                            const float* __restrict__ w2){
  if (blockIdx.z < 16){
#if HAS_TCGEN05
    __shared__ float tile[32][33];
    int which = blockIdx.z >= 8;
    int e = blockIdx.z & 7;
    const int K = which ? FFN : HS;
    const int N = which ? HS  : FFN;
    const int NT = N/256, KBn = K/32;
    const float* w = which ? w2 : w1;
    char* dstb = which ? (char*)g_w2t : (char*)g_w1t;
    int nb = which ? blockIdx.y : blockIdx.x;
    int kb = which ? blockIdx.x : blockIdx.y;
    int n0 = nb*32, k0 = kb*32;
    int tx = threadIdx.x & 31, ty = threadIdx.x >> 5;   // 32 x 8
    const float* in = w + (size_t)e*K*N;
    #pragma unroll
    for (int r=0;r<4;r++)
      tile[ty+8*r][tx] = in[(size_t)(k0+ty+8*r)*N + n0+tx];
    __syncthreads();
    #pragma unroll
    for (int r=0;r<4;r++){
      float v = tile[tx][ty+8*r];
      int n = n0 + ty + 8*r, k = k0 + tx;
      size_t blk = ((size_t)(e*NT + (n>>8)))*KBn + (k>>5);
      uint32_t inner = sw64((uint32_t)((n & 255)*64 + (k & 31)*2));
      *(__half*)(dstb + blk*16384 + inner) = __float2half_rn(v);
    }
#endif
    return;
  }
  // ---- gather ----
  int bid = (blockIdx.z - 16)*4096 + blockIdx.y*128 + blockIdx.x;
  int i = bid*2 + (threadIdx.x >> 7);
  int t128 = threadIdx.x & 127;
  int dst = g_dst_slot[i];
  if (dst < 0) return;
  const float4* src = (const float4*)(x + (size_t)(i>>1)*HS);
#if HAS_TCGEN05
  // A block layout: [e][mt(16)][kb(32)][256 x 32 SW64] 16KB blocks
  int e  = dst >> 12;
  int mt = (dst >> 8) & 15;
  int r  = dst & 255;
  char* ab = (char*)g_xb + (((size_t)(e*16 + mt))*32)*16384;
  float4 a = src[t128*2], b = src[t128*2+1];
  union { uint4 u; __half2 h[4]; } pk;
  pk.h[0] = __floats2half2_rn(a.x, a.y);
  pk.h[1] = __floats2half2_rn(a.z, a.w);
  pk.h[2] = __floats2half2_rn(b.x, b.y);
  pk.h[3] = __floats2half2_rn(b.z, b.w);
  int kb = t128 >> 2, c = t128 & 3;
  uint32_t inner = sw64((uint32_t)(r*64 + c*16));
  *(uint4*)(ab + (size_t)kb*16384 + inner) = pk.u;
#else
  __half* xb = g_xb + (size_t)dst*HS;
  for (int j = t128; j < HS/4; j += 128){
    float4 v = src[j];
    *(__half2*)&xb[j*4]   = __floats2half2_rn(v.x, v.y);
    *(__half2*)&xb[j*4+2] = __floats2half2_rn(v.z, v.w);
  }
#endif
}

// ---------------- HMMA-path weight convert fp32 -> fp16 ([E][K][N]) --------
__global__ void split_w_kernel(const float* __restrict__ w, int which){
#if !HAS_TCGEN05
  __half* dst = which ? g_w2 : g_w1;
  size_t i = (size_t)blockIdx.x*blockDim.x + threadIdx.x;
  const size_t n4 = (size_t)NEXP*HS*FFN/4;
  if (i >= n4) return;
  float4 v = ((const float4*)w)[i];
  *(__half2*)&dst[i*4]   = __floats2half2_rn(v.x, v.y);
  *(__half2*)&dst[i*4+2] = __floats2half2_rn(v.z, v.w);
#endif
}

// =====================================================================
// PATH A: tcgen05 fp16 GEMM, tile 256x256 (two M=128 halves, 512 TMEM cols),
// K-chunk 32, cp.async.bulk feed, 4-stage ring of (A 16KB | B 16KB) = 32KB.
// 1 CTA/SM. Warp-specialized loader/MMA threads.
// =====================================================================
#define STAGEB 32768
#define GSMEM (4*STAGEB + 1024)

template<int PHASE>
__global__ void __launch_bounds__(256,1) gemm_tc_kernel(){
#if HAS_TCGEN05
  constexpr int Kdim = (PHASE==1) ? HS  : FFN;
  constexpr int Ndim = (PHASE==1) ? FFN : HS;
  constexpr int NKB  = Kdim/32;
  constexpr int NT   = Ndim/256;
  const char* A_g = (const char*)((PHASE==1) ? g_xb  : g_h);
  const char* B_g = (const char*)((PHASE==1) ? g_w1t : g_w2t);

  extern __shared__ char dyn[];
  __shared__ uint64_t s_mbar[8];     // [0..3] full, [4..7] mma-done
  __shared__ uint32_t s_tptr;
  uint32_t sbase = (smem_addr32(dyn) + 1023u) & ~1023u;

  const int tid = threadIdx.x;
  const int wid = tid >> 5, lane = tid & 31;
  const int e = blockIdx.z, bx = blockIdx.x, by = blockIdx.y;
  const size_t Ablk = ((size_t)(e*16 + by))*NKB;
  const size_t Bblk = ((size_t)(e*NT + bx))*NKB;

  uint32_t fullb[4], mmab[4];
  #pragma unroll
  for (int s=0;s<4;s++){ fullb[s]=smem_addr32(&s_mbar[s]); mmab[s]=smem_addr32(&s_mbar[4+s]); }

  if (wid == 0) tcg_alloc(smem_addr32(&s_tptr), 512);
  if (tid == 0){
    #pragma unroll
    for (int s=0;s<4;s++){ mbar_init(fullb[s],1); mbar_init(mmab[s],1); }
  }
  __syncthreads();
  const uint32_t tmem = s_tptr;
  const uint32_t idesc = (1u<<4) | ((256u>>3)<<17) | ((128u>>4)<<24);

  if (wid == 1 && elect_one()){
    // ---- loader thread ----
    #pragma unroll
    for (int s=0;s<4;s++){
      uint32_t st = sbase + s*STAGEB;
      mbar_expect_tx(fullb[s], STAGEB);
      bulkcp(st,         A_g + (Ablk + s)*16384, 16384, fullb[s]);
      bulkcp(st + 16384, B_g + (Bblk + s)*16384, 16384, fullb[s]);
    }
    int phm[4] = {0,0,0,0};
    for (int s = 4; s < NKB; s++){
      int pb = s & 3;
      mbar_wait(mmab[pb], phm[pb]); phm[pb] ^= 1;   // mma(s-4) done -> buffer free
      uint32_t st = sbase + pb*STAGEB;
      mbar_expect_tx(fullb[pb], STAGEB);
      bulkcp(st,         A_g + (Ablk + s)*16384, 16384, fullb[pb]);
      bulkcp(st + 16384, B_g + (Bblk + s)*16384, 16384, fullb[pb]);
    }
  } else if (wid == 0 && elect_one()){
    // ---- MMA thread ----
    for (int kb = 0; kb < NKB; kb++){
      int buf = kb & 3;
      mbar_wait(fullb[buf], (kb>>2)&1);
      uint32_t st = sbase + buf*STAGEB;
      uint64_t dB = make_desc_sw64(st + 16384);
      #pragma unroll
      for (int half=0; half<2; half++){
        uint64_t dA = make_desc_sw64(st + half*8192);   // rows 128-255 start at +8KB
        uint32_t d  = tmem + half*256;
        #pragma unroll
        for (int ks=0; ks<2; ks++)
          mma_f16_ss(d, dA + ks*2, dB + ks*2, idesc, (kb==0 && ks==0) ? 0u : 1u);
      }
      tcg_commit(mmab[buf]);
    }
    mbar_wait(mmab[(NKB-1)&3], ((NKB/4)-1)&1);
  }
  __syncthreads();
  tcg_fence_after();

  // ---- epilogue: warp w -> tile rows (w>>2)*128 + (w&3)*32 + lane; 8 col-chunks ----
  {
    const int half = wid >> 2;
    const int r = half*128 + (wid & 3)*32 + lane;    // row within 256-row tile
    #pragma unroll
    for (int ch=0; ch<8; ch++){
      uint32_t rg[32];
      ldtm32(rg, tmem + half*256 + ch*32);
      tcg_wait_ld();
      if constexpr (PHASE==1){
        // write gelu(h) into phase-2 A layout: [e][by][kb2][256x32 SW64]
        int kb2 = bx*8 + ch;
        char* dst = (char*)g_h + (((size_t)(e*16 + by))*(FFN/32) + kb2)*16384;
        uint32_t hp[16];
        #pragma unroll
        for (int j=0;j<32;j+=2){
          float g0 = gelu_fast(__uint_as_float(rg[j]));
          float g1 = gelu_fast(__uint_as_float(rg[j+1]));
          uint32_t p;
          asm("cvt.rn.f16x2.f32 %0, %1, %2;" : "=r"(p) : "f"(g1), "f"(g0));
          hp[j>>1] = p;
        }
        #pragma unroll
        for (int i=0;i<4;i++){
          uint32_t inner = sw64((uint32_t)(r*64 + i*16));
          *(uint4*)(dst + inner) = make_uint4(hp[i*4],hp[i*4+1],hp[i*4+2],hp[i*4+3]);
        }
      } else {
        int nc = bx*256 + ch*32;
        size_t o = ((size_t)e*CAP + by*256 + r)*HS + nc;
        #pragma unroll
        for (int j=0;j<32;j+=4){
          *(float4*)&g_y[o+j] = make_float4(__uint_as_float(rg[j]),  __uint_as_float(rg[j+1]),
                                            __uint_as_float(rg[j+2]),__uint_as_float(rg[j+3]));
        }
      }
    }
  }
  __syncthreads();
  if (wid == 0){
    tcg_relinquish();
    tcg_dealloc(tmem, 512);
  }
#endif
}

// =====================================================================
// PATH B: HMMA mma.sync fp16 grouped GEMM (fallback, row-major layouts)
// =====================================================================
#define HSMEM (2*9472*2)
template<int PHASE>
__global__ void __launch_bounds__(512,1) gemm_split_kernel(){
#if !HAS_TCGEN05
  constexpr int K  = (PHASE==1) ? HS  : FFN;
  constexpr int N  = (PHASE==1) ? FFN : HS;
  constexpr int KB = K/32;
  const __half* __restrict__ A_g = (PHASE==1) ? g_xb : g_h;
  const __half* __restrict__ B_g = (PHASE==1) ? g_w1 : g_w2;

  extern __shared__ __align__(16) __half sm[];

  const int e  = blockIdx.z;
  const int m0 = blockIdx.y * 128;
  const int n0 = blockIdx.x * 128;
  const size_t Abase = (size_t)e*CAP*K;
  const size_t Bbase = (size_t)e*K*N;
  const size_t Cbase = (size_t)e*CAP*N;

  const int tid = threadIdx.x;
  const int warp = tid >> 5, lane = tid & 31;
  const int wm = warp >> 2, wn = warp & 3;
  const int ar = tid >> 2,  ac = (tid & 3)  * 8;
  const int br = tid >> 4,  bc = (tid & 15) * 8;

  float acc[2][4][4];
  #pragma unroll
  for (int i=0;i<2;i++)
    #pragma unroll
    for (int j=0;j<4;j++)
      #pragma unroll
      for (int k=0;k<4;k++) acc[i][j][k]=0.f;

  {
    __half* s = sm;
    cp16s(smem_addr32(s +        ar*40 + ac), A_g + Abase + (size_t)(m0+ar)*K + ac);
    cp16s(smem_addr32(s + 5120 + br*136 + bc), B_g + Bbase + (size_t)br*N + n0 + bc);
    cp_commit();
  }
  for (int kb=0; kb<KB; kb++){
    if (kb+1 < KB){
      const int k0 = (kb+1)*32;
      __half* s = sm + ((kb+1)&1)*9472;
      cp16s(smem_addr32(s +        ar*40 + ac), A_g + Abase + (size_t)(m0+ar)*K + k0 + ac);
      cp16s(smem_addr32(s + 5120 + br*136 + bc), B_g + Bbase + (size_t)(k0+br)*N + n0 + bc);
      cp_commit();
      cp_wait<1>();
    } else {
      cp_wait<0>();
    }
    __syncthreads();
    const __half* s = sm + (kb&1)*9472;
    #pragma unroll
    for (int ks=0; ks<2; ks++){
      uint32_t a[2][4];
      #pragma unroll
      for (int mt=0; mt<2; mt++){
        const __half* p = s + (wm*32 + mt*16 + (lane&15))*40 + ks*16 + (lane>>4)*8;
        ldsm4(a[mt], p);
      }
      uint32_t b[2][4];
      #pragma unroll
      for (int nh=0; nh<2; nh++){
        const __half* p = s + 5120 + (ks*16 + (lane&15))*136 + wn*32 + nh*16 + (lane>>4)*8;
        ldsm4t(b[nh], p);
      }
      #pragma unroll
      for (int mt=0; mt<2; mt++){
        #pragma unroll
        for (int nt=0; nt<4; nt++){
          const int nh = nt>>1, sb = (nt&1)*2;
          mma_f16_hmma(acc[mt][nt], a[mt], b[nh][sb], b[nh][sb+1]);
        }
      }
    }
    __syncthreads();
  }
  const int g = lane>>2, tg = lane&3;
  #pragma unroll
  for (int mt=0; mt<2; mt++){
    #pragma unroll
    for (int nt=0; nt<4; nt++){
      const int row = m0 + wm*32 + mt*16 + g;
      const int col = n0 + wn*32 + nt*8 + tg*2;
      float v0=acc[mt][nt][0], v1=acc[mt][nt][1], v2=acc[mt][nt][2], v3=acc[mt][nt][3];
      if constexpr (PHASE==1){
        v0=gelu_fast(v0); v1=gelu_fast(v1); v2=gelu_fast(v2); v3=gelu_fast(v3);
        size_t o  = Cbase + (size_t)row*N + col;
        size_t o2 = Cbase + (size_t)(row+8)*N + col;
        *(__half2*)&g_h[o]  = __floats2half2_rn(v0, v1);
        *(__half2*)&g_h[o2] = __floats2half2_rn(v2, v3);
      } else {
        *(float2*)&g_y[Cbase + (size_t)row*N + col]     = make_float2(v0,v1);
        *(float2*)&g_y[Cbase + (size_t)(row+8)*N + col] = make_float2(v2,v3);
      }
    }
  }
#endif
}

// ---------------- per-token weighted combine + bias ----------------
__global__ void scatter_kernel(const float* __restrict__ bias, float* __restrict__ out){
  int t = blockIdx.x;
  int s0 = g_dst_slot[2*t], s1 = g_dst_slot[2*t+1];
  float w0 = g_top_w[2*t], w1 = g_top_w[2*t+1];
  const float4* y0 = (const float4*)(g_y + (size_t)(s0 < 0 ? 0 : s0)*HS);
  const float4* y1 = (const float4*)(g_y + (size_t)(s1 < 0 ? 0 : s1)*HS);
  const float4* b4 = (const float4*)bias;
  float4* o = (float4*)(out + (size_t)t*HS);
  for (int j = threadIdx.x; j < HS/4; j += blockDim.x){
    float4 r = b4[j];
    if (s0 >= 0){ float4 v = y0[j]; r.x += w0*v.x; r.y += w0*v.y; r.z += w0*v.z; r.w += w0*v.w; }
    if (s1 >= 0){ float4 v = y1[j]; r.x += w1*v.x; r.y += w1*v.y; r.z += w1*v.z; r.w += w1*v.w; }
    o[j] = r;
  }
}

// ---------------- launcher ----------------
extern "C" void kernel_launch(void* const* d_in, const int* in_sizes, int n_in,
                              void* d_out, int out_size){
  const float* x    = (const float*)d_in[0];
  const float* wr   = (const float*)d_in[1];
  const float* w1   = (const float*)d_in[2];
  const float* w2   = (const float*)d_in[3];
  const float* bias = (const float*)d_in[4];
  float* out = (float*)d_out;

  cudaFuncSetAttribute(gemm_tc_kernel<1>, cudaFuncAttributeMaxDynamicSharedMemorySize, GSMEM);
  cudaFuncSetAttribute(gemm_tc_kernel<2>, cudaFuncAttributeMaxDynamicSharedMemorySize, GSMEM);
  cudaFuncSetAttribute(gemm_split_kernel<1>, cudaFuncAttributeMaxDynamicSharedMemorySize, HSMEM);
  cudaFuncSetAttribute(gemm_split_kernel<2>, cudaFuncAttributeMaxDynamicSharedMemorySize, HSMEM);

  // Which path is compiled into the loaded binary? The tcgen05 kernel has ~120
  // regs when real, <16 when its body compiled empty. Host-side query is
  // deterministic and graph-capture-safe.
  cudaFuncAttributes fa{};
  cudaFuncGetAttributes(&fa, gemm_tc_kernel<1>);
  const bool tc = fa.numRegs > 32;

  router_kernel<<<T_TOK/8, 256>>>(x, wr);                               // 0
  scan_kernel<<<1, 1024>>>();                                           // 1
  prep_kernel<<<dim3(128,32,20), 256>>>(x, w1, w2);                     // 2
  if (tc){
    gemm_tc_kernel<1><<<dim3(FFN/256, CAP/256, NEXP), 256, GSMEM>>>();  // 3 <- profiled
    gemm_tc_kernel<2><<<dim3(HS/256,  CAP/256, NEXP), 256, GSMEM>>>();
  } else {
    const int n4 = NEXP*HS*FFN/4;
    split_w_kernel<<<(n4+255)/256, 256>>>(w1, 0);
    split_w_kernel<<<(n4+255)/256, 256>>>(w2, 1);
    gemm_split_kernel<1><<<dim3(FFN/128, CAP/128, NEXP), 512, HSMEM>>>();
    gemm_split_kernel<2><<<dim3(HS/128,  CAP/128, NEXP), 512, HSMEM>>>();
  }
  scatter_kernel<<<T_TOK, 128>>>(bias, out);
}

// round 16
// speedup vs baseline: 7.7709x; 1.8323x over previous
#include <cuda_runtime.h>
#include <cuda_bf16.h>
#include <cuda_fp16.h>
#include <math.h>
#include <stdint.h>

#define T_TOK   16384
#define HS      1024
#define FFN     4096
#define NEXP    8
#define CAP     4096
#define NASSIGN (2*T_TOK)
#define SLOTS   (NEXP*CAP)

#if defined(__CUDA_ARCH_FEAT_SM103_ALL) || defined(__CUDA_ARCH_FEAT_SM100_ALL) || defined(__CUDA_ARCH_FEAT_SM101_ALL)
#define HAS_TCGEN05 1
#else
#define HAS_TCGEN05 0
#endif

// ---------------- static device scratch ----------------
// tcgen05 path layouts (pre-swizzled smem-image blocks):
//   A blocks: [e][m_tile(16)][kb][256 rows x 32 cols fp16, SW64] = 16KB each
//   B blocks: [e][n_tile]    [kb][256 rows x 32 cols fp16, SW64] = 16KB each
__device__ __half g_xb[(size_t)SLOTS*HS];
__device__ __half g_h [(size_t)SLOTS*FFN];
__device__ float  g_y [(size_t)SLOTS*HS];
__device__ __half g_w1t[(size_t)NEXP*FFN*HS];
__device__ __half g_w2t[(size_t)NEXP*HS*FFN];
__device__ __half g_w1 [(size_t)NEXP*HS*FFN];   // fallback row-major
__device__ __half g_w2 [(size_t)NEXP*FFN*HS];   // fallback row-major
__device__ int    g_top_e[NASSIGN];
__device__ float  g_top_w[NASSIGN];
__device__ int    g_dst_slot[NASSIGN];

// ---------------- helpers ----------------
__device__ __forceinline__ uint32_t smem_addr32(const void* p){
  return (uint32_t)__cvta_generic_to_shared(p);
}
__device__ __forceinline__ void cp16s(uint32_t dst, const void* src){
  asm volatile("cp.async.cg.shared.global [%0], [%1], 16;\n" :: "r"(dst), "l"(src));
}
__device__ __forceinline__ void cp_commit(){ asm volatile("cp.async.commit_group;\n"); }
template<int NW> __device__ __forceinline__ void cp_wait(){
  asm volatile("cp.async.wait_group %0;\n" :: "n"(NW));
}
__device__ __forceinline__ void ldsm4(uint32_t* r, const __half* p){
  uint32_t a = smem_addr32(p);
  asm volatile("ldmatrix.sync.aligned.m8n8.x4.shared.b16 {%0,%1,%2,%3}, [%4];\n"
    : "=r"(r[0]),"=r"(r[1]),"=r"(r[2]),"=r"(r[3]) : "r"(a));
}
__device__ __forceinline__ void ldsm4t(uint32_t* r, const __half* p){
  uint32_t a = smem_addr32(p);
  asm volatile("ldmatrix.sync.aligned.m8n8.x4.trans.shared.b16 {%0,%1,%2,%3}, [%4];\n"
    : "=r"(r[0]),"=r"(r[1]),"=r"(r[2]),"=r"(r[3]) : "r"(a));
}
__device__ __forceinline__ void mma_f16_hmma(float* c, const uint32_t* a, uint32_t b0, uint32_t b1){
  asm volatile("mma.sync.aligned.m16n8k16.row.col.f32.f16.f16.f32 "
    "{%0,%1,%2,%3}, {%4,%5,%6,%7}, {%8,%9}, {%0,%1,%2,%3};\n"
    : "+f"(c[0]),"+f"(c[1]),"+f"(c[2]),"+f"(c[3])
    : "r"(a[0]),"r"(a[1]),"r"(a[2]),"r"(a[3]), "r"(b0),"r"(b1));
}
__device__ __forceinline__ uint32_t sw64(uint32_t off){ return off ^ ((off >> 3) & 0x30); }

__device__ __forceinline__ float gelu_fast(float x){
  float t = x*x;
  float u = x*(0.7978845608f + 0.0356774081f*t);
  float th;
  asm("tanh.approx.f32 %0, %1;" : "=f"(th) : "f"(u));
  return 0.5f*__fmaf_rn(x, th, x);
}
__device__ __forceinline__ uint32_t elect_one(){
  uint32_t pred;
  asm volatile("{\n.reg .pred p;\nelect.sync _|p, 0xFFFFFFFF;\nselp.b32 %0, 1, 0, p;\n}" : "=r"(pred));
  return pred;
}
__device__ __forceinline__ void mbar_init(uint32_t a, uint32_t cnt){
  asm volatile("mbarrier.init.shared.b64 [%0], %1;" :: "r"(a), "r"(cnt) : "memory");
}
__device__ __forceinline__ void mbar_expect_tx(uint32_t a, uint32_t bytes){
  asm volatile("mbarrier.arrive.expect_tx.shared.b64 _, [%0], %1;" :: "r"(a), "r"(bytes) : "memory");
}
__device__ __forceinline__ void mbar_wait(uint32_t a, uint32_t parity){
  asm volatile("{\n.reg .pred P;\nLW%=:\nmbarrier.try_wait.parity.acquire.cta.shared::cta.b64 P, [%0], %1, 0x989680;\n@!P bra LW%=;\n}"
    :: "r"(a), "r"(parity) : "memory");
}
#if HAS_TCGEN05
__device__ __forceinline__ void bulkcp(uint32_t dst, const void* src, uint32_t bytes, uint32_t mbar){
  asm volatile("cp.async.bulk.shared::cluster.global.mbarrier::complete_tx::bytes [%0], [%1], %2, [%3];"
    :: "r"(dst), "l"(src), "r"(bytes), "r"(mbar) : "memory");
}
__device__ __forceinline__ void tcg_alloc(uint32_t dst_smem, uint32_t ncols){
  asm volatile("tcgen05.alloc.cta_group::1.sync.aligned.shared::cta.b32 [%0], %1;" :: "r"(dst_smem), "r"(ncols) : "memory");
}
__device__ __forceinline__ void tcg_dealloc(uint32_t tmem, uint32_t ncols){
  asm volatile("tcgen05.dealloc.cta_group::1.sync.aligned.b32 %0, %1;" :: "r"(tmem), "r"(ncols));
}
__device__ __forceinline__ void tcg_relinquish(){
  asm volatile("tcgen05.relinquish_alloc_permit.cta_group::1.sync.aligned;");
}
__device__ __forceinline__ void tcg_commit(uint32_t mbar){
  asm volatile("tcgen05.commit.cta_group::1.mbarrier::arrive::one.shared::cluster.b64 [%0];" :: "r"(mbar) : "memory");
}
__device__ __forceinline__ void tcg_fence_after(){
  asm volatile("tcgen05.fence::after_thread_sync;" ::: "memory");
}
__device__ __forceinline__ void mma_f16_ss(uint32_t d, uint64_t a, uint64_t b, uint32_t idesc, uint32_t en){
  asm volatile("{\n.reg .pred p;\nsetp.ne.u32 p, %4, 0;\n"
    "tcgen05.mma.cta_group::1.kind::f16 [%0], %1, %2, %3, {%5,%5,%5,%5}, p;\n}"
    :: "r"(d), "l"(a), "l"(b), "r"(idesc), "r"(en), "r"(0u) : "memory");
}
__device__ __forceinline__ void ldtm32(uint32_t* r, uint32_t addr){
  asm volatile("tcgen05.ld.sync.aligned.32x32b.x32.b32 "
    "{%0,%1,%2,%3,%4,%5,%6,%7,%8,%9,%10,%11,%12,%13,%14,%15,"
    "%16,%17,%18,%19,%20,%21,%22,%23,%24,%25,%26,%27,%28,%29,%30,%31}, [%32];"
    : "=r"(r[0]),"=r"(r[1]),"=r"(r[2]),"=r"(r[3]),"=r"(r[4]),"=r"(r[5]),"=r"(r[6]),"=r"(r[7]),
      "=r"(r[8]),"=r"(r[9]),"=r"(r[10]),"=r"(r[11]),"=r"(r[12]),"=r"(r[13]),"=r"(r[14]),"=r"(r[15]),
      "=r"(r[16]),"=r"(r[17]),"=r"(r[18]),"=r"(r[19]),"=r"(r[20]),"=r"(r[21]),"=r"(r[22]),"=r"(r[23]),
      "=r"(r[24]),"=r"(r[25]),"=r"(r[26]),"=r"(r[27]),"=r"(r[28]),"=r"(r[29]),"=r"(r[30]),"=r"(r[31])
    : "r"(addr));
}
__device__ __forceinline__ void tcg_wait_ld(){
  asm volatile("tcgen05.wait::ld.sync.aligned;" ::: "memory");
}
// SW64 K-major smem descriptor: layout=4, SBO=32 (8 rows x 64B atom), LBO=1
__device__ __forceinline__ uint64_t make_desc_sw64(uint32_t base_addr){
  const uint64_t BASE = (uint64_t(4) << 61) | (uint64_t(1) << 46) | (uint64_t(32) << 32) | (uint64_t(1) << 16);
  return BASE | ((uint64_t)(base_addr >> 4) & 0x3FFF);
}
#endif

// ---------------- router: fp32 logits + softmax + top-2 (one warp per token) ----------
__global__ void router_kernel(const float* __restrict__ x, const float* __restrict__ wr){
  int widx = (blockIdx.x * blockDim.x + threadIdx.x) >> 5;
  int lane = threadIdx.x & 31;
  if (widx >= T_TOK) return;
  const float4* xr = (const float4*)(x + (size_t)widx * HS);
  const float4* w4 = (const float4*)wr;
  float acc[NEXP];
  #pragma unroll
  for (int e=0;e<NEXP;e++) acc[e]=0.f;
  #pragma unroll
  for (int it=0; it<8; it++){
    int h4 = it*32 + lane;                 // float4 index; h = h4*4
    float4 xv = xr[h4];
    const float4* wrow = w4 + (size_t)h4*8;
    float4 w0a = wrow[0], w0b = wrow[1];
    float4 w1a = wrow[2], w1b = wrow[3];
    float4 w2a = wrow[4], w2b = wrow[5];
    float4 w3a = wrow[6], w3b = wrow[7];
    acc[0] = fmaf(xv.x, w0a.x, fmaf(xv.y, w1a.x, fmaf(xv.z, w2a.x, fmaf(xv.w, w3a.x, acc[0]))));
    acc[1] = fmaf(xv.x, w0a.y, fmaf(xv.y, w1a.y, fmaf(xv.z, w2a.y, fmaf(xv.w, w3a.y, acc[1]))));
    acc[2] = fmaf(xv.x, w0a.z, fmaf(xv.y, w1a.z, fmaf(xv.z, w2a.z, fmaf(xv.w, w3a.z, acc[2]))));
    acc[3] = fmaf(xv.x, w0a.w, fmaf(xv.y, w1a.w, fmaf(xv.z, w2a.w, fmaf(xv.w, w3a.w, acc[3]))));
    acc[4] = fmaf(xv.x, w0b.x, fmaf(xv.y, w1b.x, fmaf(xv.z, w2b.x, fmaf(xv.w, w3b.x, acc[4]))));
    acc[5] = fmaf(xv.x, w0b.y, fmaf(xv.y, w1b.y, fmaf(xv.z, w2b.y, fmaf(xv.w, w3b.y, acc[5]))));
    acc[6] = fmaf(xv.x, w0b.z, fmaf(xv.y, w1b.z, fmaf(xv.z, w2b.z, fmaf(xv.w, w3b.z, acc[6]))));
    acc[7] = fmaf(xv.x, w0b.w, fmaf(xv.y, w1b.w, fmaf(xv.z, w2b.w, fmaf(xv.w, w3b.w, acc[7]))));
  }
  #pragma unroll
  for (int off=16; off; off>>=1){
    #pragma unroll
    for (int e=0;e<NEXP;e++) acc[e] += __shfl_xor_sync(0xffffffffu, acc[e], off);
  }
  if (lane == 0){
    float m = acc[0];
    #pragma unroll
    for (int e=1;e<NEXP;e++) m = fmaxf(m, acc[e]);
    float ex[NEXP], s = 0.f;
    #pragma unroll
    for (int e=0;e<NEXP;e++){ ex[e] = __expf(acc[e]-m); s += ex[e]; }
    int e0 = 0; float b0 = acc[0];
    #pragma unroll
    for (int e=1;e<NEXP;e++) if (acc[e] > b0){ b0 = acc[e]; e0 = e; }
    int e1 = (e0==0) ? 1 : 0; float b1 = acc[e1];
    #pragma unroll
    for (int e=0;e<NEXP;e++) if (e != e0 && acc[e] > b1){ b1 = acc[e]; e1 = e; }
    float inv = 1.f/s;
    g_top_e[2*widx]   = e0;
    g_top_e[2*widx+1] = e1;
    g_top_w[2*widx]   = ex[e0]*inv;
    g_top_w[2*widx+1] = ex[e1]*inv;
  }
}

// ---------------- stable counting sort + capacity (hierarchical scan) ----------------
__global__ void __launch_bounds__(1024,1) scan_kernel(){
  __shared__ int wbase[32][NEXP];
  __shared__ int etot[NEXP];
  __shared__ int starts[NEXP];
  int t = threadIdx.x, lane = t & 31, w = t >> 5;
  const int i0 = t * 32;
  int e_loc[32];
  int cnt[NEXP];
  #pragma unroll
  for (int e=0;e<NEXP;e++) cnt[e]=0;
  #pragma unroll
  for (int j=0;j<32;j++){ e_loc[j] = g_top_e[i0+j]; cnt[e_loc[j]]++; }
  int excl[NEXP];
  #pragma unroll
  for (int e=0;e<NEXP;e++){
    int v = cnt[e], s = v;
    #pragma unroll
    for (int off=1; off<32; off<<=1){
      int n = __shfl_up_sync(0xffffffffu, s, off);
      if (lane >= off) s += n;
    }
    excl[e] = s - v;
    if (lane == 31) wbase[w][e] = s;
  }
  __syncthreads();
  if (w == 0){
    #pragma unroll
    for (int e=0;e<NEXP;e++){
      int v = wbase[lane][e], s = v;
      #pragma unroll
      for (int off=1; off<32; off<<=1){
        int n = __shfl_up_sync(0xffffffffu, s, off);
        if (lane >= off) s += n;
      }
      wbase[lane][e] = s - v;
      if (lane == 31) etot[e] = s;
    }
  }
  __syncthreads();
  if (t == 0){
    int run = 0;
    #pragma unroll
    for (int e=0;e<NEXP;e++){ starts[e] = run; run += etot[e]; }
  }
  __syncthreads();
  int base[NEXP];
  #pragma unroll
  for (int e=0;e<NEXP;e++) base[e] = starts[e] + wbase[w][e] + excl[e];
  #pragma unroll
  for (int j=0;j<32;j++){
    int e = e_loc[j];
    int pos = base[e]++;
    int r = pos - starts[e];
    g_dst_slot[i0+j] = (r < CAP) ? (e*CAP + r) : -1;
  }
}

// ---------------- fused prep, EXACT grid (128,32,20), block 256 ----------------
__global__ void prep_kernel(const float* __restrict__ x,
                            const float* __restrict__ w1,
                            const float* __restrict__ w2){
  if (blockIdx.z < 16){
#if HAS_TCGEN05
    __shared__ float tile[32][33];
    int which = blockIdx.z >= 8;
    int e = blockIdx.z & 7;
    const int K = which ? FFN : HS;
    const int N = which ? HS  : FFN;
    const int NT = N/256, KBn = K/32;
    const float* w = which ? w2 : w1;
    char* dstb = which ? (char*)g_w2t : (char*)g_w1t;
    int nb = which ? blockIdx.y : blockIdx.x;
    int kb = which ? blockIdx.x : blockIdx.y;
    int n0 = nb*32, k0 = kb*32;
    int tx = threadIdx.x & 31, ty = threadIdx.x >> 5;   // 32 x 8
    const float* in = w + (size_t)e*K*N;
    #pragma unroll
    for (int r=0;r<4;r++)
      tile[ty+8*r][tx] = in[(size_t)(k0+ty+8*r)*N + n0+tx];
    __syncthreads();
    #pragma unroll
    for (int r=0;r<4;r++){
      float v = tile[tx][ty+8*r];
      int n = n0 + ty + 8*r, k = k0 + tx;
      size_t blk = ((size_t)(e*NT + (n>>8)))*KBn + (k>>5);
      uint32_t inner = sw64((uint32_t)((n & 255)*64 + (k & 31)*2));
      *(__half*)(dstb + blk*16384 + inner) = __float2half_rn(v);
    }
#endif
    return;
  }
  // ---- gather ----
  int bid = (blockIdx.z - 16)*4096 + blockIdx.y*128 + blockIdx.x;
  int i = bid*2 + (threadIdx.x >> 7);
  int t128 = threadIdx.x & 127;
  int dst = g_dst_slot[i];
  if (dst < 0) return;
  const float4* src = (const float4*)(x + (size_t)(i>>1)*HS);
#if HAS_TCGEN05
  int e  = dst >> 12;
  int mt = (dst >> 8) & 15;
  int r  = dst & 255;
  char* ab = (char*)g_xb + (((size_t)(e*16 + mt))*32)*16384;
  float4 a = src[t128*2], b = src[t128*2+1];
  union { uint4 u; __half2 h[4]; } pk;
  pk.h[0] = __floats2half2_rn(a.x, a.y);
  pk.h[1] = __floats2half2_rn(a.z, a.w);
  pk.h[2] = __floats2half2_rn(b.x, b.y);
  pk.h[3] = __floats2half2_rn(b.z, b.w);
  int kb = t128 >> 2, c = t128 & 3;
  uint32_t inner = sw64((uint32_t)(r*64 + c*16));
  *(uint4*)(ab + (size_t)kb*16384 + inner) = pk.u;
#else
  __half* xb = g_xb + (size_t)dst*HS;
  for (int j = t128; j < HS/4; j += 128){
    float4 v = src[j];
    *(__half2*)&xb[j*4]   = __floats2half2_rn(v.x, v.y);
    *(__half2*)&xb[j*4+2] = __floats2half2_rn(v.z, v.w);
  }
#endif
}

// ---------------- HMMA-path weight convert fp32 -> fp16 ([E][K][N]) --------
__global__ void split_w_kernel(const float* __restrict__ w, int which){
#if !HAS_TCGEN05
  __half* dst = which ? g_w2 : g_w1;
  size_t i = (size_t)blockIdx.x*blockDim.x + threadIdx.x;
  const size_t n4 = (size_t)NEXP*HS*FFN/4;
  if (i >= n4) return;
  float4 v = ((const float4*)w)[i];
  *(__half2*)&dst[i*4]   = __floats2half2_rn(v.x, v.y);
  *(__half2*)&dst[i*4+2] = __floats2half2_rn(v.z, v.w);
#endif
}

// =====================================================================
// PATH A: tcgen05 fp16 GEMM, tile 256x256 (two M=128 halves, 512 TMEM cols),
// K-chunk 32, cp.async.bulk feed, 4-stage ring of (A 16KB | B 16KB) = 32KB.
// =====================================================================
#define STAGEB 32768
#define GSMEM (4*STAGEB + 1024)

template<int PHASE>
__global__ void __launch_bounds__(256,1) gemm_tc_kernel(){
#if HAS_TCGEN05
  constexpr int Kdim = (PHASE==1) ? HS  : FFN;
  constexpr int Ndim = (PHASE==1) ? FFN : HS;
  constexpr int NKB  = Kdim/32;
  constexpr int NT   = Ndim/256;
  const char* A_g = (const char*)((PHASE==1) ? g_xb  : g_h);
  const char* B_g = (const char*)((PHASE==1) ? g_w1t : g_w2t);

  extern __shared__ char dyn[];
  __shared__ uint64_t s_mbar[8];
  __shared__ uint32_t s_tptr;
  uint32_t sbase = (smem_addr32(dyn) + 1023u) & ~1023u;

  const int tid = threadIdx.x;
  const int wid = tid >> 5, lane = tid & 31;
  const int e = blockIdx.z, bx = blockIdx.x, by = blockIdx.y;
  const size_t Ablk = ((size_t)(e*16 + by))*NKB;
  const size_t Bblk = ((size_t)(e*NT + bx))*NKB;

  uint32_t fullb[4], mmab[4];
  #pragma unroll
  for (int s=0;s<4;s++){ fullb[s]=smem_addr32(&s_mbar[s]); mmab[s]=smem_addr32(&s_mbar[4+s]); }

  if (wid == 0) tcg_alloc(smem_addr32(&s_tptr), 512);
  if (tid == 0){
    #pragma unroll
    for (int s=0;s<4;s++){ mbar_init(fullb[s],1); mbar_init(mmab[s],1); }
  }
  __syncthreads();
  const uint32_t tmem = s_tptr;
  const uint32_t idesc = (1u<<4) | ((256u>>3)<<17) | ((128u>>4)<<24);

  if (wid == 1 && elect_one()){
    #pragma unroll
    for (int s=0;s<4;s++){
      uint32_t st = sbase + s*STAGEB;
      mbar_expect_tx(fullb[s], STAGEB);
      bulkcp(st,         A_g + (Ablk + s)*16384, 16384, fullb[s]);
      bulkcp(st + 16384, B_g + (Bblk + s)*16384, 16384, fullb[s]);
    }
    int phm[4] = {0,0,0,0};
    for (int s = 4; s < NKB; s++){
      int pb = s & 3;
      mbar_wait(mmab[pb], phm[pb]); phm[pb] ^= 1;
      uint32_t st = sbase + pb*STAGEB;
      mbar_expect_tx(fullb[pb], STAGEB);
      bulkcp(st,         A_g + (Ablk + s)*16384, 16384, fullb[pb]);
      bulkcp(st + 16384, B_g + (Bblk + s)*16384, 16384, fullb[pb]);
    }
  } else if (wid == 0 && elect_one()){
    for (int kb = 0; kb < NKB; kb++){
      int buf = kb & 3;
      mbar_wait(fullb[buf], (kb>>2)&1);
      uint32_t st = sbase + buf*STAGEB;
      uint64_t dB = make_desc_sw64(st + 16384);
      #pragma unroll
      for (int half=0; half<2; half++){
        uint64_t dA = make_desc_sw64(st + half*8192);
        uint32_t d  = tmem + half*256;
        #pragma unroll
        for (int ks=0; ks<2; ks++)
          mma_f16_ss(d, dA + ks*2, dB + ks*2, idesc, (kb==0 && ks==0) ? 0u : 1u);
      }
      tcg_commit(mmab[buf]);
    }
    mbar_wait(mmab[(NKB-1)&3], ((NKB/4)-1)&1);
  }
  __syncthreads();
  tcg_fence_after();

  {
    const int half = wid >> 2;
    const int r = half*128 + (wid & 3)*32 + lane;
    #pragma unroll
    for (int ch=0; ch<8; ch++){
      uint32_t rg[32];
      ldtm32(rg, tmem + half*256 + ch*32);
      tcg_wait_ld();
      if constexpr (PHASE==1){
        int kb2 = bx*8 + ch;
        char* dst = (char*)g_h + (((size_t)(e*16 + by))*(FFN/32) + kb2)*16384;
        uint32_t hp[16];
        #pragma unroll
        for (int j=0;j<32;j+=2){
          float g0 = gelu_fast(__uint_as_float(rg[j]));
          float g1 = gelu_fast(__uint_as_float(rg[j+1]));
          uint32_t p;
          asm("cvt.rn.f16x2.f32 %0, %1, %2;" : "=r"(p) : "f"(g1), "f"(g0));
          hp[j>>1] = p;
        }
        #pragma unroll
        for (int i=0;i<4;i++){
          uint32_t inner = sw64((uint32_t)(r*64 + i*16));
          *(uint4*)(dst + inner) = make_uint4(hp[i*4],hp[i*4+1],hp[i*4+2],hp[i*4+3]);
        }
      } else {
        int nc = bx*256 + ch*32;
        size_t o = ((size_t)e*CAP + by*256 + r)*HS + nc;
        #pragma unroll
        for (int j=0;j<32;j+=4){
          *(float4*)&g_y[o+j] = make_float4(__uint_as_float(rg[j]),  __uint_as_float(rg[j+1]),
                                            __uint_as_float(rg[j+2]),__uint_as_float(rg[j+3]));
        }
      }
    }
  }
  __syncthreads();
  if (wid == 0){
    tcg_relinquish();
    tcg_dealloc(tmem, 512);
  }
#endif
}

// =====================================================================
// PATH B: HMMA mma.sync fp16 grouped GEMM (fallback, row-major layouts)
// =====================================================================
#define HSMEM (2*9472*2)
template<int PHASE>
__global__ void __launch_bounds__(512,1) gemm_split_kernel(){
#if !HAS_TCGEN05
  constexpr int K  = (PHASE==1) ? HS  : FFN;
  constexpr int N  = (PHASE==1) ? FFN : HS;
  constexpr int KB = K/32;
  const __half* __restrict__ A_g = (PHASE==1) ? g_xb : g_h;
  const __half* __restrict__ B_g = (PHASE==1) ? g_w1 : g_w2;

  extern __shared__ __align__(16) __half sm[];

  const int e  = blockIdx.z;
  const int m0 = blockIdx.y * 128;
  const int n0 = blockIdx.x * 128;
  const size_t Abase = (size_t)e*CAP*K;
  const size_t Bbase = (size_t)e*K*N;
  const size_t Cbase = (size_t)e*CAP*N;

  const int tid = threadIdx.x;
  const int warp = tid >> 5, lane = tid & 31;
  const int wm = warp >> 2, wn = warp & 3;
  const int ar = tid >> 2,  ac = (tid & 3)  * 8;
  const int br = tid >> 4,  bc = (tid & 15) * 8;

  float acc[2][4][4];
  #pragma unroll
  for (int i=0;i<2;i++)
    #pragma unroll
    for (int j=0;j<4;j++)
      #pragma unroll
      for (int k=0;k<4;k++) acc[i][j][k]=0.f;

  {
    __half* s = sm;
    cp16s(smem_addr32(s +        ar*40 + ac), A_g + Abase + (size_t)(m0+ar)*K + ac);
    cp16s(smem_addr32(s + 5120 + br*136 + bc), B_g + Bbase + (size_t)br*N + n0 + bc);
    cp_commit();
  }
  for (int kb=0; kb<KB; kb++){
    if (kb+1 < KB){
      const int k0 = (kb+1)*32;
      __half* s = sm + ((kb+1)&1)*9472;
      cp16s(smem_addr32(s +        ar*40 + ac), A_g + Abase + (size_t)(m0+ar)*K + k0 + ac);
      cp16s(smem_addr32(s + 5120 + br*136 + bc), B_g + Bbase + (size_t)(k0+br)*N + n0 + bc);
      cp_commit();
      cp_wait<1>();
    } else {
      cp_wait<0>();
    }
    __syncthreads();
    const __half* s = sm + (kb&1)*9472;
    #pragma unroll
    for (int ks=0; ks<2; ks++){
      uint32_t a[2][4];
      #pragma unroll
      for (int mt=0; mt<2; mt++){
        const __half* p = s + (wm*32 + mt*16 + (lane&15))*40 + ks*16 + (lane>>4)*8;
        ldsm4(a[mt], p);
      }
      uint32_t b[2][4];
      #pragma unroll
      for (int nh=0; nh<2; nh++){
        const __half* p = s + 5120 + (ks*16 + (lane&15))*136 + wn*32 + nh*16 + (lane>>4)*8;
        ldsm4t(b[nh], p);
      }
      #pragma unroll
      for (int mt=0; mt<2; mt++){
        #pragma unroll
        for (int nt=0; nt<4; nt++){
          const int nh = nt>>1, sb = (nt&1)*2;
          mma_f16_hmma(acc[mt][nt], a[mt], b[nh][sb], b[nh][sb+1]);
        }
      }
    }
    __syncthreads();
  }
  const int g = lane>>2, tg = lane&3;
  #pragma unroll
  for (int mt=0; mt<2; mt++){
    #pragma unroll
    for (int nt=0; nt<4; nt++){
      const int row = m0 + wm*32 + mt*16 + g;
      const int col = n0 + wn*32 + nt*8 + tg*2;
      float v0=acc[mt][nt][0], v1=acc[mt][nt][1], v2=acc[mt][nt][2], v3=acc[mt][nt][3];
      if constexpr (PHASE==1){
        v0=gelu_fast(v0); v1=gelu_fast(v1); v2=gelu_fast(v2); v3=gelu_fast(v3);
        size_t o  = Cbase + (size_t)row*N + col;
        size_t o2 = Cbase + (size_t)(row+8)*N + col;
        *(__half2*)&g_h[o]  = __floats2half2_rn(v0, v1);
        *(__half2*)&g_h[o2] = __floats2half2_rn(v2, v3);
      } else {
        *(float2*)&g_y[Cbase + (size_t)row*N + col]     = make_float2(v0,v1);
        *(float2*)&g_y[Cbase + (size_t)(row+8)*N + col] = make_float2(v2,v3);
      }
    }
  }
#endif
}

// ---------------- per-token weighted combine + bias ----------------
__global__ void scatter_kernel(const float* __restrict__ bias, float* __restrict__ out){
  int t = blockIdx.x;
  int s0 = g_dst_slot[2*t], s1 = g_dst_slot[2*t+1];
  float w0 = g_top_w[2*t], w1 = g_top_w[2*t+1];
  const float4* y0 = (const float4*)(g_y + (size_t)(s0 < 0 ? 0 : s0)*HS);
  const float4* y1 = (const float4*)(g_y + (size_t)(s1 < 0 ? 0 : s1)*HS);
  const float4* b4 = (const float4*)bias;
  float4* o = (float4*)(out + (size_t)t*HS);
  for (int j = threadIdx.x; j < HS/4; j += blockDim.x){
    float4 r = b4[j];
    if (s0 >= 0){ float4 v = y0[j]; r.x += w0*v.x; r.y += w0*v.y; r.z += w0*v.z; r.w += w0*v.w; }
    if (s1 >= 0){ float4 v = y1[j]; r.x += w1*v.x; r.y += w1*v.y; r.z += w1*v.z; r.w += w1*v.w; }
    o[j] = r;
  }
}

// ---------------- launcher ----------------
extern "C" void kernel_launch(void* const* d_in, const int* in_sizes, int n_in,
                              void* d_out, int out_size){
  const float* x    = (const float*)d_in[0];
  const float* wr   = (const float*)d_in[1];
  const float* w1   = (const float*)d_in[2];
  const float* w2   = (const float*)d_in[3];
  const float* bias = (const float*)d_in[4];
  float* out = (float*)d_out;

  cudaFuncSetAttribute(gemm_tc_kernel<1>, cudaFuncAttributeMaxDynamicSharedMemorySize, GSMEM);
  cudaFuncSetAttribute(gemm_tc_kernel<2>, cudaFuncAttributeMaxDynamicSharedMemorySize, GSMEM);
  cudaFuncSetAttribute(gemm_split_kernel<1>, cudaFuncAttributeMaxDynamicSharedMemorySize, HSMEM);
  cudaFuncSetAttribute(gemm_split_kernel<2>, cudaFuncAttributeMaxDynamicSharedMemorySize, HSMEM);

  cudaFuncAttributes fa{};
  cudaFuncGetAttributes(&fa, gemm_tc_kernel<1>);
  const bool tc = fa.numRegs > 32;

  router_kernel<<<T_TOK/8, 256>>>(x, wr);                               // 0
  scan_kernel<<<1, 1024>>>();                                           // 1
  prep_kernel<<<dim3(128,32,20), 256>>>(x, w1, w2);                     // 2
  if (tc){
    gemm_tc_kernel<1><<<dim3(FFN/256, CAP/256, NEXP), 256, GSMEM>>>();  // 3 <- profiled
    gemm_tc_kernel<2><<<dim3(HS/256,  CAP/256, NEXP), 256, GSMEM>>>();
  } else {
    const int n4 = NEXP*HS*FFN/4;
    split_w_kernel<<<(n4+255)/256, 256>>>(w1, 0);
    split_w_kernel<<<(n4+255)/256, 256>>>(w2, 1);
    gemm_split_kernel<1><<<dim3(FFN/128, CAP/128, NEXP), 512, HSMEM>>>();
    gemm_split_kernel<2><<<dim3(HS/128,  CAP/128, NEXP), 512, HSMEM>>>();
  }
  scatter_kernel<<<T_TOK, 128>>>(bias, out);
}